// round 10
// baseline (speedup 1.0000x reference)
#include <cuda_runtime.h>
#include <cuda_fp16.h>
#include <cstdint>
#include <math.h>

// ---------------- fixed problem geometry ----------------
#define MAXN 50000
#define MAXE 800000
// C=128, A_ALL=256, RAD_IN=32, FC1=FC2=64, H=8, AH=VH=16

// ---------------- scratch ----------------
__device__ __align__(16) float g_msg_src[(size_t)MAXN * 128];
__device__ __align__(16) float g_msg_dst[(size_t)MAXN * 128];
__device__ __align__(16) float g_nsum[(size_t)MAXN * 8];
__device__ __align__(16) float g_nacc[(size_t)MAXN * 128];
// prepacked fp16 weight images (exact SMEM layouts, swizzled)
__device__ __align__(16) unsigned char g_Bimg[65536];   // w_sep [k][n] fp16
__device__ __align__(16) unsigned char g_W1img[8192];   // hi @0, lo @4096
__device__ __align__(16) unsigned char g_W2img[16384];  // hi @0, lo @8192
__device__ __align__(16) unsigned char g_W3img[32768];  // hi @0, lo @16384

// ---------------- helpers ----------------
__device__ __forceinline__ uint32_t smem_u32(const void* p) {
    uint32_t a;
    asm("{ .reg .u64 t; cvta.to.shared.u64 t, %1; cvt.u32.u64 %0, t; }"
        : "=r"(a) : "l"(p));
    return a;
}

#define LDSM4(r, addr) \
    asm volatile("ldmatrix.sync.aligned.m8n8.x4.shared.b16 {%0,%1,%2,%3}, [%4];" \
        : "=r"((r)[0]), "=r"((r)[1]), "=r"((r)[2]), "=r"((r)[3]) : "r"(addr))

#define LDSM4T(r, addr) \
    asm volatile("ldmatrix.sync.aligned.m8n8.x4.trans.shared.b16 {%0,%1,%2,%3}, [%4];" \
        : "=r"((r)[0]), "=r"((r)[1]), "=r"((r)[2]), "=r"((r)[3]) : "r"(addr))

#define MMA16816(d, a, b0v, b1v) \
    asm volatile("mma.sync.aligned.m16n8k16.row.col.f32.f16.f16.f32 " \
        "{%0,%1,%2,%3}, {%4,%5,%6,%7}, {%8,%9}, {%0,%1,%2,%3};" \
        : "+f"((d)[0]), "+f"((d)[1]), "+f"((d)[2]), "+f"((d)[3]) \
        : "r"((a)[0]), "r"((a)[1]), "r"((a)[2]), "r"((a)[3]), "r"(b0v), "r"(b1v))

#define STS32(addr, v) \
    asm volatile("st.shared.b32 [%0], %1;" :: "r"(addr), "r"(v))
#define STS64(addr, v0, v1) \
    asm volatile("st.shared.v2.b32 [%0], {%1,%2};" :: "r"(addr), "r"(v0), "r"(v1))

// async 16B global->shared copy (sm_80+)
#define CP16(dst, src) \
    asm volatile("{ .reg .u64 g; cvta.to.global.u64 g, %1; " \
                 "cp.async.cg.shared.global [%0], [g], 16; }" \
                 :: "r"(dst), "l"(src) : "memory")
#define CP_COMMIT() asm volatile("cp.async.commit_group;" ::: "memory")
#define CP_WAIT(n)  asm volatile("cp.async.wait_group %0;" :: "n"(n) : "memory")

// vector fire-and-forget global reduction (sm_90+)
#define RED2(ptr, x, y) \
    asm volatile("red.global.add.v2.f32 [%0], {%1,%2};" :: "l"(ptr), "f"(x), "f"(y) : "memory")

__device__ __forceinline__ uint32_t packh2(float x, float y) {
    __half2 t = __floats2half2_rn(x, y);
    return *(uint32_t*)&t;
}
__device__ __forceinline__ void split2(float x, float y, uint32_t& hi, uint32_t& lo) {
    __half h0 = __float2half_rn(x), h1 = __float2half_rn(y);
    __half2 hh = __halves2half2(h0, h1);
    hi = *(uint32_t*)&hh;
    lo = packh2(x - __half2float(h0), y - __half2float(h1));
}
__device__ __forceinline__ void split4(float4 v, uint32_t& hA, uint32_t& hB,
                                       uint32_t& lA, uint32_t& lB) {
    split2(v.x, v.y, hA, lA);
    split2(v.z, v.w, hB, lB);
}
__device__ __forceinline__ float silu(float x) {
    return x / (1.0f + __expf(-x));
}

// ---------------- K0: init segment buffers ----------------
__global__ void init_kernel(int n) {
    int i = blockIdx.x * blockDim.x + threadIdx.x;
    if (i < n * 128) g_nacc[i] = 0.0f;
    if (i < n * 8) g_nsum[i] = 0.0f;
}

// ---------------- K0b: prepack weight images (fp16, swizzled SMEM layout) --
__global__ void prep_kernel(const float* __restrict__ w1, const float* __restrict__ w2,
                            const float* __restrict__ w3, const float* __restrict__ w_sep)
{
    int idx = blockIdx.x * blockDim.x + threadIdx.x;  // float4 units
    if (idx < 8192) {                       // w_sep: 128 x 256, rows 512B
        int k = idx >> 6, n4 = (idx & 63) << 2;
        float4 v = *(const float4*)(w_sep + (size_t)k * 256 + n4);
        uint32_t hA = packh2(v.x, v.y), hB = packh2(v.z, v.w);
        uint32_t addr = (uint32_t)k * 512 + ((uint32_t)((n4 >> 3) ^ (k & 7)) << 4) + (n4 & 7) * 2;
        *(uint2*)(g_Bimg + addr) = make_uint2(hA, hB);
    } else if (idx < 8704) {                // w1: 32 x 64, rows 128B
        int i = idx - 8192;
        int k = i >> 4, n4 = (i & 15) << 2;
        float4 v = *(const float4*)(w1 + (size_t)k * 64 + n4);
        uint32_t hA, hB, lA, lB; split4(v, hA, hB, lA, lB);
        uint32_t addr = (uint32_t)k * 128 + ((uint32_t)((n4 >> 3) ^ (k & 7)) << 4) + (n4 & 7) * 2;
        *(uint2*)(g_W1img + addr) = make_uint2(hA, hB);
        *(uint2*)(g_W1img + 4096 + addr) = make_uint2(lA, lB);
    } else if (idx < 9728) {                // w2: 64 x 64, rows 128B
        int i = idx - 8704;
        int k = i >> 4, n4 = (i & 15) << 2;
        float4 v = *(const float4*)(w2 + (size_t)k * 64 + n4);
        uint32_t hA, hB, lA, lB; split4(v, hA, hB, lA, lB);
        uint32_t addr = (uint32_t)k * 128 + ((uint32_t)((n4 >> 3) ^ (k & 7)) << 4) + (n4 & 7) * 2;
        *(uint2*)(g_W2img + addr) = make_uint2(hA, hB);
        *(uint2*)(g_W2img + 8192 + addr) = make_uint2(lA, lB);
    } else if (idx < 11776) {               // w3: 64 x 128, rows 256B
        int i = idx - 9728;
        int k = i >> 5, n4 = (i & 31) << 2;
        float4 v = *(const float4*)(w3 + (size_t)k * 128 + n4);
        uint32_t hA, hB, lA, lB; split4(v, hA, hB, lA, lB);
        uint32_t addr = (uint32_t)k * 256 + ((uint32_t)((n4 >> 3) ^ (k & 7)) << 4) + (n4 & 7) * 2;
        *(uint2*)(g_W3img + addr) = make_uint2(hA, hB);
        *(uint2*)(g_W3img + 16384 + addr) = make_uint2(lA, lB);
    }
}

// ---------------- K1: dual node GEMM  msg_src/msg_dst = X @ {w_src,w_dst} ---
__global__ __launch_bounds__(256) void node_gemm_dual(
    const float* __restrict__ X, const float* __restrict__ Wsrc,
    const float* __restrict__ Wdst, const float* __restrict__ bias_src, int n)
{
    __shared__ float At[32 * 64];
    __shared__ float Bs0[32 * 128];
    __shared__ float Bs1[32 * 128];
    int tid = threadIdx.x;
    int r0 = blockIdx.x * 64;
    int cg = tid & 15, rg = tid >> 4;
    int col = cg * 8, row = rg * 4;

    float acc0[4][8], acc1[4][8];
#pragma unroll
    for (int i = 0; i < 4; i++)
#pragma unroll
        for (int j = 0; j < 8; j++) { acc0[i][j] = 0.0f; acc1[i][j] = 0.0f; }

    int lm = tid >> 2, lk = (tid & 3) * 8;
    int lkr = tid >> 3, lc = (tid & 7) * 16;

    for (int k0 = 0; k0 < 128; k0 += 32) {
        float4 a0, a1;
        int gr = r0 + lm;
        if (gr < n) {
            a0 = *(const float4*)(X + (size_t)gr * 128 + k0 + lk);
            a1 = *(const float4*)(X + (size_t)gr * 128 + k0 + lk + 4);
        } else {
            a0 = make_float4(0.f, 0.f, 0.f, 0.f); a1 = a0;
        }
        At[(lk + 0) * 64 + lm] = a0.x; At[(lk + 1) * 64 + lm] = a0.y;
        At[(lk + 2) * 64 + lm] = a0.z; At[(lk + 3) * 64 + lm] = a0.w;
        At[(lk + 4) * 64 + lm] = a1.x; At[(lk + 5) * 64 + lm] = a1.y;
        At[(lk + 6) * 64 + lm] = a1.z; At[(lk + 7) * 64 + lm] = a1.w;
#pragma unroll
        for (int q = 0; q < 4; q++) {
            *(float4*)(Bs0 + lkr * 128 + lc + 4 * q) =
                *(const float4*)(Wsrc + (size_t)(k0 + lkr) * 128 + lc + 4 * q);
            *(float4*)(Bs1 + lkr * 128 + lc + 4 * q) =
                *(const float4*)(Wdst + (size_t)(k0 + lkr) * 128 + lc + 4 * q);
        }
        __syncthreads();
#pragma unroll
        for (int kk = 0; kk < 32; kk++) {
            float a[4], b0[8], b1[8];
            *(float4*)a        = *(float4*)(At + kk * 64 + row);
            *(float4*)(b0)     = *(float4*)(Bs0 + kk * 128 + col);
            *(float4*)(b0 + 4) = *(float4*)(Bs0 + kk * 128 + col + 4);
            *(float4*)(b1)     = *(float4*)(Bs1 + kk * 128 + col);
            *(float4*)(b1 + 4) = *(float4*)(Bs1 + kk * 128 + col + 4);
#pragma unroll
            for (int i = 0; i < 4; i++)
#pragma unroll
                for (int j = 0; j < 8; j++) {
                    acc0[i][j] += a[i] * b0[j];
                    acc1[i][j] += a[i] * b1[j];
                }
        }
        __syncthreads();
    }

    float bj[8];
    *(float4*)bj       = *(const float4*)(bias_src + col);
    *(float4*)(bj + 4) = *(const float4*)(bias_src + col + 4);
#pragma unroll
    for (int i = 0; i < 4; i++) {
        int gr = r0 + row + i;
        if (gr >= n) continue;
        *(float4*)(g_msg_src + (size_t)gr * 128 + col) =
            make_float4(acc0[i][0] + bj[0], acc0[i][1] + bj[1],
                        acc0[i][2] + bj[2], acc0[i][3] + bj[3]);
        *(float4*)(g_msg_src + (size_t)gr * 128 + col + 4) =
            make_float4(acc0[i][4] + bj[4], acc0[i][5] + bj[5],
                        acc0[i][6] + bj[6], acc0[i][7] + bj[7]);
        *(float4*)(g_msg_dst + (size_t)gr * 128 + col) =
            make_float4(acc1[i][0], acc1[i][1], acc1[i][2], acc1[i][3]);
        *(float4*)(g_msg_dst + (size_t)gr * 128 + col + 4) =
            make_float4(acc1[i][4], acc1[i][5], acc1[i][6], acc1[i][7]);
    }
}

// ============================================================================
// K23: PERSISTENT fused radial-MLP + gather + w_sep GEMM + attention scatter
// 512 threads (16 warps). Weights staged ONCE per CTA; grid-stride over
// 128-edge tiles. fp16 HMMA; MLP B-side hi/lo compensated.
//
// Dynamic SMEM (204800 B), all regions disjoint:
//  [0,8K)       W1 hi/lo        [8K,24K)   W2 hi/lo
//  [24K,56K)    W3 hi/lo        [56K,120K) B (w_sep image)
//  [120K,136K)  X hi            [136K,152K) H1 hi
//  [152K,168K)  H2 hi           [168K,200K) A [m][k] rows 256B
// ============================================================================
__global__ __launch_bounds__(512, 1) void fused_edge_kernel(
    const float* __restrict__ edge_scalars, const float* __restrict__ edge_attr,
    const int* __restrict__ edge_src, const int* __restrict__ edge_dst,
    const float* __restrict__ b1, const float* __restrict__ b2,
    const float* __restrict__ b3, const float* __restrict__ b_sep,
    const float* __restrict__ alpha_dot, int E, int numTiles)
{
    extern __shared__ char dynsm[];
    __shared__ float sB1[64], sB2[64], sB3[128];
    __shared__ float sBsep[256], sAD[128];
    __shared__ int   sSrc[128], sDst[128];
    __shared__ float sAttr[128];

    const int tid = threadIdx.x;
    const int wid = tid >> 5, lane = tid & 31;
    const int mtx = lane >> 3, rin = lane & 7;
    const int lr = lane >> 2, lc = lane & 3;

    const uint32_t sb = smem_u32(dynsm);
    const uint32_t W1hi = sb;                 // lo at +4096
    const uint32_t W2hi = sb + 8192;          // lo at +8192
    const uint32_t W3hi = sb + 24576, W3lo = sb + 40960;
    const uint32_t Bsm  = sb + 57344;
    const uint32_t Xhi  = sb + 122880;
    const uint32_t H1hi = sb + 139264;
    const uint32_t H2hi = sb + 155648;
    const uint32_t Asm  = sb + 172032;

    // ---------------- one-time staging ----------------
    CP16(W1hi + tid * 16, g_W1img + tid * 16);                      // 512
#pragma unroll
    for (int it = 0; it < 2; it++) {                                // 1024
        int i = tid + 512 * it;
        CP16(W2hi + i * 16, g_W2img + i * 16);
    }
#pragma unroll
    for (int it = 0; it < 4; it++) {                                // 2048
        int i = tid + 512 * it;
        CP16(W3hi + i * 16, g_W3img + i * 16);
    }
#pragma unroll
    for (int it = 0; it < 8; it++) {                                // 4096
        int i = tid + 512 * it;
        CP16(Bsm + i * 16, g_Bimg + i * 16);
    }
    CP_COMMIT();
    if (tid < 64)  { sB1[tid] = b1[tid]; sB2[tid] = b2[tid]; }
    if (tid < 128) { sB3[tid] = b3[tid]; sAD[tid] = alpha_dot[tid]; }
    if (tid < 256) sBsep[tid] = b_sep[tid];
    CP_WAIT(0);
    __syncthreads();

    const int mi1 = wid & 7, ni1 = wid >> 3;     // MLP warp tiling
    const int mr = mi1 * 16;
    const int mi = wid & 3, ni = wid >> 2;       // phase2 warp tiling
    const int mrow0 = mi * 32, ncol0 = ni * 64;

    // =================== persistent tile loop ===================
    for (int tile = blockIdx.x; tile < numTiles; tile += gridDim.x) {
        const int e0 = tile * 128;
        __syncthreads();   // previous iteration fully done (sDst/X/H/A reuse)

        // ---- stage edge indices + X ----
        if (tid < 128) {
            int e = min(e0 + tid, E - 1);
            sSrc[tid] = edge_src[e];
            sDst[tid] = edge_dst[e];
            sAttr[tid] = (e0 + tid < E) ? edge_attr[e] : 0.0f;
        }
#pragma unroll
        for (int it = 0; it < 2; it++) {
            int i = tid + 512 * it;
            int m = i >> 3, k4 = (i & 7) << 2;
            int e = min(e0 + m, E - 1);
            float4 v = *(const float4*)(edge_scalars + (size_t)e * 32 + k4);
            uint32_t hA = packh2(v.x, v.y), hB = packh2(v.z, v.w);
            uint32_t addr = (uint32_t)m * 128 + ((uint32_t)(((k4 >> 3) ^ (m & 7))) << 4) + (k4 & 7) * 2;
            STS64(Xhi + addr, hA, hB);
        }
        __syncthreads();

        // ---- layer1: H1 = silu(X @ W1 + b1) [128x64, K=32] ----
        {
            const int nc = ni1 * 32;
            float acc[4][4];
#pragma unroll
            for (int i = 0; i < 4; i++)
#pragma unroll
                for (int j = 0; j < 4; j++) acc[i][j] = 0.0f;
#pragma unroll
            for (int ks = 0; ks < 2; ks++) {
                int m = mr + (mtx & 1) * 8 + rin;
                int kc = ks * 2 + (mtx >> 1);
                uint32_t aH[4];
                LDSM4(aH, Xhi + (uint32_t)m * 128 + ((uint32_t)(kc ^ (m & 7)) << 4));
                uint32_t bH[2][4], bL[2][4];
#pragma unroll
                for (int ntp = 0; ntp < 2; ntp++) {
                    int k = ks * 16 + (mtx & 1) * 8 + rin;
                    int nch = (nc >> 3) + ntp * 2 + (mtx >> 1);
                    uint32_t boff = (uint32_t)k * 128 + ((uint32_t)(nch ^ (k & 7)) << 4);
                    LDSM4T(bH[ntp], W1hi + boff);
                    LDSM4T(bL[ntp], W1hi + 4096 + boff);
                }
#pragma unroll
                for (int nt = 0; nt < 4; nt++) {
                    MMA16816(acc[nt], aH, bH[nt >> 1][(nt & 1) * 2], bH[nt >> 1][(nt & 1) * 2 + 1]);
                    MMA16816(acc[nt], aH, bL[nt >> 1][(nt & 1) * 2], bL[nt >> 1][(nt & 1) * 2 + 1]);
                }
            }
#pragma unroll
            for (int nt = 0; nt < 4; nt++) {
                int col = nc + nt * 8 + lc * 2;
                float s0 = silu(acc[nt][0] + sB1[col]);
                float s1 = silu(acc[nt][1] + sB1[col + 1]);
                float s2 = silu(acc[nt][2] + sB1[col]);
                float s3 = silu(acc[nt][3] + sB1[col + 1]);
                int r0 = mr + lr, r1 = r0 + 8;
                uint32_t ad0 = (uint32_t)r0 * 128 + ((uint32_t)((col >> 3) ^ (r0 & 7)) << 4) + (col & 7) * 2;
                STS32(H1hi + ad0, packh2(s0, s1));
                uint32_t ad1 = (uint32_t)r1 * 128 + ((uint32_t)((col >> 3) ^ (r1 & 7)) << 4) + (col & 7) * 2;
                STS32(H1hi + ad1, packh2(s2, s3));
            }
        }
        __syncthreads();

        // ---- layer2: H2 = silu(H1 @ W2 + b2) [128x64, K=64] ----
        {
            const int nc = ni1 * 32;
            float acc[4][4];
#pragma unroll
            for (int i = 0; i < 4; i++)
#pragma unroll
                for (int j = 0; j < 4; j++) acc[i][j] = 0.0f;
#pragma unroll
            for (int ks = 0; ks < 4; ks++) {
                int m = mr + (mtx & 1) * 8 + rin;
                int kc = ks * 2 + (mtx >> 1);
                uint32_t aH[4];
                LDSM4(aH, H1hi + (uint32_t)m * 128 + ((uint32_t)(kc ^ (m & 7)) << 4));
                uint32_t bH[2][4], bL[2][4];
#pragma unroll
                for (int ntp = 0; ntp < 2; ntp++) {
                    int k = ks * 16 + (mtx & 1) * 8 + rin;
                    int nch = (nc >> 3) + ntp * 2 + (mtx >> 1);
                    uint32_t boff = (uint32_t)k * 128 + ((uint32_t)(nch ^ (k & 7)) << 4);
                    LDSM4T(bH[ntp], W2hi + boff);
                    LDSM4T(bL[ntp], W2hi + 8192 + boff);
                }
#pragma unroll
                for (int nt = 0; nt < 4; nt++) {
                    MMA16816(acc[nt], aH, bH[nt >> 1][(nt & 1) * 2], bH[nt >> 1][(nt & 1) * 2 + 1]);
                    MMA16816(acc[nt], aH, bL[nt >> 1][(nt & 1) * 2], bL[nt >> 1][(nt & 1) * 2 + 1]);
                }
            }
#pragma unroll
            for (int nt = 0; nt < 4; nt++) {
                int col = nc + nt * 8 + lc * 2;
                float s0 = silu(acc[nt][0] + sB2[col]);
                float s1 = silu(acc[nt][1] + sB2[col + 1]);
                float s2 = silu(acc[nt][2] + sB2[col]);
                float s3 = silu(acc[nt][3] + sB2[col + 1]);
                int r0 = mr + lr, r1 = r0 + 8;
                uint32_t ad0 = (uint32_t)r0 * 128 + ((uint32_t)((col >> 3) ^ (r0 & 7)) << 4) + (col & 7) * 2;
                STS32(H2hi + ad0, packh2(s0, s1));
                uint32_t ad1 = (uint32_t)r1 * 128 + ((uint32_t)((col >> 3) ^ (r1 & 7)) << 4) + (col & 7) * 2;
                STS32(H2hi + ad1, packh2(s2, s3));
            }
        }
        __syncthreads();

        // ---- layer3: rad = H2 @ W3 + b3 [128x128, K=64] (regs) ----
        float acc3[8][4];
#pragma unroll
        for (int i = 0; i < 8; i++)
#pragma unroll
            for (int j = 0; j < 4; j++) acc3[i][j] = 0.0f;
        {
            const int nc = ni1 * 64;
#pragma unroll
            for (int ks = 0; ks < 4; ks++) {
                int m = mr + (mtx & 1) * 8 + rin;
                int kc = ks * 2 + (mtx >> 1);
                uint32_t aH[4];
                LDSM4(aH, H2hi + (uint32_t)m * 128 + ((uint32_t)(kc ^ (m & 7)) << 4));
                uint32_t bH[4][4];
#pragma unroll
                for (int ntp = 0; ntp < 4; ntp++) {
                    int k = ks * 16 + (mtx & 1) * 8 + rin;
                    int nch = (nc >> 3) + ntp * 2 + (mtx >> 1);
                    uint32_t boff = (uint32_t)k * 256 + ((uint32_t)(nch ^ (k & 7)) << 4);
                    LDSM4T(bH[ntp], W3hi + boff);
                }
#pragma unroll
                for (int nt = 0; nt < 8; nt++)
                    MMA16816(acc3[nt], aH, bH[nt >> 1][(nt & 1) * 2], bH[nt >> 1][(nt & 1) * 2 + 1]);
                uint32_t bL[4][4];
#pragma unroll
                for (int ntp = 0; ntp < 4; ntp++) {
                    int k = ks * 16 + (mtx & 1) * 8 + rin;
                    int nch = (nc >> 3) + ntp * 2 + (mtx >> 1);
                    uint32_t boff = (uint32_t)k * 256 + ((uint32_t)(nch ^ (k & 7)) << 4);
                    LDSM4T(bL[ntp], W3lo + boff);
                }
#pragma unroll
                for (int nt = 0; nt < 8; nt++)
                    MMA16816(acc3[nt], aH, bL[nt >> 1][(nt & 1) * 2], bL[nt >> 1][(nt & 1) * 2 + 1]);
            }
        }

        // ---- gather msgs + form A = (src+dst)*attr*rad (fp16) ----
        {
            const int nc = ni1 * 64;
#pragma unroll
            for (int rh = 0; rh < 2; rh++) {
                int r = mr + rh * 8 + lr;
                int src = sSrc[r], dst = sDst[r];
                float at = sAttr[r];
                const float* ps = g_msg_src + (size_t)src * 128;
                const float* pd = g_msg_dst + (size_t)dst * 128;
#pragma unroll
                for (int nt = 0; nt < 8; nt++) {
                    int col = nc + nt * 8 + lc * 2;
                    float rad0 = acc3[nt][rh * 2 + 0] + sB3[col];
                    float rad1 = acc3[nt][rh * 2 + 1] + sB3[col + 1];
                    float2 ms = *(const float2*)(ps + col);
                    float2 md = *(const float2*)(pd + col);
                    float m0 = (ms.x + md.x) * at * rad0;
                    float m1 = (ms.y + md.y) * at * rad1;
                    uint32_t ad = (uint32_t)r * 256 + ((uint32_t)((col >> 3) ^ (r & 7)) << 4) + (col & 7) * 2;
                    STS32(Asm + ad, packh2(m0, m1));
                }
            }
        }
        __syncthreads();

        // ---- phase2: D[128,256] = A @ B + epilogue ----
        float d[2][8][4];
#pragma unroll
        for (int a = 0; a < 2; a++)
#pragma unroll
            for (int b = 0; b < 8; b++)
#pragma unroll
                for (int c = 0; c < 4; c++) d[a][b][c] = 0.0f;

#pragma unroll
        for (int ks = 0; ks < 8; ks++) {
            uint32_t ah[2][4];
#pragma unroll
            for (int mt = 0; mt < 2; mt++) {
                int m = mrow0 + mt * 16 + (mtx & 1) * 8 + rin;
                int kchunk = ks * 2 + (mtx >> 1);
                LDSM4(ah[mt], Asm + (uint32_t)m * 256 + ((uint32_t)(kchunk ^ (m & 7)) << 4));
            }
            uint32_t b[4][4];
#pragma unroll
            for (int ntp = 0; ntp < 4; ntp++) {
                int k = ks * 16 + (mtx & 1) * 8 + rin;
                int nchunk = (ncol0 >> 3) + ntp * 2 + (mtx >> 1);
                LDSM4T(b[ntp], Bsm + (uint32_t)k * 512 + ((uint32_t)(nchunk ^ (k & 7)) << 4));
            }
#pragma unroll
            for (int mt = 0; mt < 2; mt++)
#pragma unroll
                for (int nt = 0; nt < 8; nt++)
                    MMA16816(d[mt][nt], ah[mt], b[nt >> 1][(nt & 1) * 2], b[nt >> 1][(nt & 1) * 2 + 1]);
        }

        // ---- epilogue: w = exp(score); direct segment reduction ----
#pragma unroll
        for (int hh = 0; hh < 2; hh++) {
            const int h = ni * 2 + hh;
#pragma unroll
            for (int mt = 0; mt < 2; mt++) {
                const int r0i = mrow0 + mt * 16 + lr;
                const int e0i = e0 + r0i;
                float p0 = 0.0f, p1 = 0.0f;
#pragma unroll
                for (int q = 0; q < 2; q++) {
                    const int nt = hh * 4 + q;
                    const int colb = ncol0 + nt * 8 + lc * 2;
                    const int jb = q * 8 + lc * 2;
                    const float bb0 = sBsep[colb], bb1 = sBsep[colb + 1];
                    const float w0 = sAD[h * 16 + jb], w1 = sAD[h * 16 + jb + 1];
                    float x, sg;
                    x = d[mt][nt][0] + bb0; sg = 1.0f / (1.0f + __expf(-x)); p0 += x * (0.2f + 0.8f * sg) * w0;
                    x = d[mt][nt][1] + bb1; sg = 1.0f / (1.0f + __expf(-x)); p0 += x * (0.2f + 0.8f * sg) * w1;
                    x = d[mt][nt][2] + bb0; sg = 1.0f / (1.0f + __expf(-x)); p1 += x * (0.2f + 0.8f * sg) * w0;
                    x = d[mt][nt][3] + bb1; sg = 1.0f / (1.0f + __expf(-x)); p1 += x * (0.2f + 0.8f * sg) * w1;
                }
                p0 += __shfl_xor_sync(0xffffffffu, p0, 1);
                p0 += __shfl_xor_sync(0xffffffffu, p0, 2);
                p1 += __shfl_xor_sync(0xffffffffu, p1, 1);
                p1 += __shfl_xor_sync(0xffffffffu, p1, 2);
                const float ew0 = __expf(p0), ew1 = __expf(p1);
                const int d0 = sDst[r0i], d1 = sDst[r0i + 8];
                if (lc == 0) {
                    if (e0i < E)     atomicAdd(&g_nsum[(size_t)d0 * 8 + h], ew0);
                    if (e0i + 8 < E) atomicAdd(&g_nsum[(size_t)d1 * 8 + h], ew1);
                }
#pragma unroll
                for (int q = 0; q < 2; q++) {
                    const int nt = hh * 4 + 2 + q;
                    const int colb = ncol0 + nt * 8 + lc * 2;
                    const int vidx = q * 8 + lc * 2;
                    const float bb0 = sBsep[colb], bb1 = sBsep[colb + 1];
                    if (e0i < E)
                        RED2(g_nacc + (size_t)d0 * 128 + h * 16 + vidx,
                             (d[mt][nt][0] + bb0) * ew0, (d[mt][nt][1] + bb1) * ew0);
                    if (e0i + 8 < E)
                        RED2(g_nacc + (size_t)d1 * 128 + h * 16 + vidx,
                             (d[mt][nt][2] + bb0) * ew1, (d[mt][nt][3] + bb1) * ew1);
                }
            }
        }
    }
}

// ---------------- K5: out = (nacc / (nsum+eps)) @ w_proj + b_proj -----------
__global__ __launch_bounds__(256) void out_gemm_kernel(
    const float* __restrict__ W, const float* __restrict__ bias,
    float* __restrict__ out, int n)
{
    __shared__ float At[32 * 64];
    __shared__ float Bs[32 * 128];
    int tid = threadIdx.x;
    int r0 = blockIdx.x * 64;
    int cg = tid & 15, rg = tid >> 4;
    int col = cg * 8, row = rg * 4;

    float acc[4][8];
#pragma unroll
    for (int i = 0; i < 4; i++)
#pragma unroll
        for (int j = 0; j < 8; j++) acc[i][j] = 0.0f;

    int lm = tid >> 2, lk = (tid & 3) * 8;
    int lkr = tid >> 3, lc = (tid & 7) * 16;

    for (int k0 = 0; k0 < 128; k0 += 32) {
        float4 a0, a1;
        int gr = r0 + lm;
        if (gr < n) {
            a0 = *(const float4*)(g_nacc + (size_t)gr * 128 + k0 + lk);
            a1 = *(const float4*)(g_nacc + (size_t)gr * 128 + k0 + lk + 4);
            int hh = (k0 + lk) >> 4;
            float inv = 1.0f / (g_nsum[(size_t)gr * 8 + hh] + 1e-16f);
            a0.x *= inv; a0.y *= inv; a0.z *= inv; a0.w *= inv;
            a1.x *= inv; a1.y *= inv; a1.z *= inv; a1.w *= inv;
        } else {
            a0 = make_float4(0.f, 0.f, 0.f, 0.f); a1 = a0;
        }
        At[(lk + 0) * 64 + lm] = a0.x; At[(lk + 1) * 64 + lm] = a0.y;
        At[(lk + 2) * 64 + lm] = a0.z; At[(lk + 3) * 64 + lm] = a0.w;
        At[(lk + 4) * 64 + lm] = a1.x; At[(lk + 5) * 64 + lm] = a1.y;
        At[(lk + 6) * 64 + lm] = a1.z; At[(lk + 7) * 64 + lm] = a1.w;
#pragma unroll
        for (int q = 0; q < 4; q++)
            *(float4*)(Bs + lkr * 128 + lc + 4 * q) =
                *(const float4*)(W + (size_t)(k0 + lkr) * 128 + lc + 4 * q);
        __syncthreads();
#pragma unroll
        for (int kk = 0; kk < 32; kk++) {
            float a[4], b[8];
            *(float4*)a       = *(float4*)(At + kk * 64 + row);
            *(float4*)(b)     = *(float4*)(Bs + kk * 128 + col);
            *(float4*)(b + 4) = *(float4*)(Bs + kk * 128 + col + 4);
#pragma unroll
            for (int i = 0; i < 4; i++)
#pragma unroll
                for (int j = 0; j < 8; j++) acc[i][j] += a[i] * b[j];
        }
        __syncthreads();
    }

    float bj[8];
    *(float4*)(bj)     = *(const float4*)(bias + col);
    *(float4*)(bj + 4) = *(const float4*)(bias + col + 4);
#pragma unroll
    for (int i = 0; i < 4; i++) {
        int gr = r0 + row + i;
        if (gr >= n) continue;
        float4 o0 = make_float4(acc[i][0] + bj[0], acc[i][1] + bj[1],
                                acc[i][2] + bj[2], acc[i][3] + bj[3]);
        float4 o1 = make_float4(acc[i][4] + bj[4], acc[i][5] + bj[5],
                                acc[i][6] + bj[6], acc[i][7] + bj[7]);
        *(float4*)(out + (size_t)gr * 128 + col)     = o0;
        *(float4*)(out + (size_t)gr * 128 + col + 4) = o1;
    }
}

// ---------------- launch ----------------
extern "C" void kernel_launch(void* const* d_in, const int* in_sizes, int n_in,
                              void* d_out, int out_size)
{
    const float* node_input = (const float*)d_in[0];
    const float* edge_attr  = (const float*)d_in[2];
    const float* edge_scal  = (const float*)d_in[3];
    const int*   edge_src   = (const int*)d_in[4];
    const int*   edge_dst   = (const int*)d_in[5];
    const float* w_src      = (const float*)d_in[7];
    const float* b_src      = (const float*)d_in[8];
    const float* w_dst      = (const float*)d_in[9];
    const float* fc_w1      = (const float*)d_in[10];
    const float* fc_b1      = (const float*)d_in[11];
    const float* fc_w2      = (const float*)d_in[12];
    const float* fc_b2      = (const float*)d_in[13];
    const float* fc_w3      = (const float*)d_in[14];
    const float* fc_b3      = (const float*)d_in[15];
    const float* w_sep      = (const float*)d_in[16];
    const float* b_sep      = (const float*)d_in[17];
    const float* alpha_dot  = (const float*)d_in[18];
    const float* w_proj     = (const float*)d_in[19];
    const float* b_proj     = (const float*)d_in[20];
    float* out = (float*)d_out;

    int N = in_sizes[0] / 128;
    int E = in_sizes[4];

    cudaFuncSetAttribute(fused_edge_kernel, cudaFuncAttributeMaxDynamicSharedMemorySize, 204800);

    static int sms = 0;
    if (sms == 0) {
        cudaDeviceGetAttribute(&sms, cudaDevAttrMultiProcessorCount, 0);
        if (sms <= 0) sms = 148;
    }

    init_kernel<<<(N * 128 + 255) / 256, 256>>>(N);
    prep_kernel<<<46, 256>>>(fc_w1, fc_w2, fc_w3, w_sep);

    int nb = (N + 63) / 64;
    node_gemm_dual<<<nb, 256>>>(node_input, w_src, w_dst, b_src, N);

    int numTiles = (E + 127) / 128;
    int nblk = numTiles < sms ? numTiles : sms;
    fused_edge_kernel<<<nblk, 512, 204800>>>(edge_scal, edge_attr, edge_src, edge_dst,
                                             fc_b1, fc_b2, fc_b3,
                                             b_sep, alpha_dot, E, numTiles);

    out_gemm_kernel<<<nb, 256>>>(w_proj, b_proj, out, N);
}

// round 12
// speedup vs baseline: 1.1726x; 1.1726x over previous
#include <cuda_runtime.h>
#include <cuda_fp16.h>
#include <cstdint>
#include <math.h>

// ---------------- fixed problem geometry ----------------
#define MAXN 50000
#define MAXE 800000
// C=128, A_ALL=256, RAD_IN=32, FC1=FC2=64, H=8, AH=VH=16

// ---------------- scratch ----------------
__device__ __align__(16) __half g_msgh_src[(size_t)MAXN * 128];   // LINEAR rows
__device__ __align__(16) __half g_msgh_dst[(size_t)MAXN * 128];   // LINEAR rows
__device__ __align__(16) float g_nsum[(size_t)MAXN * 8];
__device__ __align__(16) float g_nacc[(size_t)MAXN * 128];
// prepacked fp16 weight images (exact SMEM layouts, swizzled)
__device__ __align__(16) unsigned char g_Bimg[65536];   // w_sep [k][n] fp16
__device__ __align__(16) unsigned char g_W1img[8192];   // hi @0, lo @4096
__device__ __align__(16) unsigned char g_W2img[16384];  // hi @0, lo @8192
__device__ __align__(16) unsigned char g_W3img[32768];  // hi @0, lo @16384

// ---------------- helpers ----------------
__device__ __forceinline__ uint32_t smem_u32(const void* p) {
    uint32_t a;
    asm("{ .reg .u64 t; cvta.to.shared.u64 t, %1; cvt.u32.u64 %0, t; }"
        : "=r"(a) : "l"(p));
    return a;
}

#define LDSM4(r, addr) \
    asm volatile("ldmatrix.sync.aligned.m8n8.x4.shared.b16 {%0,%1,%2,%3}, [%4];" \
        : "=r"((r)[0]), "=r"((r)[1]), "=r"((r)[2]), "=r"((r)[3]) : "r"(addr))

#define LDSM4T(r, addr) \
    asm volatile("ldmatrix.sync.aligned.m8n8.x4.trans.shared.b16 {%0,%1,%2,%3}, [%4];" \
        : "=r"((r)[0]), "=r"((r)[1]), "=r"((r)[2]), "=r"((r)[3]) : "r"(addr))

#define MMA16816(d, a, b0v, b1v) \
    asm volatile("mma.sync.aligned.m16n8k16.row.col.f32.f16.f16.f32 " \
        "{%0,%1,%2,%3}, {%4,%5,%6,%7}, {%8,%9}, {%0,%1,%2,%3};" \
        : "+f"((d)[0]), "+f"((d)[1]), "+f"((d)[2]), "+f"((d)[3]) \
        : "r"((a)[0]), "r"((a)[1]), "r"((a)[2]), "r"((a)[3]), "r"(b0v), "r"(b1v))

#define STS32(addr, v) \
    asm volatile("st.shared.b32 [%0], %1;" :: "r"(addr), "r"(v))
#define STS64(addr, v0, v1) \
    asm volatile("st.shared.v2.b32 [%0], {%1,%2};" :: "r"(addr), "r"(v0), "r"(v1))
#define LDS32(v, addr) \
    asm volatile("ld.shared.b32 %0, [%1];" : "=r"(v) : "r"(addr))

// async 16B global->shared copy (sm_80+)
#define CP16(dst, src) \
    asm volatile("{ .reg .u64 g; cvta.to.global.u64 g, %1; " \
                 "cp.async.cg.shared.global [%0], [g], 16; }" \
                 :: "r"(dst), "l"(src) : "memory")
#define CP_COMMIT() asm volatile("cp.async.commit_group;" ::: "memory")
#define CP_WAIT(n)  asm volatile("cp.async.wait_group %0;" :: "n"(n) : "memory")

// vector fire-and-forget global reduction (sm_90+)
#define RED2(ptr, x, y) \
    asm volatile("red.global.add.v2.f32 [%0], {%1,%2};" :: "l"(ptr), "f"(x), "f"(y) : "memory")

__device__ __forceinline__ uint32_t packh2(float x, float y) {
    __half2 t = __floats2half2_rn(x, y);
    return *(uint32_t*)&t;
}
__device__ __forceinline__ void split2(float x, float y, uint32_t& hi, uint32_t& lo) {
    __half h0 = __float2half_rn(x), h1 = __float2half_rn(y);
    __half2 hh = __halves2half2(h0, h1);
    hi = *(uint32_t*)&hh;
    lo = packh2(x - __half2float(h0), y - __half2float(h1));
}
__device__ __forceinline__ void split4(float4 v, uint32_t& hA, uint32_t& hB,
                                       uint32_t& lA, uint32_t& lB) {
    split2(v.x, v.y, hA, lA);
    split2(v.z, v.w, hB, lB);
}
__device__ __forceinline__ float silu(float x) {
    return x / (1.0f + __expf(-x));
}

// ---------------- K0: init segment buffers ----------------
__global__ void init_kernel(int n) {
    int i = blockIdx.x * blockDim.x + threadIdx.x;
    if (i < n * 128) g_nacc[i] = 0.0f;
    if (i < n * 8) g_nsum[i] = 0.0f;
}

// ---------------- K0b: prepack weight images (fp16, swizzled SMEM layout) --
__global__ void prep_kernel(const float* __restrict__ w1, const float* __restrict__ w2,
                            const float* __restrict__ w3, const float* __restrict__ w_sep)
{
    int idx = blockIdx.x * blockDim.x + threadIdx.x;  // float4 units
    if (idx < 8192) {                       // w_sep: 128 x 256, rows 512B
        int k = idx >> 6, n4 = (idx & 63) << 2;
        float4 v = *(const float4*)(w_sep + (size_t)k * 256 + n4);
        uint32_t hA = packh2(v.x, v.y), hB = packh2(v.z, v.w);
        uint32_t addr = (uint32_t)k * 512 + ((uint32_t)((n4 >> 3) ^ (k & 7)) << 4) + (n4 & 7) * 2;
        *(uint2*)(g_Bimg + addr) = make_uint2(hA, hB);
    } else if (idx < 8704) {                // w1: 32 x 64, rows 128B
        int i = idx - 8192;
        int k = i >> 4, n4 = (i & 15) << 2;
        float4 v = *(const float4*)(w1 + (size_t)k * 64 + n4);
        uint32_t hA, hB, lA, lB; split4(v, hA, hB, lA, lB);
        uint32_t addr = (uint32_t)k * 128 + ((uint32_t)((n4 >> 3) ^ (k & 7)) << 4) + (n4 & 7) * 2;
        *(uint2*)(g_W1img + addr) = make_uint2(hA, hB);
        *(uint2*)(g_W1img + 4096 + addr) = make_uint2(lA, lB);
    } else if (idx < 9728) {                // w2: 64 x 64, rows 128B
        int i = idx - 8704;
        int k = i >> 4, n4 = (i & 15) << 2;
        float4 v = *(const float4*)(w2 + (size_t)k * 64 + n4);
        uint32_t hA, hB, lA, lB; split4(v, hA, hB, lA, lB);
        uint32_t addr = (uint32_t)k * 128 + ((uint32_t)((n4 >> 3) ^ (k & 7)) << 4) + (n4 & 7) * 2;
        *(uint2*)(g_W2img + addr) = make_uint2(hA, hB);
        *(uint2*)(g_W2img + 8192 + addr) = make_uint2(lA, lB);
    } else if (idx < 11776) {               // w3: 64 x 128, rows 256B
        int i = idx - 9728;
        int k = i >> 5, n4 = (i & 31) << 2;
        float4 v = *(const float4*)(w3 + (size_t)k * 128 + n4);
        uint32_t hA, hB, lA, lB; split4(v, hA, hB, lA, lB);
        uint32_t addr = (uint32_t)k * 256 + ((uint32_t)((n4 >> 3) ^ (k & 7)) << 4) + (n4 & 7) * 2;
        *(uint2*)(g_W3img + addr) = make_uint2(hA, hB);
        *(uint2*)(g_W3img + 16384 + addr) = make_uint2(lA, lB);
    }
}

// ---------------- K1: dual node GEMM -> fp16 msg arrays (LINEAR rows) -------
__global__ __launch_bounds__(256) void node_gemm_dual(
    const float* __restrict__ X, const float* __restrict__ Wsrc,
    const float* __restrict__ Wdst, const float* __restrict__ bias_src, int n)
{
    __shared__ float At[32 * 64];
    __shared__ float Bs0[32 * 128];
    __shared__ float Bs1[32 * 128];
    int tid = threadIdx.x;
    int r0 = blockIdx.x * 64;
    int cg = tid & 15, rg = tid >> 4;
    int col = cg * 8, row = rg * 4;

    float acc0[4][8], acc1[4][8];
#pragma unroll
    for (int i = 0; i < 4; i++)
#pragma unroll
        for (int j = 0; j < 8; j++) { acc0[i][j] = 0.0f; acc1[i][j] = 0.0f; }

    int lm = tid >> 2, lk = (tid & 3) * 8;
    int lkr = tid >> 3, lc = (tid & 7) * 16;

    for (int k0 = 0; k0 < 128; k0 += 32) {
        float4 a0, a1;
        int gr = r0 + lm;
        if (gr < n) {
            a0 = *(const float4*)(X + (size_t)gr * 128 + k0 + lk);
            a1 = *(const float4*)(X + (size_t)gr * 128 + k0 + lk + 4);
        } else {
            a0 = make_float4(0.f, 0.f, 0.f, 0.f); a1 = a0;
        }
        At[(lk + 0) * 64 + lm] = a0.x; At[(lk + 1) * 64 + lm] = a0.y;
        At[(lk + 2) * 64 + lm] = a0.z; At[(lk + 3) * 64 + lm] = a0.w;
        At[(lk + 4) * 64 + lm] = a1.x; At[(lk + 5) * 64 + lm] = a1.y;
        At[(lk + 6) * 64 + lm] = a1.z; At[(lk + 7) * 64 + lm] = a1.w;
#pragma unroll
        for (int q = 0; q < 4; q++) {
            *(float4*)(Bs0 + lkr * 128 + lc + 4 * q) =
                *(const float4*)(Wsrc + (size_t)(k0 + lkr) * 128 + lc + 4 * q);
            *(float4*)(Bs1 + lkr * 128 + lc + 4 * q) =
                *(const float4*)(Wdst + (size_t)(k0 + lkr) * 128 + lc + 4 * q);
        }
        __syncthreads();
#pragma unroll
        for (int kk = 0; kk < 32; kk++) {
            float a[4], b0[8], b1[8];
            *(float4*)a        = *(float4*)(At + kk * 64 + row);
            *(float4*)(b0)     = *(float4*)(Bs0 + kk * 128 + col);
            *(float4*)(b0 + 4) = *(float4*)(Bs0 + kk * 128 + col + 4);
            *(float4*)(b1)     = *(float4*)(Bs1 + kk * 128 + col);
            *(float4*)(b1 + 4) = *(float4*)(Bs1 + kk * 128 + col + 4);
#pragma unroll
            for (int i = 0; i < 4; i++)
#pragma unroll
                for (int j = 0; j < 8; j++) {
                    acc0[i][j] += a[i] * b0[j];
                    acc1[i][j] += a[i] * b1[j];
                }
        }
        __syncthreads();
    }

    float bj[8];
    *(float4*)bj       = *(const float4*)(bias_src + col);
    *(float4*)(bj + 4) = *(const float4*)(bias_src + col + 4);
#pragma unroll
    for (int i = 0; i < 4; i++) {
        int gr = r0 + row + i;
        if (gr >= n) continue;
        // LINEAR layout: byte offset = gr*256 + col*2 (col 8-aligned)
        uint32_t base = (uint32_t)gr * 256 + (uint32_t)col * 2;
        uint4 vs, vd;
        vs.x = packh2(acc0[i][0] + bj[0], acc0[i][1] + bj[1]);
        vs.y = packh2(acc0[i][2] + bj[2], acc0[i][3] + bj[3]);
        vs.z = packh2(acc0[i][4] + bj[4], acc0[i][5] + bj[5]);
        vs.w = packh2(acc0[i][6] + bj[6], acc0[i][7] + bj[7]);
        vd.x = packh2(acc1[i][0], acc1[i][1]);
        vd.y = packh2(acc1[i][2], acc1[i][3]);
        vd.z = packh2(acc1[i][4], acc1[i][5]);
        vd.w = packh2(acc1[i][6], acc1[i][7]);
        *(uint4*)((unsigned char*)g_msgh_src + base) = vs;
        *(uint4*)((unsigned char*)g_msgh_dst + base) = vd;
    }
}

// ============================================================================
// K23: PERSISTENT fused kernel with cp.async msg prefetch hidden under MLP.
// 512 threads (16 warps), grid-stride over 128-edge tiles.
//
// Dynamic SMEM (221184 B):
//  [0,8K)      W1 hi/lo     [8K,24K)   W2 hi/lo    [24K,56K) W3 hi/lo
//  [56K,120K)  B            [120K,136K) X          [136K,152K) H (L1&L2 shared)
//  [152K,184K) Msrc (becomes A in place)  [184K,216K) Mdst
// ============================================================================
__global__ __launch_bounds__(512, 1) void fused_edge_kernel(
    const float* __restrict__ edge_scalars, const float* __restrict__ edge_attr,
    const int* __restrict__ edge_src, const int* __restrict__ edge_dst,
    const float* __restrict__ b1, const float* __restrict__ b2,
    const float* __restrict__ b3, const float* __restrict__ b_sep,
    const float* __restrict__ alpha_dot, int E, int numTiles)
{
    extern __shared__ char dynsm[];
    __shared__ float sB1[64], sB2[64], sB3[128];
    __shared__ float sBsep[256], sAD[128];
    __shared__ int   sSrc[128], sDst[128];
    __shared__ float sAttr[128];

    const int tid = threadIdx.x;
    const int wid = tid >> 5, lane = tid & 31;
    const int mtx = lane >> 3, rin = lane & 7;
    const int lr = lane >> 2, lc = lane & 3;

    const uint32_t sb = smem_u32(dynsm);
    const uint32_t W1hi = sb;                 // lo at +4096
    const uint32_t W2hi = sb + 8192;          // lo at +8192
    const uint32_t W3hi = sb + 24576, W3lo = sb + 40960;
    const uint32_t Bsm  = sb + 57344;
    const uint32_t Xhi  = sb + 122880;
    const uint32_t Hsm  = sb + 139264;        // H1 and H2 share (named barrier)
    const uint32_t Msrc = sb + 155648;        // becomes A in place
    const uint32_t Mdst = sb + 188416;
    const uint32_t Asm  = Msrc;

    // ---------------- one-time staging ----------------
    CP16(W1hi + tid * 16, g_W1img + tid * 16);
#pragma unroll
    for (int it = 0; it < 2; it++) {
        int i = tid + 512 * it;
        CP16(W2hi + i * 16, g_W2img + i * 16);
    }
#pragma unroll
    for (int it = 0; it < 4; it++) {
        int i = tid + 512 * it;
        CP16(W3hi + i * 16, g_W3img + i * 16);
    }
#pragma unroll
    for (int it = 0; it < 8; it++) {
        int i = tid + 512 * it;
        CP16(Bsm + i * 16, g_Bimg + i * 16);
    }
    CP_COMMIT();
    if (tid < 64)  { sB1[tid] = b1[tid]; sB2[tid] = b2[tid]; }
    if (tid < 128) { sB3[tid] = b3[tid]; sAD[tid] = alpha_dot[tid]; }
    if (tid < 256) sBsep[tid] = b_sep[tid];
    CP_WAIT(0);
    __syncthreads();

    const int mi1 = wid & 7, ni1 = wid >> 3;     // MLP warp tiling
    const int mr = mi1 * 16;
    const int mi = wid & 3, ni = wid >> 2;       // phase2 warp tiling
    const int mrow0 = mi * 32, ncol0 = ni * 64;

    // =================== persistent tile loop ===================
    for (int tile = blockIdx.x; tile < numTiles; tile += gridDim.x) {
        const int e0 = tile * 128;
        __syncthreads();   // previous iteration fully done

        // ---- stage edge indices + X ----
        if (tid < 128) {
            int e = min(e0 + tid, E - 1);
            sSrc[tid] = edge_src[e];
            sDst[tid] = edge_dst[e];
            sAttr[tid] = (e0 + tid < E) ? edge_attr[e] : 0.0f;
        }
#pragma unroll
        for (int it = 0; it < 2; it++) {
            int i = tid + 512 * it;
            int m = i >> 3, k4 = (i & 7) << 2;
            int e = min(e0 + m, E - 1);
            float4 v = *(const float4*)(edge_scalars + (size_t)e * 32 + k4);
            uint32_t hA = packh2(v.x, v.y), hB = packh2(v.z, v.w);
            uint32_t addr = (uint32_t)m * 128 + ((uint32_t)(((k4 >> 3) ^ (m & 7))) << 4) + (k4 & 7) * 2;
            STS64(Xhi + addr, hA, hB);
        }
        __syncthreads();   // indices visible to all, X ready

        // ---- prefetch msg rows via cp.async (hidden under entire MLP) ----
        // global rows are LINEAR; swizzle applied once at the SMEM destination
#pragma unroll
        for (int it = 0; it < 8; it++) {
            int i = tid + 512 * it;           // 0..4095
            int r = (i >> 4) & 127, seg = i & 15, buf = i >> 11;
            int node = buf ? sDst[r] : sSrc[r];
            const unsigned char* srcp =
                (const unsigned char*)(buf ? g_msgh_dst : g_msgh_src) +
                (size_t)node * 256 + seg * 16;
            uint32_t dst = (buf ? Mdst : Msrc) + (uint32_t)r * 256 +
                           ((uint32_t)(seg ^ (r & 7)) << 4);
            CP16(dst, srcp);
        }
        CP_COMMIT();

        // ---- layer1: H = silu(X @ W1 + b1) [128x64, K=32] ----
        {
            const int nc = ni1 * 32;
            float acc[4][4];
#pragma unroll
            for (int i = 0; i < 4; i++)
#pragma unroll
                for (int j = 0; j < 4; j++) acc[i][j] = 0.0f;
#pragma unroll
            for (int ks = 0; ks < 2; ks++) {
                int m = mr + (mtx & 1) * 8 + rin;
                int kc = ks * 2 + (mtx >> 1);
                uint32_t aH[4];
                LDSM4(aH, Xhi + (uint32_t)m * 128 + ((uint32_t)(kc ^ (m & 7)) << 4));
                uint32_t bH[2][4], bL[2][4];
#pragma unroll
                for (int ntp = 0; ntp < 2; ntp++) {
                    int k = ks * 16 + (mtx & 1) * 8 + rin;
                    int nch = (nc >> 3) + ntp * 2 + (mtx >> 1);
                    uint32_t boff = (uint32_t)k * 128 + ((uint32_t)(nch ^ (k & 7)) << 4);
                    LDSM4T(bH[ntp], W1hi + boff);
                    LDSM4T(bL[ntp], W1hi + 4096 + boff);
                }
#pragma unroll
                for (int nt = 0; nt < 4; nt++) {
                    MMA16816(acc[nt], aH, bH[nt >> 1][(nt & 1) * 2], bH[nt >> 1][(nt & 1) * 2 + 1]);
                    MMA16816(acc[nt], aH, bL[nt >> 1][(nt & 1) * 2], bL[nt >> 1][(nt & 1) * 2 + 1]);
                }
            }
#pragma unroll
            for (int nt = 0; nt < 4; nt++) {
                int col = nc + nt * 8 + lc * 2;
                float s0 = silu(acc[nt][0] + sB1[col]);
                float s1 = silu(acc[nt][1] + sB1[col + 1]);
                float s2 = silu(acc[nt][2] + sB1[col]);
                float s3 = silu(acc[nt][3] + sB1[col + 1]);
                int r0 = mr + lr, r1 = r0 + 8;
                uint32_t ad0 = (uint32_t)r0 * 128 + ((uint32_t)((col >> 3) ^ (r0 & 7)) << 4) + (col & 7) * 2;
                STS32(Hsm + ad0, packh2(s0, s1));
                uint32_t ad1 = (uint32_t)r1 * 128 + ((uint32_t)((col >> 3) ^ (r1 & 7)) << 4) + (col & 7) * 2;
                STS32(Hsm + ad1, packh2(s2, s3));
            }
        }
        __syncthreads();

        // ---- layer2: H <- silu(H @ W2 + b2) [128x64, K=64] (in place) ----
        {
            const int nc = ni1 * 32;
            float acc[4][4];
#pragma unroll
            for (int i = 0; i < 4; i++)
#pragma unroll
                for (int j = 0; j < 4; j++) acc[i][j] = 0.0f;
#pragma unroll
            for (int ks = 0; ks < 4; ks++) {
                int m = mr + (mtx & 1) * 8 + rin;
                int kc = ks * 2 + (mtx >> 1);
                uint32_t aH[4];
                LDSM4(aH, Hsm + (uint32_t)m * 128 + ((uint32_t)(kc ^ (m & 7)) << 4));
                uint32_t bH[2][4], bL[2][4];
#pragma unroll
                for (int ntp = 0; ntp < 2; ntp++) {
                    int k = ks * 16 + (mtx & 1) * 8 + rin;
                    int nch = (nc >> 3) + ntp * 2 + (mtx >> 1);
                    uint32_t boff = (uint32_t)k * 128 + ((uint32_t)(nch ^ (k & 7)) << 4);
                    LDSM4T(bH[ntp], W2hi + boff);
                    LDSM4T(bL[ntp], W2hi + 8192 + boff);
                }
#pragma unroll
                for (int nt = 0; nt < 4; nt++) {
                    MMA16816(acc[nt], aH, bH[nt >> 1][(nt & 1) * 2], bH[nt >> 1][(nt & 1) * 2 + 1]);
                    MMA16816(acc[nt], aH, bL[nt >> 1][(nt & 1) * 2], bL[nt >> 1][(nt & 1) * 2 + 1]);
                }
            }
            // pair barrier: warps (mi1, ni1=0/1) both done reading rows
            // mr..mr+15 of H before either overwrites them
            asm volatile("bar.sync %0, 64;" :: "r"(mi1 + 1) : "memory");
#pragma unroll
            for (int nt = 0; nt < 4; nt++) {
                int col = nc + nt * 8 + lc * 2;
                float s0 = silu(acc[nt][0] + sB2[col]);
                float s1 = silu(acc[nt][1] + sB2[col + 1]);
                float s2 = silu(acc[nt][2] + sB2[col]);
                float s3 = silu(acc[nt][3] + sB2[col + 1]);
                int r0 = mr + lr, r1 = r0 + 8;
                uint32_t ad0 = (uint32_t)r0 * 128 + ((uint32_t)((col >> 3) ^ (r0 & 7)) << 4) + (col & 7) * 2;
                STS32(Hsm + ad0, packh2(s0, s1));
                uint32_t ad1 = (uint32_t)r1 * 128 + ((uint32_t)((col >> 3) ^ (r1 & 7)) << 4) + (col & 7) * 2;
                STS32(Hsm + ad1, packh2(s2, s3));
            }
        }
        __syncthreads();

        // ---- layer3: rad = H @ W3 + b3 [128x128, K=64] (regs) ----
        float acc3[8][4];
#pragma unroll
        for (int i = 0; i < 8; i++)
#pragma unroll
            for (int j = 0; j < 4; j++) acc3[i][j] = 0.0f;
        {
            const int nc = ni1 * 64;
#pragma unroll
            for (int ks = 0; ks < 4; ks++) {
                int m = mr + (mtx & 1) * 8 + rin;
                int kc = ks * 2 + (mtx >> 1);
                uint32_t aH[4];
                LDSM4(aH, Hsm + (uint32_t)m * 128 + ((uint32_t)(kc ^ (m & 7)) << 4));
                uint32_t bH[4][4];
#pragma unroll
                for (int ntp = 0; ntp < 4; ntp++) {
                    int k = ks * 16 + (mtx & 1) * 8 + rin;
                    int nch = (nc >> 3) + ntp * 2 + (mtx >> 1);
                    uint32_t boff = (uint32_t)k * 256 + ((uint32_t)(nch ^ (k & 7)) << 4);
                    LDSM4T(bH[ntp], W3hi + boff);
                }
#pragma unroll
                for (int nt = 0; nt < 8; nt++)
                    MMA16816(acc3[nt], aH, bH[nt >> 1][(nt & 1) * 2], bH[nt >> 1][(nt & 1) * 2 + 1]);
                uint32_t bL[4][4];
#pragma unroll
                for (int ntp = 0; ntp < 4; ntp++) {
                    int k = ks * 16 + (mtx & 1) * 8 + rin;
                    int nch = (nc >> 3) + ntp * 2 + (mtx >> 1);
                    uint32_t boff = (uint32_t)k * 256 + ((uint32_t)(nch ^ (k & 7)) << 4);
                    LDSM4T(bL[ntp], W3lo + boff);
                }
#pragma unroll
                for (int nt = 0; nt < 8; nt++)
                    MMA16816(acc3[nt], aH, bL[nt >> 1][(nt & 1) * 2], bL[nt >> 1][(nt & 1) * 2 + 1]);
            }
        }
        CP_WAIT(0);        // msg rows landed (overlapped with the MLP)
        __syncthreads();

        // ---- gather from SMEM + form A = (src+dst)*attr*rad (in place) ----
        {
            const int nc = ni1 * 64;
#pragma unroll
            for (int rh = 0; rh < 2; rh++) {
                int r = mr + rh * 8 + lr;
                float at = sAttr[r];
#pragma unroll
                for (int nt = 0; nt < 8; nt++) {
                    int col = nc + nt * 8 + lc * 2;
                    uint32_t ad = (uint32_t)r * 256 + ((uint32_t)((col >> 3) ^ (r & 7)) << 4) + (col & 7) * 2;
                    uint32_t us, ud;
                    LDS32(us, Msrc + ad);
                    LDS32(ud, Mdst + ad);
                    float2 ms = __half22float2(*(__half2*)&us);
                    float2 md = __half22float2(*(__half2*)&ud);
                    float rad0 = acc3[nt][rh * 2 + 0] + sB3[col];
                    float rad1 = acc3[nt][rh * 2 + 1] + sB3[col + 1];
                    float m0 = (ms.x + md.x) * at * rad0;
                    float m1 = (ms.y + md.y) * at * rad1;
                    STS32(Asm + ad, packh2(m0, m1));
                }
            }
        }
        __syncthreads();

        // ---- phase2: D[128,256] = A @ B + epilogue ----
        float d[2][8][4];
#pragma unroll
        for (int a = 0; a < 2; a++)
#pragma unroll
            for (int b = 0; b < 8; b++)
#pragma unroll
                for (int c = 0; c < 4; c++) d[a][b][c] = 0.0f;

#pragma unroll
        for (int ks = 0; ks < 8; ks++) {
            uint32_t ah[2][4];
#pragma unroll
            for (int mt = 0; mt < 2; mt++) {
                int m = mrow0 + mt * 16 + (mtx & 1) * 8 + rin;
                int kchunk = ks * 2 + (mtx >> 1);
                LDSM4(ah[mt], Asm + (uint32_t)m * 256 + ((uint32_t)(kchunk ^ (m & 7)) << 4));
            }
            uint32_t b[4][4];
#pragma unroll
            for (int ntp = 0; ntp < 4; ntp++) {
                int k = ks * 16 + (mtx & 1) * 8 + rin;
                int nchunk = (ncol0 >> 3) + ntp * 2 + (mtx >> 1);
                LDSM4T(b[ntp], Bsm + (uint32_t)k * 512 + ((uint32_t)(nchunk ^ (k & 7)) << 4));
            }
#pragma unroll
            for (int mt = 0; mt < 2; mt++)
#pragma unroll
                for (int nt = 0; nt < 8; nt++)
                    MMA16816(d[mt][nt], ah[mt], b[nt >> 1][(nt & 1) * 2], b[nt >> 1][(nt & 1) * 2 + 1]);
        }

        // ---- epilogue: w = exp(score); direct segment reduction ----
#pragma unroll
        for (int hh = 0; hh < 2; hh++) {
            const int h = ni * 2 + hh;
#pragma unroll
            for (int mt = 0; mt < 2; mt++) {
                const int r0i = mrow0 + mt * 16 + lr;
                const int e0i = e0 + r0i;
                float p0 = 0.0f, p1 = 0.0f;
#pragma unroll
                for (int q = 0; q < 2; q++) {
                    const int nt = hh * 4 + q;
                    const int colb = ncol0 + nt * 8 + lc * 2;
                    const int jb = q * 8 + lc * 2;
                    const float bb0 = sBsep[colb], bb1 = sBsep[colb + 1];
                    const float w0 = sAD[h * 16 + jb], w1 = sAD[h * 16 + jb + 1];
                    float x, sg;
                    x = d[mt][nt][0] + bb0; sg = 1.0f / (1.0f + __expf(-x)); p0 += x * (0.2f + 0.8f * sg) * w0;
                    x = d[mt][nt][1] + bb1; sg = 1.0f / (1.0f + __expf(-x)); p0 += x * (0.2f + 0.8f * sg) * w1;
                    x = d[mt][nt][2] + bb0; sg = 1.0f / (1.0f + __expf(-x)); p1 += x * (0.2f + 0.8f * sg) * w0;
                    x = d[mt][nt][3] + bb1; sg = 1.0f / (1.0f + __expf(-x)); p1 += x * (0.2f + 0.8f * sg) * w1;
                }
                p0 += __shfl_xor_sync(0xffffffffu, p0, 1);
                p0 += __shfl_xor_sync(0xffffffffu, p0, 2);
                p1 += __shfl_xor_sync(0xffffffffu, p1, 1);
                p1 += __shfl_xor_sync(0xffffffffu, p1, 2);
                const float ew0 = __expf(p0), ew1 = __expf(p1);
                const int d0 = sDst[r0i], d1 = sDst[r0i + 8];
                if (lc == 0) {
                    if (e0i < E)     atomicAdd(&g_nsum[(size_t)d0 * 8 + h], ew0);
                    if (e0i + 8 < E) atomicAdd(&g_nsum[(size_t)d1 * 8 + h], ew1);
                }
#pragma unroll
                for (int q = 0; q < 2; q++) {
                    const int nt = hh * 4 + 2 + q;
                    const int colb = ncol0 + nt * 8 + lc * 2;
                    const int vidx = q * 8 + lc * 2;
                    const float bb0 = sBsep[colb], bb1 = sBsep[colb + 1];
                    if (e0i < E)
                        RED2(g_nacc + (size_t)d0 * 128 + h * 16 + vidx,
                             (d[mt][nt][0] + bb0) * ew0, (d[mt][nt][1] + bb1) * ew0);
                    if (e0i + 8 < E)
                        RED2(g_nacc + (size_t)d1 * 128 + h * 16 + vidx,
                             (d[mt][nt][2] + bb0) * ew1, (d[mt][nt][3] + bb1) * ew1);
                }
            }
        }
    }
}

// ---------------- K5: out = (nacc / (nsum+eps)) @ w_proj + b_proj -----------
__global__ __launch_bounds__(256) void out_gemm_kernel(
    const float* __restrict__ W, const float* __restrict__ bias,
    float* __restrict__ out, int n)
{
    __shared__ float At[32 * 64];
    __shared__ float Bs[32 * 128];
    int tid = threadIdx.x;
    int r0 = blockIdx.x * 64;
    int cg = tid & 15, rg = tid >> 4;
    int col = cg * 8, row = rg * 4;

    float acc[4][8];
#pragma unroll
    for (int i = 0; i < 4; i++)
#pragma unroll
        for (int j = 0; j < 8; j++) acc[i][j] = 0.0f;

    int lm = tid >> 2, lk = (tid & 3) * 8;
    int lkr = tid >> 3, lc = (tid & 7) * 16;

    for (int k0 = 0; k0 < 128; k0 += 32) {
        float4 a0, a1;
        int gr = r0 + lm;
        if (gr < n) {
            a0 = *(const float4*)(g_nacc + (size_t)gr * 128 + k0 + lk);
            a1 = *(const float4*)(g_nacc + (size_t)gr * 128 + k0 + lk + 4);
            int hh = (k0 + lk) >> 4;
            float inv = 1.0f / (g_nsum[(size_t)gr * 8 + hh] + 1e-16f);
            a0.x *= inv; a0.y *= inv; a0.z *= inv; a0.w *= inv;
            a1.x *= inv; a1.y *= inv; a1.z *= inv; a1.w *= inv;
        } else {
            a0 = make_float4(0.f, 0.f, 0.f, 0.f); a1 = a0;
        }
        At[(lk + 0) * 64 + lm] = a0.x; At[(lk + 1) * 64 + lm] = a0.y;
        At[(lk + 2) * 64 + lm] = a0.z; At[(lk + 3) * 64 + lm] = a0.w;
        At[(lk + 4) * 64 + lm] = a1.x; At[(lk + 5) * 64 + lm] = a1.y;
        At[(lk + 6) * 64 + lm] = a1.z; At[(lk + 7) * 64 + lm] = a1.w;
#pragma unroll
        for (int q = 0; q < 4; q++)
            *(float4*)(Bs + lkr * 128 + lc + 4 * q) =
                *(const float4*)(W + (size_t)(k0 + lkr) * 128 + lc + 4 * q);
        __syncthreads();
#pragma unroll
        for (int kk = 0; kk < 32; kk++) {
            float a[4], b[8];
            *(float4*)a       = *(float4*)(At + kk * 64 + row);
            *(float4*)(b)     = *(float4*)(Bs + kk * 128 + col);
            *(float4*)(b + 4) = *(float4*)(Bs + kk * 128 + col + 4);
#pragma unroll
            for (int i = 0; i < 4; i++)
#pragma unroll
                for (int j = 0; j < 8; j++) acc[i][j] += a[i] * b[j];
        }
        __syncthreads();
    }

    float bj[8];
    *(float4*)(bj)     = *(const float4*)(bias + col);
    *(float4*)(bj + 4) = *(const float4*)(bias + col + 4);
#pragma unroll
    for (int i = 0; i < 4; i++) {
        int gr = r0 + row + i;
        if (gr >= n) continue;
        float4 o0 = make_float4(acc[i][0] + bj[0], acc[i][1] + bj[1],
                                acc[i][2] + bj[2], acc[i][3] + bj[3]);
        float4 o1 = make_float4(acc[i][4] + bj[4], acc[i][5] + bj[5],
                                acc[i][6] + bj[6], acc[i][7] + bj[7]);
        *(float4*)(out + (size_t)gr * 128 + col)     = o0;
        *(float4*)(out + (size_t)gr * 128 + col + 4) = o1;
    }
}

// ---------------- launch ----------------
extern "C" void kernel_launch(void* const* d_in, const int* in_sizes, int n_in,
                              void* d_out, int out_size)
{
    const float* node_input = (const float*)d_in[0];
    const float* edge_attr  = (const float*)d_in[2];
    const float* edge_scal  = (const float*)d_in[3];
    const int*   edge_src   = (const int*)d_in[4];
    const int*   edge_dst   = (const int*)d_in[5];
    const float* w_src      = (const float*)d_in[7];
    const float* b_src      = (const float*)d_in[8];
    const float* w_dst      = (const float*)d_in[9];
    const float* fc_w1      = (const float*)d_in[10];
    const float* fc_b1      = (const float*)d_in[11];
    const float* fc_w2      = (const float*)d_in[12];
    const float* fc_b2      = (const float*)d_in[13];
    const float* fc_w3      = (const float*)d_in[14];
    const float* fc_b3      = (const float*)d_in[15];
    const float* w_sep      = (const float*)d_in[16];
    const float* b_sep      = (const float*)d_in[17];
    const float* alpha_dot  = (const float*)d_in[18];
    const float* w_proj     = (const float*)d_in[19];
    const float* b_proj     = (const float*)d_in[20];
    float* out = (float*)d_out;

    int N = in_sizes[0] / 128;
    int E = in_sizes[4];

    cudaFuncSetAttribute(fused_edge_kernel, cudaFuncAttributeMaxDynamicSharedMemorySize, 221184);

    static int sms = 0;
    if (sms == 0) {
        cudaDeviceGetAttribute(&sms, cudaDevAttrMultiProcessorCount, 0);
        if (sms <= 0) sms = 148;
    }

    init_kernel<<<(N * 128 + 255) / 256, 256>>>(N);
    prep_kernel<<<46, 256>>>(fc_w1, fc_w2, fc_w3, w_sep);

    int nb = (N + 63) / 64;
    node_gemm_dual<<<nb, 256>>>(node_input, w_src, w_dst, b_src, N);

    int numTiles = (E + 127) / 128;
    int nblk = numTiles < sms ? numTiles : sms;
    fused_edge_kernel<<<nblk, 512, 221184>>>(edge_scal, edge_attr, edge_src, edge_dst,
                                             fc_b1, fc_b2, fc_b3,
                                             b_sep, alpha_dot, E, numTiles);

    out_gemm_kernel<<<nb, 256>>>(w_proj, b_proj, out, N);
}

// round 13
// speedup vs baseline: 1.4807x; 1.2627x over previous
#include <cuda_runtime.h>
#include <cuda_fp16.h>
#include <cstdint>
#include <math.h>

// ---------------- fixed problem geometry ----------------
#define MAXN 50000
#define MAXE 800000
// C=128, A_ALL=256, RAD_IN=32, FC1=FC2=64, H=8, AH=VH=16

// ---------------- scratch ----------------
__device__ __align__(16) __half g_msgh_src[(size_t)MAXN * 128];   // LINEAR rows
__device__ __align__(16) __half g_msgh_dst[(size_t)MAXN * 128];   // LINEAR rows
__device__ __align__(16) float g_nsum[(size_t)MAXN * 8];
__device__ __align__(16) float g_nacc[(size_t)MAXN * 128];
// prepacked fp16 weight images (exact SMEM layouts, swizzled)
__device__ __align__(16) unsigned char g_Bimg[65536];    // w_sep [k][n] 256n
__device__ __align__(16) unsigned char g_W1img[8192];    // hi @0, lo @4096
__device__ __align__(16) unsigned char g_W2img[16384];   // hi @0, lo @8192
__device__ __align__(16) unsigned char g_W3img[32768];   // hi @0, lo @16384
__device__ __align__(16) unsigned char g_BnodeImg[65536];// [w_src|w_dst] [k][256n]
__device__ __align__(16) unsigned char g_PImg[32768];    // w_proj [k][128n]

// ---------------- helpers ----------------
__device__ __forceinline__ uint32_t smem_u32(const void* p) {
    uint32_t a;
    asm("{ .reg .u64 t; cvta.to.shared.u64 t, %1; cvt.u32.u64 %0, t; }"
        : "=r"(a) : "l"(p));
    return a;
}

#define LDSM4(r, addr) \
    asm volatile("ldmatrix.sync.aligned.m8n8.x4.shared.b16 {%0,%1,%2,%3}, [%4];" \
        : "=r"((r)[0]), "=r"((r)[1]), "=r"((r)[2]), "=r"((r)[3]) : "r"(addr))

#define LDSM4T(r, addr) \
    asm volatile("ldmatrix.sync.aligned.m8n8.x4.trans.shared.b16 {%0,%1,%2,%3}, [%4];" \
        : "=r"((r)[0]), "=r"((r)[1]), "=r"((r)[2]), "=r"((r)[3]) : "r"(addr))

#define MMA16816(d, a, b0v, b1v) \
    asm volatile("mma.sync.aligned.m16n8k16.row.col.f32.f16.f16.f32 " \
        "{%0,%1,%2,%3}, {%4,%5,%6,%7}, {%8,%9}, {%0,%1,%2,%3};" \
        : "+f"((d)[0]), "+f"((d)[1]), "+f"((d)[2]), "+f"((d)[3]) \
        : "r"((a)[0]), "r"((a)[1]), "r"((a)[2]), "r"((a)[3]), "r"(b0v), "r"(b1v))

#define STS32(addr, v) \
    asm volatile("st.shared.b32 [%0], %1;" :: "r"(addr), "r"(v))
#define STS64(addr, v0, v1) \
    asm volatile("st.shared.v2.b32 [%0], {%1,%2};" :: "r"(addr), "r"(v0), "r"(v1))
#define LDS32(v, addr) \
    asm volatile("ld.shared.b32 %0, [%1];" : "=r"(v) : "r"(addr))

// async 16B global->shared copy (sm_80+)
#define CP16(dst, src) \
    asm volatile("{ .reg .u64 g; cvta.to.global.u64 g, %1; " \
                 "cp.async.cg.shared.global [%0], [g], 16; }" \
                 :: "r"(dst), "l"(src) : "memory")
#define CP_COMMIT() asm volatile("cp.async.commit_group;" ::: "memory")
#define CP_WAIT(n)  asm volatile("cp.async.wait_group %0;" :: "n"(n) : "memory")

// vector fire-and-forget global reduction (sm_90+)
#define RED2(ptr, x, y) \
    asm volatile("red.global.add.v2.f32 [%0], {%1,%2};" :: "l"(ptr), "f"(x), "f"(y) : "memory")

__device__ __forceinline__ uint32_t packh2(float x, float y) {
    __half2 t = __floats2half2_rn(x, y);
    return *(uint32_t*)&t;
}
__device__ __forceinline__ void split2(float x, float y, uint32_t& hi, uint32_t& lo) {
    __half h0 = __float2half_rn(x), h1 = __float2half_rn(y);
    __half2 hh = __halves2half2(h0, h1);
    hi = *(uint32_t*)&hh;
    lo = packh2(x - __half2float(h0), y - __half2float(h1));
}
__device__ __forceinline__ void split4(float4 v, uint32_t& hA, uint32_t& hB,
                                       uint32_t& lA, uint32_t& lB) {
    split2(v.x, v.y, hA, lA);
    split2(v.z, v.w, hB, lB);
}
__device__ __forceinline__ float silu(float x) {
    return x / (1.0f + __expf(-x));
}

// ---------------- K0: init segment buffers ----------------
__global__ void init_kernel(int n) {
    int i = blockIdx.x * blockDim.x + threadIdx.x;
    if (i < n * 128) g_nacc[i] = 0.0f;
    if (i < n * 8) g_nsum[i] = 0.0f;
}

// ---------------- K0b: prepack weight images (fp16, swizzled SMEM layout) --
__global__ void prep_kernel(const float* __restrict__ w1, const float* __restrict__ w2,
                            const float* __restrict__ w3, const float* __restrict__ w_sep,
                            const float* __restrict__ w_src, const float* __restrict__ w_dst,
                            const float* __restrict__ w_proj)
{
    int idx = blockIdx.x * blockDim.x + threadIdx.x;  // float4 units
    if (idx < 8192) {                       // w_sep: 128 x 256, rows 512B
        int k = idx >> 6, n4 = (idx & 63) << 2;
        float4 v = *(const float4*)(w_sep + (size_t)k * 256 + n4);
        uint32_t hA = packh2(v.x, v.y), hB = packh2(v.z, v.w);
        uint32_t addr = (uint32_t)k * 512 + ((uint32_t)((n4 >> 3) ^ (k & 7)) << 4) + (n4 & 7) * 2;
        *(uint2*)(g_Bimg + addr) = make_uint2(hA, hB);
    } else if (idx < 8704) {                // w1: 32 x 64, rows 128B
        int i = idx - 8192;
        int k = i >> 4, n4 = (i & 15) << 2;
        float4 v = *(const float4*)(w1 + (size_t)k * 64 + n4);
        uint32_t hA, hB, lA, lB; split4(v, hA, hB, lA, lB);
        uint32_t addr = (uint32_t)k * 128 + ((uint32_t)((n4 >> 3) ^ (k & 7)) << 4) + (n4 & 7) * 2;
        *(uint2*)(g_W1img + addr) = make_uint2(hA, hB);
        *(uint2*)(g_W1img + 4096 + addr) = make_uint2(lA, lB);
    } else if (idx < 9728) {                // w2: 64 x 64, rows 128B
        int i = idx - 8704;
        int k = i >> 4, n4 = (i & 15) << 2;
        float4 v = *(const float4*)(w2 + (size_t)k * 64 + n4);
        uint32_t hA, hB, lA, lB; split4(v, hA, hB, lA, lB);
        uint32_t addr = (uint32_t)k * 128 + ((uint32_t)((n4 >> 3) ^ (k & 7)) << 4) + (n4 & 7) * 2;
        *(uint2*)(g_W2img + addr) = make_uint2(hA, hB);
        *(uint2*)(g_W2img + 8192 + addr) = make_uint2(lA, lB);
    } else if (idx < 11776) {               // w3: 64 x 128, rows 256B
        int i = idx - 9728;
        int k = i >> 5, n4 = (i & 31) << 2;
        float4 v = *(const float4*)(w3 + (size_t)k * 128 + n4);
        uint32_t hA, hB, lA, lB; split4(v, hA, hB, lA, lB);
        uint32_t addr = (uint32_t)k * 256 + ((uint32_t)((n4 >> 3) ^ (k & 7)) << 4) + (n4 & 7) * 2;
        *(uint2*)(g_W3img + addr) = make_uint2(hA, hB);
        *(uint2*)(g_W3img + 16384 + addr) = make_uint2(lA, lB);
    } else if (idx < 19968) {               // Bnode = [w_src|w_dst]: 128 x 256, rows 512B
        int i = idx - 11776;
        int k = i >> 6, n4 = (i & 63) << 2;
        float4 v = (n4 < 128)
            ? *(const float4*)(w_src + (size_t)k * 128 + n4)
            : *(const float4*)(w_dst + (size_t)k * 128 + (n4 - 128));
        uint32_t hA = packh2(v.x, v.y), hB = packh2(v.z, v.w);
        uint32_t addr = (uint32_t)k * 512 + ((uint32_t)((n4 >> 3) ^ (k & 7)) << 4) + (n4 & 7) * 2;
        *(uint2*)(g_BnodeImg + addr) = make_uint2(hA, hB);
    } else if (idx < 24064) {               // w_proj: 128 x 128, rows 256B
        int i = idx - 19968;
        int k = i >> 5, n4 = (i & 31) << 2;
        float4 v = *(const float4*)(w_proj + (size_t)k * 128 + n4);
        uint32_t hA = packh2(v.x, v.y), hB = packh2(v.z, v.w);
        uint32_t addr = (uint32_t)k * 256 + ((uint32_t)((n4 >> 3) ^ (k & 7)) << 4) + (n4 & 7) * 2;
        *(uint2*)(g_PImg + addr) = make_uint2(hA, hB);
    }
}

// ---------------- K1: node GEMM on HMMA -> fp16 msg arrays (LINEAR rows) ----
// D[128,256] = split(node_input[128,128]) @ [w_src|w_dst]; 2-pass A hi/lo.
__global__ __launch_bounds__(512, 1) void node_mma_kernel(
    const float* __restrict__ X, const float* __restrict__ bias_src, int n)
{
    extern __shared__ char dynsm[];
    __shared__ float sBias[128];
    const int tid = threadIdx.x;
    const int wid = tid >> 5, lane = tid & 31;
    const int mtx = lane >> 3, rin = lane & 7;
    const int lr = lane >> 2, lc = lane & 3;
    const int r0 = blockIdx.x * 128;

    const uint32_t sb = smem_u32(dynsm);
    const uint32_t Ahi = sb, Alo = sb + 32768, Bsm = sb + 65536;

    // stage B (4096 x 16B) async
#pragma unroll
    for (int it = 0; it < 8; it++) {
        int i = tid + 512 * it;
        CP16(Bsm + i * 16, g_BnodeImg + i * 16);
    }
    CP_COMMIT();
    if (tid < 128) sBias[tid] = bias_src[tid];

    // stage A hi/lo
#pragma unroll
    for (int it = 0; it < 8; it++) {
        int i = tid + 512 * it;
        int m = i >> 5, k4 = (i & 31) << 2;
        int gr = r0 + m;
        float4 v = make_float4(0.f, 0.f, 0.f, 0.f);
        if (gr < n) v = *(const float4*)(X + (size_t)gr * 128 + k4);
        uint32_t hA, hB, lA, lB; split4(v, hA, hB, lA, lB);
        uint32_t addr = (uint32_t)m * 256 + ((uint32_t)((k4 >> 3) ^ (m & 7)) << 4) + (k4 & 7) * 2;
        STS64(Ahi + addr, hA, hB);
        STS64(Alo + addr, lA, lB);
    }
    CP_WAIT(0);
    __syncthreads();

    const int mi = wid & 3, ni = wid >> 2;
    const int mrow0 = mi * 32, ncol0 = ni * 64;

    float d[2][8][4];
#pragma unroll
    for (int a = 0; a < 2; a++)
#pragma unroll
        for (int b = 0; b < 8; b++)
#pragma unroll
            for (int c = 0; c < 4; c++) d[a][b][c] = 0.0f;

#pragma unroll
    for (int ks = 0; ks < 8; ks++) {
        uint32_t ah[2][4], al[2][4];
#pragma unroll
        for (int mt = 0; mt < 2; mt++) {
            int m = mrow0 + mt * 16 + (mtx & 1) * 8 + rin;
            int kchunk = ks * 2 + (mtx >> 1);
            uint32_t ao = (uint32_t)m * 256 + ((uint32_t)(kchunk ^ (m & 7)) << 4);
            LDSM4(ah[mt], Ahi + ao);
            LDSM4(al[mt], Alo + ao);
        }
        uint32_t b[4][4];
#pragma unroll
        for (int ntp = 0; ntp < 4; ntp++) {
            int k = ks * 16 + (mtx & 1) * 8 + rin;
            int nchunk = (ncol0 >> 3) + ntp * 2 + (mtx >> 1);
            LDSM4T(b[ntp], Bsm + (uint32_t)k * 512 + ((uint32_t)(nchunk ^ (k & 7)) << 4));
        }
#pragma unroll
        for (int mt = 0; mt < 2; mt++)
#pragma unroll
            for (int nt = 0; nt < 8; nt++) {
                MMA16816(d[mt][nt], ah[mt], b[nt >> 1][(nt & 1) * 2], b[nt >> 1][(nt & 1) * 2 + 1]);
                MMA16816(d[mt][nt], al[mt], b[nt >> 1][(nt & 1) * 2], b[nt >> 1][(nt & 1) * 2 + 1]);
            }
    }

    // epilogue: cols<128 -> msg_src (+bias); cols>=128 -> msg_dst
#pragma unroll
    for (int mt = 0; mt < 2; mt++) {
        int gr0 = r0 + mrow0 + mt * 16 + lr;
        int gr1 = gr0 + 8;
#pragma unroll
        for (int nt = 0; nt < 8; nt++) {
            int cg = ncol0 + nt * 8 + lc * 2;
            float bb0 = 0.0f, bb1 = 0.0f;
            unsigned char* buf;
            int c;
            if (cg < 128) { buf = (unsigned char*)g_msgh_src; c = cg; bb0 = sBias[c]; bb1 = sBias[c + 1]; }
            else          { buf = (unsigned char*)g_msgh_dst; c = cg - 128; }
            if (gr0 < n)
                *(uint32_t*)(buf + (size_t)gr0 * 256 + c * 2) =
                    packh2(d[mt][nt][0] + bb0, d[mt][nt][1] + bb1);
            if (gr1 < n)
                *(uint32_t*)(buf + (size_t)gr1 * 256 + c * 2) =
                    packh2(d[mt][nt][2] + bb0, d[mt][nt][3] + bb1);
        }
    }
}

// ============================================================================
// K23: PERSISTENT fused kernel (unchanged from R12)
// ============================================================================
__global__ __launch_bounds__(512, 1) void fused_edge_kernel(
    const float* __restrict__ edge_scalars, const float* __restrict__ edge_attr,
    const int* __restrict__ edge_src, const int* __restrict__ edge_dst,
    const float* __restrict__ b1, const float* __restrict__ b2,
    const float* __restrict__ b3, const float* __restrict__ b_sep,
    const float* __restrict__ alpha_dot, int E, int numTiles)
{
    extern __shared__ char dynsm[];
    __shared__ float sB1[64], sB2[64], sB3[128];
    __shared__ float sBsep[256], sAD[128];
    __shared__ int   sSrc[128], sDst[128];
    __shared__ float sAttr[128];

    const int tid = threadIdx.x;
    const int wid = tid >> 5, lane = tid & 31;
    const int mtx = lane >> 3, rin = lane & 7;
    const int lr = lane >> 2, lc = lane & 3;

    const uint32_t sb = smem_u32(dynsm);
    const uint32_t W1hi = sb;
    const uint32_t W2hi = sb + 8192;
    const uint32_t W3hi = sb + 24576, W3lo = sb + 40960;
    const uint32_t Bsm  = sb + 57344;
    const uint32_t Xhi  = sb + 122880;
    const uint32_t Hsm  = sb + 139264;
    const uint32_t Msrc = sb + 155648;
    const uint32_t Mdst = sb + 188416;
    const uint32_t Asm  = Msrc;

    CP16(W1hi + tid * 16, g_W1img + tid * 16);
#pragma unroll
    for (int it = 0; it < 2; it++) {
        int i = tid + 512 * it;
        CP16(W2hi + i * 16, g_W2img + i * 16);
    }
#pragma unroll
    for (int it = 0; it < 4; it++) {
        int i = tid + 512 * it;
        CP16(W3hi + i * 16, g_W3img + i * 16);
    }
#pragma unroll
    for (int it = 0; it < 8; it++) {
        int i = tid + 512 * it;
        CP16(Bsm + i * 16, g_Bimg + i * 16);
    }
    CP_COMMIT();
    if (tid < 64)  { sB1[tid] = b1[tid]; sB2[tid] = b2[tid]; }
    if (tid < 128) { sB3[tid] = b3[tid]; sAD[tid] = alpha_dot[tid]; }
    if (tid < 256) sBsep[tid] = b_sep[tid];
    CP_WAIT(0);
    __syncthreads();

    const int mi1 = wid & 7, ni1 = wid >> 3;
    const int mr = mi1 * 16;
    const int mi = wid & 3, ni = wid >> 2;
    const int mrow0 = mi * 32, ncol0 = ni * 64;

    for (int tile = blockIdx.x; tile < numTiles; tile += gridDim.x) {
        const int e0 = tile * 128;
        __syncthreads();

        if (tid < 128) {
            int e = min(e0 + tid, E - 1);
            sSrc[tid] = edge_src[e];
            sDst[tid] = edge_dst[e];
            sAttr[tid] = (e0 + tid < E) ? edge_attr[e] : 0.0f;
        }
#pragma unroll
        for (int it = 0; it < 2; it++) {
            int i = tid + 512 * it;
            int m = i >> 3, k4 = (i & 7) << 2;
            int e = min(e0 + m, E - 1);
            float4 v = *(const float4*)(edge_scalars + (size_t)e * 32 + k4);
            uint32_t hA = packh2(v.x, v.y), hB = packh2(v.z, v.w);
            uint32_t addr = (uint32_t)m * 128 + ((uint32_t)(((k4 >> 3) ^ (m & 7))) << 4) + (k4 & 7) * 2;
            STS64(Xhi + addr, hA, hB);
        }
        __syncthreads();

#pragma unroll
        for (int it = 0; it < 8; it++) {
            int i = tid + 512 * it;
            int r = (i >> 4) & 127, seg = i & 15, buf = i >> 11;
            int node = buf ? sDst[r] : sSrc[r];
            const unsigned char* srcp =
                (const unsigned char*)(buf ? g_msgh_dst : g_msgh_src) +
                (size_t)node * 256 + seg * 16;
            uint32_t dst = (buf ? Mdst : Msrc) + (uint32_t)r * 256 +
                           ((uint32_t)(seg ^ (r & 7)) << 4);
            CP16(dst, srcp);
        }
        CP_COMMIT();

        {
            const int nc = ni1 * 32;
            float acc[4][4];
#pragma unroll
            for (int i = 0; i < 4; i++)
#pragma unroll
                for (int j = 0; j < 4; j++) acc[i][j] = 0.0f;
#pragma unroll
            for (int ks = 0; ks < 2; ks++) {
                int m = mr + (mtx & 1) * 8 + rin;
                int kc = ks * 2 + (mtx >> 1);
                uint32_t aH[4];
                LDSM4(aH, Xhi + (uint32_t)m * 128 + ((uint32_t)(kc ^ (m & 7)) << 4));
                uint32_t bH[2][4], bL[2][4];
#pragma unroll
                for (int ntp = 0; ntp < 2; ntp++) {
                    int k = ks * 16 + (mtx & 1) * 8 + rin;
                    int nch = (nc >> 3) + ntp * 2 + (mtx >> 1);
                    uint32_t boff = (uint32_t)k * 128 + ((uint32_t)(nch ^ (k & 7)) << 4);
                    LDSM4T(bH[ntp], W1hi + boff);
                    LDSM4T(bL[ntp], W1hi + 4096 + boff);
                }
#pragma unroll
                for (int nt = 0; nt < 4; nt++) {
                    MMA16816(acc[nt], aH, bH[nt >> 1][(nt & 1) * 2], bH[nt >> 1][(nt & 1) * 2 + 1]);
                    MMA16816(acc[nt], aH, bL[nt >> 1][(nt & 1) * 2], bL[nt >> 1][(nt & 1) * 2 + 1]);
                }
            }
#pragma unroll
            for (int nt = 0; nt < 4; nt++) {
                int col = nc + nt * 8 + lc * 2;
                float s0 = silu(acc[nt][0] + sB1[col]);
                float s1 = silu(acc[nt][1] + sB1[col + 1]);
                float s2 = silu(acc[nt][2] + sB1[col]);
                float s3 = silu(acc[nt][3] + sB1[col + 1]);
                int r0 = mr + lr, r1 = r0 + 8;
                uint32_t ad0 = (uint32_t)r0 * 128 + ((uint32_t)((col >> 3) ^ (r0 & 7)) << 4) + (col & 7) * 2;
                STS32(Hsm + ad0, packh2(s0, s1));
                uint32_t ad1 = (uint32_t)r1 * 128 + ((uint32_t)((col >> 3) ^ (r1 & 7)) << 4) + (col & 7) * 2;
                STS32(Hsm + ad1, packh2(s2, s3));
            }
        }
        __syncthreads();

        {
            const int nc = ni1 * 32;
            float acc[4][4];
#pragma unroll
            for (int i = 0; i < 4; i++)
#pragma unroll
                for (int j = 0; j < 4; j++) acc[i][j] = 0.0f;
#pragma unroll
            for (int ks = 0; ks < 4; ks++) {
                int m = mr + (mtx & 1) * 8 + rin;
                int kc = ks * 2 + (mtx >> 1);
                uint32_t aH[4];
                LDSM4(aH, Hsm + (uint32_t)m * 128 + ((uint32_t)(kc ^ (m & 7)) << 4));
                uint32_t bH[2][4], bL[2][4];
#pragma unroll
                for (int ntp = 0; ntp < 2; ntp++) {
                    int k = ks * 16 + (mtx & 1) * 8 + rin;
                    int nch = (nc >> 3) + ntp * 2 + (mtx >> 1);
                    uint32_t boff = (uint32_t)k * 128 + ((uint32_t)(nch ^ (k & 7)) << 4);
                    LDSM4T(bH[ntp], W2hi + boff);
                    LDSM4T(bL[ntp], W2hi + 8192 + boff);
                }
#pragma unroll
                for (int nt = 0; nt < 4; nt++) {
                    MMA16816(acc[nt], aH, bH[nt >> 1][(nt & 1) * 2], bH[nt >> 1][(nt & 1) * 2 + 1]);
                    MMA16816(acc[nt], aH, bL[nt >> 1][(nt & 1) * 2], bL[nt >> 1][(nt & 1) * 2 + 1]);
                }
            }
            asm volatile("bar.sync %0, 64;" :: "r"(mi1 + 1) : "memory");
#pragma unroll
            for (int nt = 0; nt < 4; nt++) {
                int col = nc + nt * 8 + lc * 2;
                float s0 = silu(acc[nt][0] + sB2[col]);
                float s1 = silu(acc[nt][1] + sB2[col + 1]);
                float s2 = silu(acc[nt][2] + sB2[col]);
                float s3 = silu(acc[nt][3] + sB2[col + 1]);
                int r0 = mr + lr, r1 = r0 + 8;
                uint32_t ad0 = (uint32_t)r0 * 128 + ((uint32_t)((col >> 3) ^ (r0 & 7)) << 4) + (col & 7) * 2;
                STS32(Hsm + ad0, packh2(s0, s1));
                uint32_t ad1 = (uint32_t)r1 * 128 + ((uint32_t)((col >> 3) ^ (r1 & 7)) << 4) + (col & 7) * 2;
                STS32(Hsm + ad1, packh2(s2, s3));
            }
        }
        __syncthreads();

        float acc3[8][4];
#pragma unroll
        for (int i = 0; i < 8; i++)
#pragma unroll
            for (int j = 0; j < 4; j++) acc3[i][j] = 0.0f;
        {
            const int nc = ni1 * 64;
#pragma unroll
            for (int ks = 0; ks < 4; ks++) {
                int m = mr + (mtx & 1) * 8 + rin;
                int kc = ks * 2 + (mtx >> 1);
                uint32_t aH[4];
                LDSM4(aH, Hsm + (uint32_t)m * 128 + ((uint32_t)(kc ^ (m & 7)) << 4));
                uint32_t bH[4][4];
#pragma unroll
                for (int ntp = 0; ntp < 4; ntp++) {
                    int k = ks * 16 + (mtx & 1) * 8 + rin;
                    int nch = (nc >> 3) + ntp * 2 + (mtx >> 1);
                    uint32_t boff = (uint32_t)k * 256 + ((uint32_t)(nch ^ (k & 7)) << 4);
                    LDSM4T(bH[ntp], W3hi + boff);
                }
#pragma unroll
                for (int nt = 0; nt < 8; nt++)
                    MMA16816(acc3[nt], aH, bH[nt >> 1][(nt & 1) * 2], bH[nt >> 1][(nt & 1) * 2 + 1]);
                uint32_t bL[4][4];
#pragma unroll
                for (int ntp = 0; ntp < 4; ntp++) {
                    int k = ks * 16 + (mtx & 1) * 8 + rin;
                    int nch = (nc >> 3) + ntp * 2 + (mtx >> 1);
                    uint32_t boff = (uint32_t)k * 256 + ((uint32_t)(nch ^ (k & 7)) << 4);
                    LDSM4T(bL[ntp], W3lo + boff);
                }
#pragma unroll
                for (int nt = 0; nt < 8; nt++)
                    MMA16816(acc3[nt], aH, bL[nt >> 1][(nt & 1) * 2], bL[nt >> 1][(nt & 1) * 2 + 1]);
            }
        }
        CP_WAIT(0);
        __syncthreads();

        {
            const int nc = ni1 * 64;
#pragma unroll
            for (int rh = 0; rh < 2; rh++) {
                int r = mr + rh * 8 + lr;
                float at = sAttr[r];
#pragma unroll
                for (int nt = 0; nt < 8; nt++) {
                    int col = nc + nt * 8 + lc * 2;
                    uint32_t ad = (uint32_t)r * 256 + ((uint32_t)((col >> 3) ^ (r & 7)) << 4) + (col & 7) * 2;
                    uint32_t us, ud;
                    LDS32(us, Msrc + ad);
                    LDS32(ud, Mdst + ad);
                    float2 ms = __half22float2(*(__half2*)&us);
                    float2 md = __half22float2(*(__half2*)&ud);
                    float rad0 = acc3[nt][rh * 2 + 0] + sB3[col];
                    float rad1 = acc3[nt][rh * 2 + 1] + sB3[col + 1];
                    float m0 = (ms.x + md.x) * at * rad0;
                    float m1 = (ms.y + md.y) * at * rad1;
                    STS32(Asm + ad, packh2(m0, m1));
                }
            }
        }
        __syncthreads();

        float d[2][8][4];
#pragma unroll
        for (int a = 0; a < 2; a++)
#pragma unroll
            for (int b = 0; b < 8; b++)
#pragma unroll
                for (int c = 0; c < 4; c++) d[a][b][c] = 0.0f;

#pragma unroll
        for (int ks = 0; ks < 8; ks++) {
            uint32_t ah[2][4];
#pragma unroll
            for (int mt = 0; mt < 2; mt++) {
                int m = mrow0 + mt * 16 + (mtx & 1) * 8 + rin;
                int kchunk = ks * 2 + (mtx >> 1);
                LDSM4(ah[mt], Asm + (uint32_t)m * 256 + ((uint32_t)(kchunk ^ (m & 7)) << 4));
            }
            uint32_t b[4][4];
#pragma unroll
            for (int ntp = 0; ntp < 4; ntp++) {
                int k = ks * 16 + (mtx & 1) * 8 + rin;
                int nchunk = (ncol0 >> 3) + ntp * 2 + (mtx >> 1);
                LDSM4T(b[ntp], Bsm + (uint32_t)k * 512 + ((uint32_t)(nchunk ^ (k & 7)) << 4));
            }
#pragma unroll
            for (int mt = 0; mt < 2; mt++)
#pragma unroll
                for (int nt = 0; nt < 8; nt++)
                    MMA16816(d[mt][nt], ah[mt], b[nt >> 1][(nt & 1) * 2], b[nt >> 1][(nt & 1) * 2 + 1]);
        }

#pragma unroll
        for (int hh = 0; hh < 2; hh++) {
            const int h = ni * 2 + hh;
#pragma unroll
            for (int mt = 0; mt < 2; mt++) {
                const int r0i = mrow0 + mt * 16 + lr;
                const int e0i = e0 + r0i;
                float p0 = 0.0f, p1 = 0.0f;
#pragma unroll
                for (int q = 0; q < 2; q++) {
                    const int nt = hh * 4 + q;
                    const int colb = ncol0 + nt * 8 + lc * 2;
                    const int jb = q * 8 + lc * 2;
                    const float bb0 = sBsep[colb], bb1 = sBsep[colb + 1];
                    const float w0 = sAD[h * 16 + jb], w1 = sAD[h * 16 + jb + 1];
                    float x, sg;
                    x = d[mt][nt][0] + bb0; sg = 1.0f / (1.0f + __expf(-x)); p0 += x * (0.2f + 0.8f * sg) * w0;
                    x = d[mt][nt][1] + bb1; sg = 1.0f / (1.0f + __expf(-x)); p0 += x * (0.2f + 0.8f * sg) * w1;
                    x = d[mt][nt][2] + bb0; sg = 1.0f / (1.0f + __expf(-x)); p1 += x * (0.2f + 0.8f * sg) * w0;
                    x = d[mt][nt][3] + bb1; sg = 1.0f / (1.0f + __expf(-x)); p1 += x * (0.2f + 0.8f * sg) * w1;
                }
                p0 += __shfl_xor_sync(0xffffffffu, p0, 1);
                p0 += __shfl_xor_sync(0xffffffffu, p0, 2);
                p1 += __shfl_xor_sync(0xffffffffu, p1, 1);
                p1 += __shfl_xor_sync(0xffffffffu, p1, 2);
                const float ew0 = __expf(p0), ew1 = __expf(p1);
                const int d0 = sDst[r0i], d1 = sDst[r0i + 8];
                if (lc == 0) {
                    if (e0i < E)     atomicAdd(&g_nsum[(size_t)d0 * 8 + h], ew0);
                    if (e0i + 8 < E) atomicAdd(&g_nsum[(size_t)d1 * 8 + h], ew1);
                }
#pragma unroll
                for (int q = 0; q < 2; q++) {
                    const int nt = hh * 4 + 2 + q;
                    const int colb = ncol0 + nt * 8 + lc * 2;
                    const int vidx = q * 8 + lc * 2;
                    const float bb0 = sBsep[colb], bb1 = sBsep[colb + 1];
                    if (e0i < E)
                        RED2(g_nacc + (size_t)d0 * 128 + h * 16 + vidx,
                             (d[mt][nt][0] + bb0) * ew0, (d[mt][nt][1] + bb1) * ew0);
                    if (e0i + 8 < E)
                        RED2(g_nacc + (size_t)d1 * 128 + h * 16 + vidx,
                             (d[mt][nt][2] + bb0) * ew1, (d[mt][nt][3] + bb1) * ew1);
                }
            }
        }
    }
}

// ---------------- K5: out GEMM on HMMA ---------------------------------------
// D[128,128] = split(nacc*inv) @ w_proj; 2-pass A hi/lo; bias epilogue.
__global__ __launch_bounds__(512, 1) void out_mma_kernel(
    const float* __restrict__ bias, float* __restrict__ out, int n)
{
    extern __shared__ char dynsm[];
    __shared__ float sBias[128];
    const int tid = threadIdx.x;
    const int wid = tid >> 5, lane = tid & 31;
    const int mtx = lane >> 3, rin = lane & 7;
    const int lr = lane >> 2, lc = lane & 3;
    const int r0 = blockIdx.x * 128;

    const uint32_t sb = smem_u32(dynsm);
    const uint32_t Ahi = sb, Alo = sb + 32768, Bsm = sb + 65536;

    // stage B (2048 x 16B) async
#pragma unroll
    for (int it = 0; it < 4; it++) {
        int i = tid + 512 * it;
        CP16(Bsm + i * 16, g_PImg + i * 16);
    }
    CP_COMMIT();
    if (tid < 128) sBias[tid] = bias[tid];

    // stage A hi/lo with softmax normalization
#pragma unroll
    for (int it = 0; it < 8; it++) {
        int i = tid + 512 * it;
        int m = i >> 5, k4 = (i & 31) << 2;
        int gr = r0 + m;
        float4 v = make_float4(0.f, 0.f, 0.f, 0.f);
        if (gr < n) {
            v = *(const float4*)(g_nacc + (size_t)gr * 128 + k4);
            float inv = 1.0f / (g_nsum[(size_t)gr * 8 + (k4 >> 4)] + 1e-16f);
            v.x *= inv; v.y *= inv; v.z *= inv; v.w *= inv;
        }
        uint32_t hA, hB, lA, lB; split4(v, hA, hB, lA, lB);
        uint32_t addr = (uint32_t)m * 256 + ((uint32_t)((k4 >> 3) ^ (m & 7)) << 4) + (k4 & 7) * 2;
        STS64(Ahi + addr, hA, hB);
        STS64(Alo + addr, lA, lB);
    }
    CP_WAIT(0);
    __syncthreads();

    const int mi = wid & 3, ni = wid >> 2;
    const int mrow0 = mi * 32, ncol0 = ni * 32;

    float d[2][4][4];
#pragma unroll
    for (int a = 0; a < 2; a++)
#pragma unroll
        for (int b = 0; b < 4; b++)
#pragma unroll
            for (int c = 0; c < 4; c++) d[a][b][c] = 0.0f;

#pragma unroll
    for (int ks = 0; ks < 8; ks++) {
        uint32_t ah[2][4], al[2][4];
#pragma unroll
        for (int mt = 0; mt < 2; mt++) {
            int m = mrow0 + mt * 16 + (mtx & 1) * 8 + rin;
            int kchunk = ks * 2 + (mtx >> 1);
            uint32_t ao = (uint32_t)m * 256 + ((uint32_t)(kchunk ^ (m & 7)) << 4);
            LDSM4(ah[mt], Ahi + ao);
            LDSM4(al[mt], Alo + ao);
        }
        uint32_t b[2][4];
#pragma unroll
        for (int ntp = 0; ntp < 2; ntp++) {
            int k = ks * 16 + (mtx & 1) * 8 + rin;
            int nchunk = (ncol0 >> 3) + ntp * 2 + (mtx >> 1);
            LDSM4T(b[ntp], Bsm + (uint32_t)k * 256 + ((uint32_t)(nchunk ^ (k & 7)) << 4));
        }
#pragma unroll
        for (int mt = 0; mt < 2; mt++)
#pragma unroll
            for (int nt = 0; nt < 4; nt++) {
                MMA16816(d[mt][nt], ah[mt], b[nt >> 1][(nt & 1) * 2], b[nt >> 1][(nt & 1) * 2 + 1]);
                MMA16816(d[mt][nt], al[mt], b[nt >> 1][(nt & 1) * 2], b[nt >> 1][(nt & 1) * 2 + 1]);
            }
    }

#pragma unroll
    for (int mt = 0; mt < 2; mt++) {
        int gr0 = r0 + mrow0 + mt * 16 + lr;
        int gr1 = gr0 + 8;
#pragma unroll
        for (int nt = 0; nt < 4; nt++) {
            int c = ncol0 + nt * 8 + lc * 2;
            float bb0 = sBias[c], bb1 = sBias[c + 1];
            if (gr0 < n)
                *(float2*)(out + (size_t)gr0 * 128 + c) =
                    make_float2(d[mt][nt][0] + bb0, d[mt][nt][1] + bb1);
            if (gr1 < n)
                *(float2*)(out + (size_t)gr1 * 128 + c) =
                    make_float2(d[mt][nt][2] + bb0, d[mt][nt][3] + bb1);
        }
    }
}

// ---------------- launch ----------------
extern "C" void kernel_launch(void* const* d_in, const int* in_sizes, int n_in,
                              void* d_out, int out_size)
{
    const float* node_input = (const float*)d_in[0];
    const float* edge_attr  = (const float*)d_in[2];
    const float* edge_scal  = (const float*)d_in[3];
    const int*   edge_src   = (const int*)d_in[4];
    const int*   edge_dst   = (const int*)d_in[5];
    const float* w_src      = (const float*)d_in[7];
    const float* b_src      = (const float*)d_in[8];
    const float* w_dst      = (const float*)d_in[9];
    const float* fc_w1      = (const float*)d_in[10];
    const float* fc_b1      = (const float*)d_in[11];
    const float* fc_w2      = (const float*)d_in[12];
    const float* fc_b2      = (const float*)d_in[13];
    const float* fc_w3      = (const float*)d_in[14];
    const float* fc_b3      = (const float*)d_in[15];
    const float* w_sep      = (const float*)d_in[16];
    const float* b_sep      = (const float*)d_in[17];
    const float* alpha_dot  = (const float*)d_in[18];
    const float* w_proj     = (const float*)d_in[19];
    const float* b_proj     = (const float*)d_in[20];
    float* out = (float*)d_out;

    int N = in_sizes[0] / 128;
    int E = in_sizes[4];

    cudaFuncSetAttribute(fused_edge_kernel, cudaFuncAttributeMaxDynamicSharedMemorySize, 221184);
    cudaFuncSetAttribute(node_mma_kernel,   cudaFuncAttributeMaxDynamicSharedMemorySize, 131072);
    cudaFuncSetAttribute(out_mma_kernel,    cudaFuncAttributeMaxDynamicSharedMemorySize, 98304);

    static int sms = 0;
    if (sms == 0) {
        cudaDeviceGetAttribute(&sms, cudaDevAttrMultiProcessorCount, 0);
        if (sms <= 0) sms = 148;
    }

    init_kernel<<<(N * 128 + 255) / 256, 256>>>(N);
    prep_kernel<<<94, 256>>>(fc_w1, fc_w2, fc_w3, w_sep, w_src, w_dst, w_proj);

    int nt = (N + 127) / 128;
    node_mma_kernel<<<nt, 512, 131072>>>(node_input, b_src, N);

    int numTiles = (E + 127) / 128;
    int nblk = numTiles < sms ? numTiles : sms;
    fused_edge_kernel<<<nblk, 512, 221184>>>(edge_scal, edge_attr, edge_src, edge_dst,
                                             fc_b1, fc_b2, fc_b3,
                                             b_sep, alpha_dot, E, numTiles);

    out_mma_kernel<<<nt, 512, 98304>>>(b_proj, out, N);
}

// round 14
// speedup vs baseline: 1.5387x; 1.0392x over previous
#include <cuda_runtime.h>
#include <cuda_fp16.h>
#include <cstdint>
#include <math.h>

// ---------------- fixed problem geometry ----------------
#define MAXN 50000
#define MAXE 800000
// C=128, A_ALL=256, RAD_IN=32, FC1=FC2=64, H=8, AH=VH=16

// ---------------- scratch ----------------
__device__ __align__(16) __half g_msgh_src[(size_t)MAXN * 128];   // LINEAR rows
__device__ __align__(16) __half g_msgh_dst[(size_t)MAXN * 128];   // LINEAR rows
__device__ __align__(16) float g_nsum[(size_t)MAXN * 8];
__device__ __align__(16) float g_nacc[(size_t)MAXN * 128];
// prepacked fp16 weight images (exact SMEM layouts, swizzled)
__device__ __align__(16) unsigned char g_Bimg[65536];    // w_sep [k][n] 256n
__device__ __align__(16) unsigned char g_W1img[8192];    // hi @0, lo @4096
__device__ __align__(16) unsigned char g_W2img[16384];   // hi @0, lo @8192
__device__ __align__(16) unsigned char g_W3img[32768];   // hi @0, lo @16384
__device__ __align__(16) unsigned char g_BnodeImg[65536];// [w_src|w_dst] [k][256n]
__device__ __align__(16) unsigned char g_PImg[32768];    // w_proj [k][128n]

// ---------------- helpers ----------------
__device__ __forceinline__ uint32_t smem_u32(const void* p) {
    uint32_t a;
    asm("{ .reg .u64 t; cvta.to.shared.u64 t, %1; cvt.u32.u64 %0, t; }"
        : "=r"(a) : "l"(p));
    return a;
}

#define LDSM4(r, addr) \
    asm volatile("ldmatrix.sync.aligned.m8n8.x4.shared.b16 {%0,%1,%2,%3}, [%4];" \
        : "=r"((r)[0]), "=r"((r)[1]), "=r"((r)[2]), "=r"((r)[3]) : "r"(addr))

#define LDSM4T(r, addr) \
    asm volatile("ldmatrix.sync.aligned.m8n8.x4.trans.shared.b16 {%0,%1,%2,%3}, [%4];" \
        : "=r"((r)[0]), "=r"((r)[1]), "=r"((r)[2]), "=r"((r)[3]) : "r"(addr))

#define MMA16816(d, a, b0v, b1v) \
    asm volatile("mma.sync.aligned.m16n8k16.row.col.f32.f16.f16.f32 " \
        "{%0,%1,%2,%3}, {%4,%5,%6,%7}, {%8,%9}, {%0,%1,%2,%3};" \
        : "+f"((d)[0]), "+f"((d)[1]), "+f"((d)[2]), "+f"((d)[3]) \
        : "r"((a)[0]), "r"((a)[1]), "r"((a)[2]), "r"((a)[3]), "r"(b0v), "r"(b1v))

#define STS32(addr, v) \
    asm volatile("st.shared.b32 [%0], %1;" :: "r"(addr), "r"(v))
#define STS64(addr, v0, v1) \
    asm volatile("st.shared.v2.b32 [%0], {%1,%2};" :: "r"(addr), "r"(v0), "r"(v1))
#define LDS32(v, addr) \
    asm volatile("ld.shared.b32 %0, [%1];" : "=r"(v) : "r"(addr))

// async 16B global->shared copy (sm_80+)
#define CP16(dst, src) \
    asm volatile("{ .reg .u64 g; cvta.to.global.u64 g, %1; " \
                 "cp.async.cg.shared.global [%0], [g], 16; }" \
                 :: "r"(dst), "l"(src) : "memory")
#define CP_COMMIT() asm volatile("cp.async.commit_group;" ::: "memory")
#define CP_WAIT(n)  asm volatile("cp.async.wait_group %0;" :: "n"(n) : "memory")

// vector fire-and-forget global reduction (sm_90+)
#define RED2(ptr, x, y) \
    asm volatile("red.global.add.v2.f32 [%0], {%1,%2};" :: "l"(ptr), "f"(x), "f"(y) : "memory")

// named barrier
#define NBAR(id, cnt) \
    asm volatile("bar.sync %0, %1;" :: "r"(id), "r"(cnt) : "memory")

__device__ __forceinline__ uint32_t packh2(float x, float y) {
    __half2 t = __floats2half2_rn(x, y);
    return *(uint32_t*)&t;
}
__device__ __forceinline__ void split2(float x, float y, uint32_t& hi, uint32_t& lo) {
    __half h0 = __float2half_rn(x), h1 = __float2half_rn(y);
    __half2 hh = __halves2half2(h0, h1);
    hi = *(uint32_t*)&hh;
    lo = packh2(x - __half2float(h0), y - __half2float(h1));
}
__device__ __forceinline__ void split4(float4 v, uint32_t& hA, uint32_t& hB,
                                       uint32_t& lA, uint32_t& lB) {
    split2(v.x, v.y, hA, lA);
    split2(v.z, v.w, hB, lB);
}
__device__ __forceinline__ float silu(float x) {
    return x / (1.0f + __expf(-x));
}

// ---------------- K0: init segment buffers ----------------
__global__ void init_kernel(int n) {
    int i = blockIdx.x * blockDim.x + threadIdx.x;
    if (i < n * 128) g_nacc[i] = 0.0f;
    if (i < n * 8) g_nsum[i] = 0.0f;
}

// ---------------- K0b: prepack weight images (fp16, swizzled SMEM layout) --
__global__ void prep_kernel(const float* __restrict__ w1, const float* __restrict__ w2,
                            const float* __restrict__ w3, const float* __restrict__ w_sep,
                            const float* __restrict__ w_src, const float* __restrict__ w_dst,
                            const float* __restrict__ w_proj)
{
    int idx = blockIdx.x * blockDim.x + threadIdx.x;  // float4 units
    if (idx < 8192) {                       // w_sep: 128 x 256, rows 512B
        int k = idx >> 6, n4 = (idx & 63) << 2;
        float4 v = *(const float4*)(w_sep + (size_t)k * 256 + n4);
        uint32_t hA = packh2(v.x, v.y), hB = packh2(v.z, v.w);
        uint32_t addr = (uint32_t)k * 512 + ((uint32_t)((n4 >> 3) ^ (k & 7)) << 4) + (n4 & 7) * 2;
        *(uint2*)(g_Bimg + addr) = make_uint2(hA, hB);
    } else if (idx < 8704) {                // w1: 32 x 64, rows 128B
        int i = idx - 8192;
        int k = i >> 4, n4 = (i & 15) << 2;
        float4 v = *(const float4*)(w1 + (size_t)k * 64 + n4);
        uint32_t hA, hB, lA, lB; split4(v, hA, hB, lA, lB);
        uint32_t addr = (uint32_t)k * 128 + ((uint32_t)((n4 >> 3) ^ (k & 7)) << 4) + (n4 & 7) * 2;
        *(uint2*)(g_W1img + addr) = make_uint2(hA, hB);
        *(uint2*)(g_W1img + 4096 + addr) = make_uint2(lA, lB);
    } else if (idx < 9728) {                // w2: 64 x 64, rows 128B
        int i = idx - 8704;
        int k = i >> 4, n4 = (i & 15) << 2;
        float4 v = *(const float4*)(w2 + (size_t)k * 64 + n4);
        uint32_t hA, hB, lA, lB; split4(v, hA, hB, lA, lB);
        uint32_t addr = (uint32_t)k * 128 + ((uint32_t)((n4 >> 3) ^ (k & 7)) << 4) + (n4 & 7) * 2;
        *(uint2*)(g_W2img + addr) = make_uint2(hA, hB);
        *(uint2*)(g_W2img + 8192 + addr) = make_uint2(lA, lB);
    } else if (idx < 11776) {               // w3: 64 x 128, rows 256B
        int i = idx - 9728;
        int k = i >> 5, n4 = (i & 31) << 2;
        float4 v = *(const float4*)(w3 + (size_t)k * 128 + n4);
        uint32_t hA, hB, lA, lB; split4(v, hA, hB, lA, lB);
        uint32_t addr = (uint32_t)k * 256 + ((uint32_t)((n4 >> 3) ^ (k & 7)) << 4) + (n4 & 7) * 2;
        *(uint2*)(g_W3img + addr) = make_uint2(hA, hB);
        *(uint2*)(g_W3img + 16384 + addr) = make_uint2(lA, lB);
    } else if (idx < 19968) {               // Bnode = [w_src|w_dst]: 128 x 256, rows 512B
        int i = idx - 11776;
        int k = i >> 6, n4 = (i & 63) << 2;
        float4 v = (n4 < 128)
            ? *(const float4*)(w_src + (size_t)k * 128 + n4)
            : *(const float4*)(w_dst + (size_t)k * 128 + (n4 - 128));
        uint32_t hA = packh2(v.x, v.y), hB = packh2(v.z, v.w);
        uint32_t addr = (uint32_t)k * 512 + ((uint32_t)((n4 >> 3) ^ (k & 7)) << 4) + (n4 & 7) * 2;
        *(uint2*)(g_BnodeImg + addr) = make_uint2(hA, hB);
    } else if (idx < 24064) {               // w_proj: 128 x 128, rows 256B
        int i = idx - 19968;
        int k = i >> 5, n4 = (i & 31) << 2;
        float4 v = *(const float4*)(w_proj + (size_t)k * 128 + n4);
        uint32_t hA = packh2(v.x, v.y), hB = packh2(v.z, v.w);
        uint32_t addr = (uint32_t)k * 256 + ((uint32_t)((n4 >> 3) ^ (k & 7)) << 4) + (n4 & 7) * 2;
        *(uint2*)(g_PImg + addr) = make_uint2(hA, hB);
    }
}

// ---------------- K1: node GEMM on HMMA -> fp16 msg arrays (LINEAR rows) ----
__global__ __launch_bounds__(512, 1) void node_mma_kernel(
    const float* __restrict__ X, const float* __restrict__ bias_src, int n)
{
    extern __shared__ char dynsm[];
    __shared__ float sBias[128];
    const int tid = threadIdx.x;
    const int wid = tid >> 5, lane = tid & 31;
    const int mtx = lane >> 3, rin = lane & 7;
    const int lr = lane >> 2, lc = lane & 3;
    const int r0 = blockIdx.x * 128;

    const uint32_t sb = smem_u32(dynsm);
    const uint32_t Ahi = sb, Alo = sb + 32768, Bsm = sb + 65536;

#pragma unroll
    for (int it = 0; it < 8; it++) {
        int i = tid + 512 * it;
        CP16(Bsm + i * 16, g_BnodeImg + i * 16);
    }
    CP_COMMIT();
    if (tid < 128) sBias[tid] = bias_src[tid];

#pragma unroll
    for (int it = 0; it < 8; it++) {
        int i = tid + 512 * it;
        int m = i >> 5, k4 = (i & 31) << 2;
        int gr = r0 + m;
        float4 v = make_float4(0.f, 0.f, 0.f, 0.f);
        if (gr < n) v = *(const float4*)(X + (size_t)gr * 128 + k4);
        uint32_t hA, hB, lA, lB; split4(v, hA, hB, lA, lB);
        uint32_t addr = (uint32_t)m * 256 + ((uint32_t)((k4 >> 3) ^ (m & 7)) << 4) + (k4 & 7) * 2;
        STS64(Ahi + addr, hA, hB);
        STS64(Alo + addr, lA, lB);
    }
    CP_WAIT(0);
    __syncthreads();

    const int mi = wid & 3, ni = wid >> 2;
    const int mrow0 = mi * 32, ncol0 = ni * 64;

    float d[2][8][4];
#pragma unroll
    for (int a = 0; a < 2; a++)
#pragma unroll
        for (int b = 0; b < 8; b++)
#pragma unroll
            for (int c = 0; c < 4; c++) d[a][b][c] = 0.0f;

#pragma unroll
    for (int ks = 0; ks < 8; ks++) {
        uint32_t ah[2][4], al[2][4];
#pragma unroll
        for (int mt = 0; mt < 2; mt++) {
            int m = mrow0 + mt * 16 + (mtx & 1) * 8 + rin;
            int kchunk = ks * 2 + (mtx >> 1);
            uint32_t ao = (uint32_t)m * 256 + ((uint32_t)(kchunk ^ (m & 7)) << 4);
            LDSM4(ah[mt], Ahi + ao);
            LDSM4(al[mt], Alo + ao);
        }
        uint32_t b[4][4];
#pragma unroll
        for (int ntp = 0; ntp < 4; ntp++) {
            int k = ks * 16 + (mtx & 1) * 8 + rin;
            int nchunk = (ncol0 >> 3) + ntp * 2 + (mtx >> 1);
            LDSM4T(b[ntp], Bsm + (uint32_t)k * 512 + ((uint32_t)(nchunk ^ (k & 7)) << 4));
        }
#pragma unroll
        for (int mt = 0; mt < 2; mt++)
#pragma unroll
            for (int nt = 0; nt < 8; nt++) {
                MMA16816(d[mt][nt], ah[mt], b[nt >> 1][(nt & 1) * 2], b[nt >> 1][(nt & 1) * 2 + 1]);
                MMA16816(d[mt][nt], al[mt], b[nt >> 1][(nt & 1) * 2], b[nt >> 1][(nt & 1) * 2 + 1]);
            }
    }

#pragma unroll
    for (int mt = 0; mt < 2; mt++) {
        int gr0 = r0 + mrow0 + mt * 16 + lr;
        int gr1 = gr0 + 8;
#pragma unroll
        for (int nt = 0; nt < 8; nt++) {
            int cg = ncol0 + nt * 8 + lc * 2;
            float bb0 = 0.0f, bb1 = 0.0f;
            unsigned char* buf;
            int c;
            if (cg < 128) { buf = (unsigned char*)g_msgh_src; c = cg; bb0 = sBias[c]; bb1 = sBias[c + 1]; }
            else          { buf = (unsigned char*)g_msgh_dst; c = cg - 128; }
            if (gr0 < n)
                *(uint32_t*)(buf + (size_t)gr0 * 256 + c * 2) =
                    packh2(d[mt][nt][0] + bb0, d[mt][nt][1] + bb1);
            if (gr1 < n)
                *(uint32_t*)(buf + (size_t)gr1 * 256 + c * 2) =
                    packh2(d[mt][nt][2] + bb0, d[mt][nt][3] + bb1);
        }
    }
}

// ============================================================================
// K23: PERSISTENT fused kernel, TWO warp groups of 8, each on 64-edge tiles.
// Groups share the weight SMEM; private X/H/Msrc/Mdst; group-scoped barriers.
//
// Dynamic SMEM (221184 B):
//  [0,8K) W1 | [8K,24K) W2 | [24K,56K) W3 hi/lo | [56K,120K) B
//  group g at 120K + g*48K: X(8K) H(8K) Msrc(16K,=A) Mdst(16K)
// ============================================================================
__global__ __launch_bounds__(512, 1) void fused_edge_kernel(
    const float* __restrict__ edge_scalars, const float* __restrict__ edge_attr,
    const int* __restrict__ edge_src, const int* __restrict__ edge_dst,
    const float* __restrict__ b1, const float* __restrict__ b2,
    const float* __restrict__ b3, const float* __restrict__ b_sep,
    const float* __restrict__ alpha_dot, int E, int numTiles)
{
    extern __shared__ char dynsm[];
    __shared__ float sB1[64], sB2[64], sB3[128];
    __shared__ float sBsep[256], sAD[128];
    __shared__ int   sSrc[2][64], sDst[2][64];
    __shared__ float sAttr[2][64];

    const int tid = threadIdx.x;
    const int lane = tid & 31;
    const int g = tid >> 8;            // warp group 0/1
    const int tg = tid & 255;          // tid within group
    const int wg = (tid >> 5) & 7;     // warp within group
    const int mtx = lane >> 3, rin = lane & 7;
    const int lr = lane >> 2, lc = lane & 3;

    const uint32_t sb = smem_u32(dynsm);
    const uint32_t W1hi = sb;
    const uint32_t W2hi = sb + 8192;
    const uint32_t W3hi = sb + 24576, W3lo = sb + 40960;
    const uint32_t Bsm  = sb + 57344;
    const uint32_t gbase = sb + 122880 + (uint32_t)g * 49152;
    const uint32_t Xhi  = gbase;
    const uint32_t Hsm  = gbase + 8192;
    const uint32_t Msrc = gbase + 16384;
    const uint32_t Mdst = gbase + 32768;
    const uint32_t Asm  = Msrc;

    // ---------------- one-time weight staging (whole CTA) ----------------
    CP16(W1hi + tid * 16, g_W1img + tid * 16);
#pragma unroll
    for (int it = 0; it < 2; it++) {
        int i = tid + 512 * it;
        CP16(W2hi + i * 16, g_W2img + i * 16);
    }
#pragma unroll
    for (int it = 0; it < 4; it++) {
        int i = tid + 512 * it;
        CP16(W3hi + i * 16, g_W3img + i * 16);
    }
#pragma unroll
    for (int it = 0; it < 8; it++) {
        int i = tid + 512 * it;
        CP16(Bsm + i * 16, g_Bimg + i * 16);
    }
    CP_COMMIT();
    if (tid < 64)  { sB1[tid] = b1[tid]; sB2[tid] = b2[tid]; }
    if (tid < 128) { sB3[tid] = b3[tid]; sAD[tid] = alpha_dot[tid]; }
    if (tid < 256) sBsep[tid] = b_sep[tid];
    CP_WAIT(0);
    __syncthreads();

    // MLP warp tiling within group: 4 M-tiles x 2 N-tiles (M=64)
    const int mi1 = wg & 3, ni1 = wg >> 2;
    const int mr = mi1 * 16;
    // phase2 warp tiling within group: 2 M-tiles x 4 N-tiles (M=64, N=256)
    const int mi = wg & 1, ni = wg >> 1;
    const int mrow0 = mi * 32, ncol0 = ni * 64;

    const int GB = 1 + g;              // group barrier id
    const int PB = 4 + g * 4 + mi1;    // layer2 pair barrier id

    // =================== persistent tile loop (64-edge tiles) ===============
    for (int tile = blockIdx.x * 2 + g; tile < numTiles; tile += gridDim.x * 2) {
        const int e0 = tile * 64;
        NBAR(GB, 256);   // previous iteration fully done with group buffers

        // ---- stage edge indices + X ----
        if (tg < 64) {
            int e = min(e0 + tg, E - 1);
            sSrc[g][tg] = edge_src[e];
            sDst[g][tg] = edge_dst[e];
            sAttr[g][tg] = (e0 + tg < E) ? edge_attr[e] : 0.0f;
        }
#pragma unroll
        for (int it = 0; it < 2; it++) {
            int i = tg + 256 * it;            // 0..511
            int m = i >> 3, k4 = (i & 7) << 2;
            int e = min(e0 + m, E - 1);
            float4 v = *(const float4*)(edge_scalars + (size_t)e * 32 + k4);
            uint32_t hA = packh2(v.x, v.y), hB = packh2(v.z, v.w);
            uint32_t addr = (uint32_t)m * 128 + ((uint32_t)(((k4 >> 3) ^ (m & 7))) << 4) + (k4 & 7) * 2;
            STS64(Xhi + addr, hA, hB);
        }
        NBAR(GB, 256);   // indices + X visible to group

        // ---- prefetch msg rows via cp.async (hidden under the MLP) ----
#pragma unroll
        for (int it = 0; it < 8; it++) {
            int i = tg + 256 * it;            // 0..2047
            int r = (i >> 4) & 63, seg = i & 15, buf = i >> 10;
            int node = buf ? sDst[g][r] : sSrc[g][r];
            const unsigned char* srcp =
                (const unsigned char*)(buf ? g_msgh_dst : g_msgh_src) +
                (size_t)node * 256 + seg * 16;
            uint32_t dst = (buf ? Mdst : Msrc) + (uint32_t)r * 256 +
                           ((uint32_t)(seg ^ (r & 7)) << 4);
            CP16(dst, srcp);
        }
        CP_COMMIT();

        // ---- layer1: H = silu(X @ W1 + b1) [64x64, K=32] ----
        {
            const int nc = ni1 * 32;
            float acc[4][4];
#pragma unroll
            for (int i = 0; i < 4; i++)
#pragma unroll
                for (int j = 0; j < 4; j++) acc[i][j] = 0.0f;
#pragma unroll
            for (int ks = 0; ks < 2; ks++) {
                int m = mr + (mtx & 1) * 8 + rin;
                int kc = ks * 2 + (mtx >> 1);
                uint32_t aH[4];
                LDSM4(aH, Xhi + (uint32_t)m * 128 + ((uint32_t)(kc ^ (m & 7)) << 4));
                uint32_t bH[2][4], bL[2][4];
#pragma unroll
                for (int ntp = 0; ntp < 2; ntp++) {
                    int k = ks * 16 + (mtx & 1) * 8 + rin;
                    int nch = (nc >> 3) + ntp * 2 + (mtx >> 1);
                    uint32_t boff = (uint32_t)k * 128 + ((uint32_t)(nch ^ (k & 7)) << 4);
                    LDSM4T(bH[ntp], W1hi + boff);
                    LDSM4T(bL[ntp], W1hi + 4096 + boff);
                }
#pragma unroll
                for (int nt = 0; nt < 4; nt++) {
                    MMA16816(acc[nt], aH, bH[nt >> 1][(nt & 1) * 2], bH[nt >> 1][(nt & 1) * 2 + 1]);
                    MMA16816(acc[nt], aH, bL[nt >> 1][(nt & 1) * 2], bL[nt >> 1][(nt & 1) * 2 + 1]);
                }
            }
#pragma unroll
            for (int nt = 0; nt < 4; nt++) {
                int col = nc + nt * 8 + lc * 2;
                float s0 = silu(acc[nt][0] + sB1[col]);
                float s1 = silu(acc[nt][1] + sB1[col + 1]);
                float s2 = silu(acc[nt][2] + sB1[col]);
                float s3 = silu(acc[nt][3] + sB1[col + 1]);
                int r0 = mr + lr, r1 = r0 + 8;
                uint32_t ad0 = (uint32_t)r0 * 128 + ((uint32_t)((col >> 3) ^ (r0 & 7)) << 4) + (col & 7) * 2;
                STS32(Hsm + ad0, packh2(s0, s1));
                uint32_t ad1 = (uint32_t)r1 * 128 + ((uint32_t)((col >> 3) ^ (r1 & 7)) << 4) + (col & 7) * 2;
                STS32(Hsm + ad1, packh2(s2, s3));
            }
        }
        NBAR(GB, 256);

        // ---- layer2: H <- silu(H @ W2 + b2) [64x64, K=64] (in place) ----
        {
            const int nc = ni1 * 32;
            float acc[4][4];
#pragma unroll
            for (int i = 0; i < 4; i++)
#pragma unroll
                for (int j = 0; j < 4; j++) acc[i][j] = 0.0f;
#pragma unroll
            for (int ks = 0; ks < 4; ks++) {
                int m = mr + (mtx & 1) * 8 + rin;
                int kc = ks * 2 + (mtx >> 1);
                uint32_t aH[4];
                LDSM4(aH, Hsm + (uint32_t)m * 128 + ((uint32_t)(kc ^ (m & 7)) << 4));
                uint32_t bH[2][4], bL[2][4];
#pragma unroll
                for (int ntp = 0; ntp < 2; ntp++) {
                    int k = ks * 16 + (mtx & 1) * 8 + rin;
                    int nch = (nc >> 3) + ntp * 2 + (mtx >> 1);
                    uint32_t boff = (uint32_t)k * 128 + ((uint32_t)(nch ^ (k & 7)) << 4);
                    LDSM4T(bH[ntp], W2hi + boff);
                    LDSM4T(bL[ntp], W2hi + 8192 + boff);
                }
#pragma unroll
                for (int nt = 0; nt < 4; nt++) {
                    MMA16816(acc[nt], aH, bH[nt >> 1][(nt & 1) * 2], bH[nt >> 1][(nt & 1) * 2 + 1]);
                    MMA16816(acc[nt], aH, bL[nt >> 1][(nt & 1) * 2], bL[nt >> 1][(nt & 1) * 2 + 1]);
                }
            }
            // pair barrier: both N-warps of this row block finished reading H
            NBAR(PB, 64);
#pragma unroll
            for (int nt = 0; nt < 4; nt++) {
                int col = nc + nt * 8 + lc * 2;
                float s0 = silu(acc[nt][0] + sB2[col]);
                float s1 = silu(acc[nt][1] + sB2[col + 1]);
                float s2 = silu(acc[nt][2] + sB2[col]);
                float s3 = silu(acc[nt][3] + sB2[col + 1]);
                int r0 = mr + lr, r1 = r0 + 8;
                uint32_t ad0 = (uint32_t)r0 * 128 + ((uint32_t)((col >> 3) ^ (r0 & 7)) << 4) + (col & 7) * 2;
                STS32(Hsm + ad0, packh2(s0, s1));
                uint32_t ad1 = (uint32_t)r1 * 128 + ((uint32_t)((col >> 3) ^ (r1 & 7)) << 4) + (col & 7) * 2;
                STS32(Hsm + ad1, packh2(s2, s3));
            }
        }
        NBAR(GB, 256);

        // ---- layer3: rad = H @ W3 + b3 [64x128, K=64] (regs) ----
        float acc3[8][4];
#pragma unroll
        for (int i = 0; i < 8; i++)
#pragma unroll
            for (int j = 0; j < 4; j++) acc3[i][j] = 0.0f;
        {
            const int nc = ni1 * 64;
#pragma unroll
            for (int ks = 0; ks < 4; ks++) {
                int m = mr + (mtx & 1) * 8 + rin;
                int kc = ks * 2 + (mtx >> 1);
                uint32_t aH[4];
                LDSM4(aH, Hsm + (uint32_t)m * 128 + ((uint32_t)(kc ^ (m & 7)) << 4));
                uint32_t bH[4][4];
#pragma unroll
                for (int ntp = 0; ntp < 4; ntp++) {
                    int k = ks * 16 + (mtx & 1) * 8 + rin;
                    int nch = (nc >> 3) + ntp * 2 + (mtx >> 1);
                    uint32_t boff = (uint32_t)k * 256 + ((uint32_t)(nch ^ (k & 7)) << 4);
                    LDSM4T(bH[ntp], W3hi + boff);
                }
#pragma unroll
                for (int nt = 0; nt < 8; nt++)
                    MMA16816(acc3[nt], aH, bH[nt >> 1][(nt & 1) * 2], bH[nt >> 1][(nt & 1) * 2 + 1]);
                uint32_t bL[4][4];
#pragma unroll
                for (int ntp = 0; ntp < 4; ntp++) {
                    int k = ks * 16 + (mtx & 1) * 8 + rin;
                    int nch = (nc >> 3) + ntp * 2 + (mtx >> 1);
                    uint32_t boff = (uint32_t)k * 256 + ((uint32_t)(nch ^ (k & 7)) << 4);
                    LDSM4T(bL[ntp], W3lo + boff);
                }
#pragma unroll
                for (int nt = 0; nt < 8; nt++)
                    MMA16816(acc3[nt], aH, bL[nt >> 1][(nt & 1) * 2], bL[nt >> 1][(nt & 1) * 2 + 1]);
            }
        }
        CP_WAIT(0);       // this thread's msg copies done
        NBAR(GB, 256);    // whole group's copies done

        // ---- gather from SMEM + form A = (src+dst)*attr*rad (in place) ----
        {
            const int nc = ni1 * 64;
#pragma unroll
            for (int rh = 0; rh < 2; rh++) {
                int r = mr + rh * 8 + lr;
                float at = sAttr[g][r];
#pragma unroll
                for (int nt = 0; nt < 8; nt++) {
                    int col = nc + nt * 8 + lc * 2;
                    uint32_t ad = (uint32_t)r * 256 + ((uint32_t)((col >> 3) ^ (r & 7)) << 4) + (col & 7) * 2;
                    uint32_t us, ud;
                    LDS32(us, Msrc + ad);
                    LDS32(ud, Mdst + ad);
                    float2 ms = __half22float2(*(__half2*)&us);
                    float2 md = __half22float2(*(__half2*)&ud);
                    float rad0 = acc3[nt][rh * 2 + 0] + sB3[col];
                    float rad1 = acc3[nt][rh * 2 + 1] + sB3[col + 1];
                    float m0 = (ms.x + md.x) * at * rad0;
                    float m1 = (ms.y + md.y) * at * rad1;
                    STS32(Asm + ad, packh2(m0, m1));
                }
            }
        }
        NBAR(GB, 256);

        // ---- phase2: D[64,256] = A @ B + epilogue ----
        float d[2][8][4];
#pragma unroll
        for (int a = 0; a < 2; a++)
#pragma unroll
            for (int b = 0; b < 8; b++)
#pragma unroll
                for (int c = 0; c < 4; c++) d[a][b][c] = 0.0f;

#pragma unroll
        for (int ks = 0; ks < 8; ks++) {
            uint32_t ah[2][4];
#pragma unroll
            for (int mt = 0; mt < 2; mt++) {
                int m = mrow0 + mt * 16 + (mtx & 1) * 8 + rin;
                int kchunk = ks * 2 + (mtx >> 1);
                LDSM4(ah[mt], Asm + (uint32_t)m * 256 + ((uint32_t)(kchunk ^ (m & 7)) << 4));
            }
            uint32_t b[4][4];
#pragma unroll
            for (int ntp = 0; ntp < 4; ntp++) {
                int k = ks * 16 + (mtx & 1) * 8 + rin;
                int nchunk = (ncol0 >> 3) + ntp * 2 + (mtx >> 1);
                LDSM4T(b[ntp], Bsm + (uint32_t)k * 512 + ((uint32_t)(nchunk ^ (k & 7)) << 4));
            }
#pragma unroll
            for (int mt = 0; mt < 2; mt++)
#pragma unroll
                for (int nt = 0; nt < 8; nt++)
                    MMA16816(d[mt][nt], ah[mt], b[nt >> 1][(nt & 1) * 2], b[nt >> 1][(nt & 1) * 2 + 1]);
        }

        // ---- epilogue: w = exp(score); direct segment reduction ----
#pragma unroll
        for (int hh = 0; hh < 2; hh++) {
            const int h = ni * 2 + hh;
#pragma unroll
            for (int mt = 0; mt < 2; mt++) {
                const int r0i = mrow0 + mt * 16 + lr;
                const int e0i = e0 + r0i;
                float p0 = 0.0f, p1 = 0.0f;
#pragma unroll
                for (int q = 0; q < 2; q++) {
                    const int nt = hh * 4 + q;
                    const int colb = ncol0 + nt * 8 + lc * 2;
                    const int jb = q * 8 + lc * 2;
                    const float bb0 = sBsep[colb], bb1 = sBsep[colb + 1];
                    const float w0 = sAD[h * 16 + jb], w1 = sAD[h * 16 + jb + 1];
                    float x, sg;
                    x = d[mt][nt][0] + bb0; sg = 1.0f / (1.0f + __expf(-x)); p0 += x * (0.2f + 0.8f * sg) * w0;
                    x = d[mt][nt][1] + bb1; sg = 1.0f / (1.0f + __expf(-x)); p0 += x * (0.2f + 0.8f * sg) * w1;
                    x = d[mt][nt][2] + bb0; sg = 1.0f / (1.0f + __expf(-x)); p1 += x * (0.2f + 0.8f * sg) * w0;
                    x = d[mt][nt][3] + bb1; sg = 1.0f / (1.0f + __expf(-x)); p1 += x * (0.2f + 0.8f * sg) * w1;
                }
                p0 += __shfl_xor_sync(0xffffffffu, p0, 1);
                p0 += __shfl_xor_sync(0xffffffffu, p0, 2);
                p1 += __shfl_xor_sync(0xffffffffu, p1, 1);
                p1 += __shfl_xor_sync(0xffffffffu, p1, 2);
                const float ew0 = __expf(p0), ew1 = __expf(p1);
                const int d0 = sDst[g][r0i], d1 = sDst[g][r0i + 8];
                if (lc == 0) {
                    if (e0i < E)     atomicAdd(&g_nsum[(size_t)d0 * 8 + h], ew0);
                    if (e0i + 8 < E) atomicAdd(&g_nsum[(size_t)d1 * 8 + h], ew1);
                }
#pragma unroll
                for (int q = 0; q < 2; q++) {
                    const int nt = hh * 4 + 2 + q;
                    const int colb = ncol0 + nt * 8 + lc * 2;
                    const int vidx = q * 8 + lc * 2;
                    const float bb0 = sBsep[colb], bb1 = sBsep[colb + 1];
                    if (e0i < E)
                        RED2(g_nacc + (size_t)d0 * 128 + h * 16 + vidx,
                             (d[mt][nt][0] + bb0) * ew0, (d[mt][nt][1] + bb1) * ew0);
                    if (e0i + 8 < E)
                        RED2(g_nacc + (size_t)d1 * 128 + h * 16 + vidx,
                             (d[mt][nt][2] + bb0) * ew1, (d[mt][nt][3] + bb1) * ew1);
                }
            }
        }
    }
}

// ---------------- K5: out GEMM on HMMA ---------------------------------------
__global__ __launch_bounds__(512, 1) void out_mma_kernel(
    const float* __restrict__ bias, float* __restrict__ out, int n)
{
    extern __shared__ char dynsm[];
    __shared__ float sBias[128];
    const int tid = threadIdx.x;
    const int wid = tid >> 5, lane = tid & 31;
    const int mtx = lane >> 3, rin = lane & 7;
    const int lr = lane >> 2, lc = lane & 3;
    const int r0 = blockIdx.x * 128;

    const uint32_t sb = smem_u32(dynsm);
    const uint32_t Ahi = sb, Alo = sb + 32768, Bsm = sb + 65536;

#pragma unroll
    for (int it = 0; it < 4; it++) {
        int i = tid + 512 * it;
        CP16(Bsm + i * 16, g_PImg + i * 16);
    }
    CP_COMMIT();
    if (tid < 128) sBias[tid] = bias[tid];

#pragma unroll
    for (int it = 0; it < 8; it++) {
        int i = tid + 512 * it;
        int m = i >> 5, k4 = (i & 31) << 2;
        int gr = r0 + m;
        float4 v = make_float4(0.f, 0.f, 0.f, 0.f);
        if (gr < n) {
            v = *(const float4*)(g_nacc + (size_t)gr * 128 + k4);
            float inv = 1.0f / (g_nsum[(size_t)gr * 8 + (k4 >> 4)] + 1e-16f);
            v.x *= inv; v.y *= inv; v.z *= inv; v.w *= inv;
        }
        uint32_t hA, hB, lA, lB; split4(v, hA, hB, lA, lB);
        uint32_t addr = (uint32_t)m * 256 + ((uint32_t)((k4 >> 3) ^ (m & 7)) << 4) + (k4 & 7) * 2;
        STS64(Ahi + addr, hA, hB);
        STS64(Alo + addr, lA, lB);
    }
    CP_WAIT(0);
    __syncthreads();

    const int mi = wid & 3, ni = wid >> 2;
    const int mrow0 = mi * 32, ncol0 = ni * 32;

    float d[2][4][4];
#pragma unroll
    for (int a = 0; a < 2; a++)
#pragma unroll
        for (int b = 0; b < 4; b++)
#pragma unroll
            for (int c = 0; c < 4; c++) d[a][b][c] = 0.0f;

#pragma unroll
    for (int ks = 0; ks < 8; ks++) {
        uint32_t ah[2][4], al[2][4];
#pragma unroll
        for (int mt = 0; mt < 2; mt++) {
            int m = mrow0 + mt * 16 + (mtx & 1) * 8 + rin;
            int kchunk = ks * 2 + (mtx >> 1);
            uint32_t ao = (uint32_t)m * 256 + ((uint32_t)(kchunk ^ (m & 7)) << 4);
            LDSM4(ah[mt], Ahi + ao);
            LDSM4(al[mt], Alo + ao);
        }
        uint32_t b[2][4];
#pragma unroll
        for (int ntp = 0; ntp < 2; ntp++) {
            int k = ks * 16 + (mtx & 1) * 8 + rin;
            int nchunk = (ncol0 >> 3) + ntp * 2 + (mtx >> 1);
            LDSM4T(b[ntp], Bsm + (uint32_t)k * 256 + ((uint32_t)(nchunk ^ (k & 7)) << 4));
        }
#pragma unroll
        for (int mt = 0; mt < 2; mt++)
#pragma unroll
            for (int nt = 0; nt < 4; nt++) {
                MMA16816(d[mt][nt], ah[mt], b[nt >> 1][(nt & 1) * 2], b[nt >> 1][(nt & 1) * 2 + 1]);
                MMA16816(d[mt][nt], al[mt], b[nt >> 1][(nt & 1) * 2], b[nt >> 1][(nt & 1) * 2 + 1]);
            }
    }

#pragma unroll
    for (int mt = 0; mt < 2; mt++) {
        int gr0 = r0 + mrow0 + mt * 16 + lr;
        int gr1 = gr0 + 8;
#pragma unroll
        for (int nt = 0; nt < 4; nt++) {
            int c = ncol0 + nt * 8 + lc * 2;
            float bb0 = sBias[c], bb1 = sBias[c + 1];
            if (gr0 < n)
                *(float2*)(out + (size_t)gr0 * 128 + c) =
                    make_float2(d[mt][nt][0] + bb0, d[mt][nt][1] + bb1);
            if (gr1 < n)
                *(float2*)(out + (size_t)gr1 * 128 + c) =
                    make_float2(d[mt][nt][2] + bb0, d[mt][nt][3] + bb1);
        }
    }
}

// ---------------- launch ----------------
extern "C" void kernel_launch(void* const* d_in, const int* in_sizes, int n_in,
                              void* d_out, int out_size)
{
    const float* node_input = (const float*)d_in[0];
    const float* edge_attr  = (const float*)d_in[2];
    const float* edge_scal  = (const float*)d_in[3];
    const int*   edge_src   = (const int*)d_in[4];
    const int*   edge_dst   = (const int*)d_in[5];
    const float* w_src      = (const float*)d_in[7];
    const float* b_src      = (const float*)d_in[8];
    const float* w_dst      = (const float*)d_in[9];
    const float* fc_w1      = (const float*)d_in[10];
    const float* fc_b1      = (const float*)d_in[11];
    const float* fc_w2      = (const float*)d_in[12];
    const float* fc_b2      = (const float*)d_in[13];
    const float* fc_w3      = (const float*)d_in[14];
    const float* fc_b3      = (const float*)d_in[15];
    const float* w_sep      = (const float*)d_in[16];
    const float* b_sep      = (const float*)d_in[17];
    const float* alpha_dot  = (const float*)d_in[18];
    const float* w_proj     = (const float*)d_in[19];
    const float* b_proj     = (const float*)d_in[20];
    float* out = (float*)d_out;

    int N = in_sizes[0] / 128;
    int E = in_sizes[4];

    cudaFuncSetAttribute(fused_edge_kernel, cudaFuncAttributeMaxDynamicSharedMemorySize, 221184);
    cudaFuncSetAttribute(node_mma_kernel,   cudaFuncAttributeMaxDynamicSharedMemorySize, 131072);
    cudaFuncSetAttribute(out_mma_kernel,    cudaFuncAttributeMaxDynamicSharedMemorySize, 98304);

    static int sms = 0;
    if (sms == 0) {
        cudaDeviceGetAttribute(&sms, cudaDevAttrMultiProcessorCount, 0);
        if (sms <= 0) sms = 148;
    }

    init_kernel<<<(N * 128 + 255) / 256, 256>>>(N);
    prep_kernel<<<94, 256>>>(fc_w1, fc_w2, fc_w3, w_sep, w_src, w_dst, w_proj);

    int nt = (N + 127) / 128;
    node_mma_kernel<<<nt, 512, 131072>>>(node_input, b_src, N);

    int numTiles = (E + 63) / 64;               // 64-edge tiles
    int nblk = (numTiles + 1) / 2;
    if (nblk > sms) nblk = sms;
    fused_edge_kernel<<<nblk, 512, 221184>>>(edge_scal, edge_attr, edge_src, edge_dst,
                                             fc_b1, fc_b2, fc_b3,
                                             b_sep, alpha_dot, E, numTiles);

    out_mma_kernel<<<nt, 512, 98304>>>(b_proj, out, N);
}

// round 15
// speedup vs baseline: 1.6625x; 1.0805x over previous
#include <cuda_runtime.h>
#include <cuda_fp16.h>
#include <cstdint>
#include <math.h>

// ---------------- fixed problem geometry ----------------
#define MAXN 50000
#define MAXE 800000
// C=128, A_ALL=256, RAD_IN=32, FC1=FC2=64, H=8, AH=VH=16

// ---------------- scratch ----------------
__device__ __align__(16) __half g_msgh_src[(size_t)MAXN * 128];   // LINEAR rows
__device__ __align__(16) __half g_msgh_dst[(size_t)MAXN * 128];   // LINEAR rows
__device__ __align__(16) float g_nsum[(size_t)MAXN * 8];
__device__ __align__(16) float g_nacc[(size_t)MAXN * 128];
// prepacked fp16 weight images (exact SMEM layouts, swizzled)
__device__ __align__(16) unsigned char g_Bimg[65536];    // w_sep [k][n] 256n
__device__ __align__(16) unsigned char g_W1img[4096];    // hi only
__device__ __align__(16) unsigned char g_W2img[8192];    // hi only
__device__ __align__(16) unsigned char g_W3img[16384];   // hi only
__device__ __align__(16) unsigned char g_BnodeImg[65536];// [w_src|w_dst] [k][256n]
__device__ __align__(16) unsigned char g_PImg[32768];    // w_proj [k][128n]

// ---------------- helpers ----------------
__device__ __forceinline__ uint32_t smem_u32(const void* p) {
    uint32_t a;
    asm("{ .reg .u64 t; cvta.to.shared.u64 t, %1; cvt.u32.u64 %0, t; }"
        : "=r"(a) : "l"(p));
    return a;
}

#define LDSM4(r, addr) \
    asm volatile("ldmatrix.sync.aligned.m8n8.x4.shared.b16 {%0,%1,%2,%3}, [%4];" \
        : "=r"((r)[0]), "=r"((r)[1]), "=r"((r)[2]), "=r"((r)[3]) : "r"(addr))

#define LDSM4T(r, addr) \
    asm volatile("ldmatrix.sync.aligned.m8n8.x4.trans.shared.b16 {%0,%1,%2,%3}, [%4];" \
        : "=r"((r)[0]), "=r"((r)[1]), "=r"((r)[2]), "=r"((r)[3]) : "r"(addr))

#define MMA16816(d, a, b0v, b1v) \
    asm volatile("mma.sync.aligned.m16n8k16.row.col.f32.f16.f16.f32 " \
        "{%0,%1,%2,%3}, {%4,%5,%6,%7}, {%8,%9}, {%0,%1,%2,%3};" \
        : "+f"((d)[0]), "+f"((d)[1]), "+f"((d)[2]), "+f"((d)[3]) \
        : "r"((a)[0]), "r"((a)[1]), "r"((a)[2]), "r"((a)[3]), "r"(b0v), "r"(b1v))

#define STS32(addr, v) \
    asm volatile("st.shared.b32 [%0], %1;" :: "r"(addr), "r"(v))
#define STS64(addr, v0, v1) \
    asm volatile("st.shared.v2.b32 [%0], {%1,%2};" :: "r"(addr), "r"(v0), "r"(v1))
#define LDS32(v, addr) \
    asm volatile("ld.shared.b32 %0, [%1];" : "=r"(v) : "r"(addr))

// async 16B global->shared copy (sm_80+)
#define CP16(dst, src) \
    asm volatile("{ .reg .u64 g; cvta.to.global.u64 g, %1; " \
                 "cp.async.cg.shared.global [%0], [g], 16; }" \
                 :: "r"(dst), "l"(src) : "memory")
#define CP_COMMIT() asm volatile("cp.async.commit_group;" ::: "memory")
#define CP_WAIT(n)  asm volatile("cp.async.wait_group %0;" :: "n"(n) : "memory")

// vector fire-and-forget global reduction (sm_90+)
#define RED2(ptr, x, y) \
    asm volatile("red.global.add.v2.f32 [%0], {%1,%2};" :: "l"(ptr), "f"(x), "f"(y) : "memory")

// named barrier
#define NBAR(id, cnt) \
    asm volatile("bar.sync %0, %1;" :: "r"(id), "r"(cnt) : "memory")

__device__ __forceinline__ uint32_t packh2(float x, float y) {
    __half2 t = __floats2half2_rn(x, y);
    return *(uint32_t*)&t;
}
__device__ __forceinline__ void split2(float x, float y, uint32_t& hi, uint32_t& lo) {
    __half h0 = __float2half_rn(x), h1 = __float2half_rn(y);
    __half2 hh = __halves2half2(h0, h1);
    hi = *(uint32_t*)&hh;
    lo = packh2(x - __half2float(h0), y - __half2float(h1));
}
__device__ __forceinline__ void split4(float4 v, uint32_t& hA, uint32_t& hB,
                                       uint32_t& lA, uint32_t& lB) {
    split2(v.x, v.y, hA, lA);
    split2(v.z, v.w, hB, lB);
}
__device__ __forceinline__ float silu(float x) {
    return x / (1.0f + __expf(-x));
}

// ---------------- K0: init segment buffers ----------------
__global__ void init_kernel(int n) {
    int i = blockIdx.x * blockDim.x + threadIdx.x;
    if (i < n * 128) g_nacc[i] = 0.0f;
    if (i < n * 8) g_nsum[i] = 0.0f;
}

// ---------------- K0b: prepack weight images (fp16, swizzled SMEM layout) --
__global__ void prep_kernel(const float* __restrict__ w1, const float* __restrict__ w2,
                            const float* __restrict__ w3, const float* __restrict__ w_sep,
                            const float* __restrict__ w_src, const float* __restrict__ w_dst,
                            const float* __restrict__ w_proj)
{
    int idx = blockIdx.x * blockDim.x + threadIdx.x;  // float4 units
    if (idx < 8192) {                       // w_sep: 128 x 256, rows 512B
        int k = idx >> 6, n4 = (idx & 63) << 2;
        float4 v = *(const float4*)(w_sep + (size_t)k * 256 + n4);
        uint32_t hA = packh2(v.x, v.y), hB = packh2(v.z, v.w);
        uint32_t addr = (uint32_t)k * 512 + ((uint32_t)((n4 >> 3) ^ (k & 7)) << 4) + (n4 & 7) * 2;
        *(uint2*)(g_Bimg + addr) = make_uint2(hA, hB);
    } else if (idx < 8704) {                // w1: 32 x 64, rows 128B (hi only)
        int i = idx - 8192;
        int k = i >> 4, n4 = (i & 15) << 2;
        float4 v = *(const float4*)(w1 + (size_t)k * 64 + n4);
        uint32_t hA = packh2(v.x, v.y), hB = packh2(v.z, v.w);
        uint32_t addr = (uint32_t)k * 128 + ((uint32_t)((n4 >> 3) ^ (k & 7)) << 4) + (n4 & 7) * 2;
        *(uint2*)(g_W1img + addr) = make_uint2(hA, hB);
    } else if (idx < 9728) {                // w2: 64 x 64, rows 128B (hi only)
        int i = idx - 8704;
        int k = i >> 4, n4 = (i & 15) << 2;
        float4 v = *(const float4*)(w2 + (size_t)k * 64 + n4);
        uint32_t hA = packh2(v.x, v.y), hB = packh2(v.z, v.w);
        uint32_t addr = (uint32_t)k * 128 + ((uint32_t)((n4 >> 3) ^ (k & 7)) << 4) + (n4 & 7) * 2;
        *(uint2*)(g_W2img + addr) = make_uint2(hA, hB);
    } else if (idx < 11776) {               // w3: 64 x 128, rows 256B (hi only)
        int i = idx - 9728;
        int k = i >> 5, n4 = (i & 31) << 2;
        float4 v = *(const float4*)(w3 + (size_t)k * 128 + n4);
        uint32_t hA = packh2(v.x, v.y), hB = packh2(v.z, v.w);
        uint32_t addr = (uint32_t)k * 256 + ((uint32_t)((n4 >> 3) ^ (k & 7)) << 4) + (n4 & 7) * 2;
        *(uint2*)(g_W3img + addr) = make_uint2(hA, hB);
    } else if (idx < 19968) {               // Bnode = [w_src|w_dst]: 128 x 256, rows 512B
        int i = idx - 11776;
        int k = i >> 6, n4 = (i & 63) << 2;
        float4 v = (n4 < 128)
            ? *(const float4*)(w_src + (size_t)k * 128 + n4)
            : *(const float4*)(w_dst + (size_t)k * 128 + (n4 - 128));
        uint32_t hA = packh2(v.x, v.y), hB = packh2(v.z, v.w);
        uint32_t addr = (uint32_t)k * 512 + ((uint32_t)((n4 >> 3) ^ (k & 7)) << 4) + (n4 & 7) * 2;
        *(uint2*)(g_BnodeImg + addr) = make_uint2(hA, hB);
    } else if (idx < 24064) {               // w_proj: 128 x 128, rows 256B
        int i = idx - 19968;
        int k = i >> 5, n4 = (i & 31) << 2;
        float4 v = *(const float4*)(w_proj + (size_t)k * 128 + n4);
        uint32_t hA = packh2(v.x, v.y), hB = packh2(v.z, v.w);
        uint32_t addr = (uint32_t)k * 256 + ((uint32_t)((n4 >> 3) ^ (k & 7)) << 4) + (n4 & 7) * 2;
        *(uint2*)(g_PImg + addr) = make_uint2(hA, hB);
    }
}

// ---------------- K1: node GEMM on HMMA -> fp16 msg arrays (LINEAR rows) ----
__global__ __launch_bounds__(512, 1) void node_mma_kernel(
    const float* __restrict__ X, const float* __restrict__ bias_src, int n)
{
    extern __shared__ char dynsm[];
    __shared__ float sBias[128];
    const int tid = threadIdx.x;
    const int wid = tid >> 5, lane = tid & 31;
    const int mtx = lane >> 3, rin = lane & 7;
    const int lr = lane >> 2, lc = lane & 3;
    const int r0 = blockIdx.x * 128;

    const uint32_t sb = smem_u32(dynsm);
    const uint32_t Ahi = sb, Alo = sb + 32768, Bsm = sb + 65536;

#pragma unroll
    for (int it = 0; it < 8; it++) {
        int i = tid + 512 * it;
        CP16(Bsm + i * 16, g_BnodeImg + i * 16);
    }
    CP_COMMIT();
    if (tid < 128) sBias[tid] = bias_src[tid];

#pragma unroll
    for (int it = 0; it < 8; it++) {
        int i = tid + 512 * it;
        int m = i >> 5, k4 = (i & 31) << 2;
        int gr = r0 + m;
        float4 v = make_float4(0.f, 0.f, 0.f, 0.f);
        if (gr < n) v = *(const float4*)(X + (size_t)gr * 128 + k4);
        uint32_t hA, hB, lA, lB; split4(v, hA, hB, lA, lB);
        uint32_t addr = (uint32_t)m * 256 + ((uint32_t)((k4 >> 3) ^ (m & 7)) << 4) + (k4 & 7) * 2;
        STS64(Ahi + addr, hA, hB);
        STS64(Alo + addr, lA, lB);
    }
    CP_WAIT(0);
    __syncthreads();

    const int mi = wid & 3, ni = wid >> 2;
    const int mrow0 = mi * 32, ncol0 = ni * 64;

    float d[2][8][4];
#pragma unroll
    for (int a = 0; a < 2; a++)
#pragma unroll
        for (int b = 0; b < 8; b++)
#pragma unroll
            for (int c = 0; c < 4; c++) d[a][b][c] = 0.0f;

#pragma unroll
    for (int ks = 0; ks < 8; ks++) {
        uint32_t ah[2][4], al[2][4];
#pragma unroll
        for (int mt = 0; mt < 2; mt++) {
            int m = mrow0 + mt * 16 + (mtx & 1) * 8 + rin;
            int kchunk = ks * 2 + (mtx >> 1);
            uint32_t ao = (uint32_t)m * 256 + ((uint32_t)(kchunk ^ (m & 7)) << 4);
            LDSM4(ah[mt], Ahi + ao);
            LDSM4(al[mt], Alo + ao);
        }
        uint32_t b[4][4];
#pragma unroll
        for (int ntp = 0; ntp < 4; ntp++) {
            int k = ks * 16 + (mtx & 1) * 8 + rin;
            int nchunk = (ncol0 >> 3) + ntp * 2 + (mtx >> 1);
            LDSM4T(b[ntp], Bsm + (uint32_t)k * 512 + ((uint32_t)(nchunk ^ (k & 7)) << 4));
        }
#pragma unroll
        for (int mt = 0; mt < 2; mt++)
#pragma unroll
            for (int nt = 0; nt < 8; nt++) {
                MMA16816(d[mt][nt], ah[mt], b[nt >> 1][(nt & 1) * 2], b[nt >> 1][(nt & 1) * 2 + 1]);
                MMA16816(d[mt][nt], al[mt], b[nt >> 1][(nt & 1) * 2], b[nt >> 1][(nt & 1) * 2 + 1]);
            }
    }

#pragma unroll
    for (int mt = 0; mt < 2; mt++) {
        int gr0 = r0 + mrow0 + mt * 16 + lr;
        int gr1 = gr0 + 8;
#pragma unroll
        for (int nt = 0; nt < 8; nt++) {
            int cg = ncol0 + nt * 8 + lc * 2;
            float bb0 = 0.0f, bb1 = 0.0f;
            unsigned char* buf;
            int c;
            if (cg < 128) { buf = (unsigned char*)g_msgh_src; c = cg; bb0 = sBias[c]; bb1 = sBias[c + 1]; }
            else          { buf = (unsigned char*)g_msgh_dst; c = cg - 128; }
            if (gr0 < n)
                *(uint32_t*)(buf + (size_t)gr0 * 256 + c * 2) =
                    packh2(d[mt][nt][0] + bb0, d[mt][nt][1] + bb1);
            if (gr1 < n)
                *(uint32_t*)(buf + (size_t)gr1 * 256 + c * 2) =
                    packh2(d[mt][nt][2] + bb0, d[mt][nt][3] + bb1);
        }
    }
}

// ============================================================================
// K23: PERSISTENT fused kernel, TWO warp groups of 8, 64-edge tiles,
// single-pass fp16 MLP weights (lo-compensation dropped).
//
// Dynamic SMEM (221184 B):
//  [0,8K) W1 | [8K,24K) W2 | [24K,56K) W3 | [56K,120K) B   (hi-only used)
//  group g at 120K + g*48K: X(8K) H(8K) Msrc(16K,=A) Mdst(16K)
// ============================================================================
__global__ __launch_bounds__(512, 1) void fused_edge_kernel(
    const float* __restrict__ edge_scalars, const float* __restrict__ edge_attr,
    const int* __restrict__ edge_src, const int* __restrict__ edge_dst,
    const float* __restrict__ b1, const float* __restrict__ b2,
    const float* __restrict__ b3, const float* __restrict__ b_sep,
    const float* __restrict__ alpha_dot, int E, int numTiles)
{
    extern __shared__ char dynsm[];
    __shared__ float sB1[64], sB2[64], sB3[128];
    __shared__ float sBsep[256], sAD[128];
    __shared__ int   sSrc[2][64], sDst[2][64];
    __shared__ float sAttr[2][64];

    const int tid = threadIdx.x;
    const int lane = tid & 31;
    const int g = tid >> 8;            // warp group 0/1
    const int tg = tid & 255;          // tid within group
    const int wg = (tid >> 5) & 7;     // warp within group
    const int mtx = lane >> 3, rin = lane & 7;
    const int lr = lane >> 2, lc = lane & 3;

    const uint32_t sb = smem_u32(dynsm);
    const uint32_t W1hi = sb;
    const uint32_t W2hi = sb + 8192;
    const uint32_t W3hi = sb + 24576;
    const uint32_t Bsm  = sb + 57344;
    const uint32_t gbase = sb + 122880 + (uint32_t)g * 49152;
    const uint32_t Xhi  = gbase;
    const uint32_t Hsm  = gbase + 8192;
    const uint32_t Msrc = gbase + 16384;
    const uint32_t Mdst = gbase + 32768;
    const uint32_t Asm  = Msrc;

    // ---------------- one-time weight staging (hi-only) ----------------
    if (tid < 256) CP16(W1hi + tid * 16, g_W1img + tid * 16);        // 4KB
    if (tid < 512) CP16(W2hi + tid * 16, g_W2img + tid * 16);        // 8KB
#pragma unroll
    for (int it = 0; it < 2; it++) {                                 // 16KB
        int i = tid + 512 * it;
        if (i < 1024) CP16(W3hi + i * 16, g_W3img + i * 16);
    }
#pragma unroll
    for (int it = 0; it < 8; it++) {                                 // 64KB
        int i = tid + 512 * it;
        CP16(Bsm + i * 16, g_Bimg + i * 16);
    }
    CP_COMMIT();
    if (tid < 64)  { sB1[tid] = b1[tid]; sB2[tid] = b2[tid]; }
    if (tid < 128) { sB3[tid] = b3[tid]; sAD[tid] = alpha_dot[tid]; }
    if (tid < 256) sBsep[tid] = b_sep[tid];
    CP_WAIT(0);
    __syncthreads();

    // MLP warp tiling within group: 4 M-tiles x 2 N-tiles (M=64)
    const int mi1 = wg & 3, ni1 = wg >> 2;
    const int mr = mi1 * 16;
    // phase2 warp tiling within group: 2 M-tiles x 4 N-tiles
    const int mi = wg & 1, ni = wg >> 1;
    const int mrow0 = mi * 32, ncol0 = ni * 64;

    const int GB = 1 + g;              // group barrier id
    const int PB = 4 + g * 4 + mi1;    // layer2 pair barrier id

    // =================== persistent tile loop (64-edge tiles) ===============
    for (int tile = blockIdx.x * 2 + g; tile < numTiles; tile += gridDim.x * 2) {
        const int e0 = tile * 64;
        NBAR(GB, 256);   // previous iteration fully done with group buffers

        // ---- stage edge indices + X ----
        if (tg < 64) {
            int e = min(e0 + tg, E - 1);
            sSrc[g][tg] = edge_src[e];
            sDst[g][tg] = edge_dst[e];
            sAttr[g][tg] = (e0 + tg < E) ? edge_attr[e] : 0.0f;
        }
#pragma unroll
        for (int it = 0; it < 2; it++) {
            int i = tg + 256 * it;            // 0..511
            int m = i >> 3, k4 = (i & 7) << 2;
            int e = min(e0 + m, E - 1);
            float4 v = *(const float4*)(edge_scalars + (size_t)e * 32 + k4);
            uint32_t hA = packh2(v.x, v.y), hB = packh2(v.z, v.w);
            uint32_t addr = (uint32_t)m * 128 + ((uint32_t)(((k4 >> 3) ^ (m & 7))) << 4) + (k4 & 7) * 2;
            STS64(Xhi + addr, hA, hB);
        }
        NBAR(GB, 256);   // indices + X visible to group

        // ---- prefetch msg rows via cp.async (hidden under the MLP) ----
#pragma unroll
        for (int it = 0; it < 8; it++) {
            int i = tg + 256 * it;            // 0..2047
            int r = (i >> 4) & 63, seg = i & 15, buf = i >> 10;
            int node = buf ? sDst[g][r] : sSrc[g][r];
            const unsigned char* srcp =
                (const unsigned char*)(buf ? g_msgh_dst : g_msgh_src) +
                (size_t)node * 256 + seg * 16;
            uint32_t dst = (buf ? Mdst : Msrc) + (uint32_t)r * 256 +
                           ((uint32_t)(seg ^ (r & 7)) << 4);
            CP16(dst, srcp);
        }
        CP_COMMIT();

        // ---- layer1: H = silu(X @ W1 + b1) [64x64, K=32] ----
        {
            const int nc = ni1 * 32;
            float acc[4][4];
#pragma unroll
            for (int i = 0; i < 4; i++)
#pragma unroll
                for (int j = 0; j < 4; j++) acc[i][j] = 0.0f;
#pragma unroll
            for (int ks = 0; ks < 2; ks++) {
                int m = mr + (mtx & 1) * 8 + rin;
                int kc = ks * 2 + (mtx >> 1);
                uint32_t aH[4];
                LDSM4(aH, Xhi + (uint32_t)m * 128 + ((uint32_t)(kc ^ (m & 7)) << 4));
                uint32_t bH[2][4];
#pragma unroll
                for (int ntp = 0; ntp < 2; ntp++) {
                    int k = ks * 16 + (mtx & 1) * 8 + rin;
                    int nch = (nc >> 3) + ntp * 2 + (mtx >> 1);
                    uint32_t boff = (uint32_t)k * 128 + ((uint32_t)(nch ^ (k & 7)) << 4);
                    LDSM4T(bH[ntp], W1hi + boff);
                }
#pragma unroll
                for (int nt = 0; nt < 4; nt++)
                    MMA16816(acc[nt], aH, bH[nt >> 1][(nt & 1) * 2], bH[nt >> 1][(nt & 1) * 2 + 1]);
            }
#pragma unroll
            for (int nt = 0; nt < 4; nt++) {
                int col = nc + nt * 8 + lc * 2;
                float s0 = silu(acc[nt][0] + sB1[col]);
                float s1 = silu(acc[nt][1] + sB1[col + 1]);
                float s2 = silu(acc[nt][2] + sB1[col]);
                float s3 = silu(acc[nt][3] + sB1[col + 1]);
                int r0 = mr + lr, r1 = r0 + 8;
                uint32_t ad0 = (uint32_t)r0 * 128 + ((uint32_t)((col >> 3) ^ (r0 & 7)) << 4) + (col & 7) * 2;
                STS32(Hsm + ad0, packh2(s0, s1));
                uint32_t ad1 = (uint32_t)r1 * 128 + ((uint32_t)((col >> 3) ^ (r1 & 7)) << 4) + (col & 7) * 2;
                STS32(Hsm + ad1, packh2(s2, s3));
            }
        }
        NBAR(GB, 256);

        // ---- layer2: H <- silu(H @ W2 + b2) [64x64, K=64] (in place) ----
        {
            const int nc = ni1 * 32;
            float acc[4][4];
#pragma unroll
            for (int i = 0; i < 4; i++)
#pragma unroll
                for (int j = 0; j < 4; j++) acc[i][j] = 0.0f;
#pragma unroll
            for (int ks = 0; ks < 4; ks++) {
                int m = mr + (mtx & 1) * 8 + rin;
                int kc = ks * 2 + (mtx >> 1);
                uint32_t aH[4];
                LDSM4(aH, Hsm + (uint32_t)m * 128 + ((uint32_t)(kc ^ (m & 7)) << 4));
                uint32_t bH[2][4];
#pragma unroll
                for (int ntp = 0; ntp < 2; ntp++) {
                    int k = ks * 16 + (mtx & 1) * 8 + rin;
                    int nch = (nc >> 3) + ntp * 2 + (mtx >> 1);
                    uint32_t boff = (uint32_t)k * 128 + ((uint32_t)(nch ^ (k & 7)) << 4);
                    LDSM4T(bH[ntp], W2hi + boff);
                }
#pragma unroll
                for (int nt = 0; nt < 4; nt++)
                    MMA16816(acc[nt], aH, bH[nt >> 1][(nt & 1) * 2], bH[nt >> 1][(nt & 1) * 2 + 1]);
            }
            // pair barrier: both N-warps of this row block finished reading H
            NBAR(PB, 64);
#pragma unroll
            for (int nt = 0; nt < 4; nt++) {
                int col = nc + nt * 8 + lc * 2;
                float s0 = silu(acc[nt][0] + sB2[col]);
                float s1 = silu(acc[nt][1] + sB2[col + 1]);
                float s2 = silu(acc[nt][2] + sB2[col]);
                float s3 = silu(acc[nt][3] + sB2[col + 1]);
                int r0 = mr + lr, r1 = r0 + 8;
                uint32_t ad0 = (uint32_t)r0 * 128 + ((uint32_t)((col >> 3) ^ (r0 & 7)) << 4) + (col & 7) * 2;
                STS32(Hsm + ad0, packh2(s0, s1));
                uint32_t ad1 = (uint32_t)r1 * 128 + ((uint32_t)((col >> 3) ^ (r1 & 7)) << 4) + (col & 7) * 2;
                STS32(Hsm + ad1, packh2(s2, s3));
            }
        }
        NBAR(GB, 256);

        // ---- layer3: rad = H @ W3 + b3 [64x128, K=64] (regs) ----
        float acc3[8][4];
#pragma unroll
        for (int i = 0; i < 8; i++)
#pragma unroll
            for (int j = 0; j < 4; j++) acc3[i][j] = 0.0f;
        {
            const int nc = ni1 * 64;
#pragma unroll
            for (int ks = 0; ks < 4; ks++) {
                int m = mr + (mtx & 1) * 8 + rin;
                int kc = ks * 2 + (mtx >> 1);
                uint32_t aH[4];
                LDSM4(aH, Hsm + (uint32_t)m * 128 + ((uint32_t)(kc ^ (m & 7)) << 4));
                uint32_t bH[4][4];
#pragma unroll
                for (int ntp = 0; ntp < 4; ntp++) {
                    int k = ks * 16 + (mtx & 1) * 8 + rin;
                    int nch = (nc >> 3) + ntp * 2 + (mtx >> 1);
                    uint32_t boff = (uint32_t)k * 256 + ((uint32_t)(nch ^ (k & 7)) << 4);
                    LDSM4T(bH[ntp], W3hi + boff);
                }
#pragma unroll
                for (int nt = 0; nt < 8; nt++)
                    MMA16816(acc3[nt], aH, bH[nt >> 1][(nt & 1) * 2], bH[nt >> 1][(nt & 1) * 2 + 1]);
            }
        }
        CP_WAIT(0);       // this thread's msg copies done
        NBAR(GB, 256);    // whole group's copies done

        // ---- gather from SMEM + form A = (src+dst)*attr*rad (in place) ----
        {
            const int nc = ni1 * 64;
#pragma unroll
            for (int rh = 0; rh < 2; rh++) {
                int r = mr + rh * 8 + lr;
                float at = sAttr[g][r];
#pragma unroll
                for (int nt = 0; nt < 8; nt++) {
                    int col = nc + nt * 8 + lc * 2;
                    uint32_t ad = (uint32_t)r * 256 + ((uint32_t)((col >> 3) ^ (r & 7)) << 4) + (col & 7) * 2;
                    uint32_t us, ud;
                    LDS32(us, Msrc + ad);
                    LDS32(ud, Mdst + ad);
                    float2 ms = __half22float2(*(__half2*)&us);
                    float2 md = __half22float2(*(__half2*)&ud);
                    float rad0 = acc3[nt][rh * 2 + 0] + sB3[col];
                    float rad1 = acc3[nt][rh * 2 + 1] + sB3[col + 1];
                    float m0 = (ms.x + md.x) * at * rad0;
                    float m1 = (ms.y + md.y) * at * rad1;
                    STS32(Asm + ad, packh2(m0, m1));
                }
            }
        }
        NBAR(GB, 256);

        // ---- phase2: D[64,256] = A @ B + epilogue ----
        float d[2][8][4];
#pragma unroll
        for (int a = 0; a < 2; a++)
#pragma unroll
            for (int b = 0; b < 8; b++)
#pragma unroll
                for (int c = 0; c < 4; c++) d[a][b][c] = 0.0f;

#pragma unroll
        for (int ks = 0; ks < 8; ks++) {
            uint32_t ah[2][4];
#pragma unroll
            for (int mt = 0; mt < 2; mt++) {
                int m = mrow0 + mt * 16 + (mtx & 1) * 8 + rin;
                int kchunk = ks * 2 + (mtx >> 1);
                LDSM4(ah[mt], Asm + (uint32_t)m * 256 + ((uint32_t)(kchunk ^ (m & 7)) << 4));
            }
            uint32_t b[4][4];
#pragma unroll
            for (int ntp = 0; ntp < 4; ntp++) {
                int k = ks * 16 + (mtx & 1) * 8 + rin;
                int nchunk = (ncol0 >> 3) + ntp * 2 + (mtx >> 1);
                LDSM4T(b[ntp], Bsm + (uint32_t)k * 512 + ((uint32_t)(nchunk ^ (k & 7)) << 4));
            }
#pragma unroll
            for (int mt = 0; mt < 2; mt++)
#pragma unroll
                for (int nt = 0; nt < 8; nt++)
                    MMA16816(d[mt][nt], ah[mt], b[nt >> 1][(nt & 1) * 2], b[nt >> 1][(nt & 1) * 2 + 1]);
        }

        // ---- epilogue: w = exp(score); direct segment reduction ----
#pragma unroll
        for (int hh = 0; hh < 2; hh++) {
            const int h = ni * 2 + hh;
#pragma unroll
            for (int mt = 0; mt < 2; mt++) {
                const int r0i = mrow0 + mt * 16 + lr;
                const int e0i = e0 + r0i;
                float p0 = 0.0f, p1 = 0.0f;
#pragma unroll
                for (int q = 0; q < 2; q++) {
                    const int nt = hh * 4 + q;
                    const int colb = ncol0 + nt * 8 + lc * 2;
                    const int jb = q * 8 + lc * 2;
                    const float bb0 = sBsep[colb], bb1 = sBsep[colb + 1];
                    const float w0 = sAD[h * 16 + jb], w1 = sAD[h * 16 + jb + 1];
                    float x, sg;
                    x = d[mt][nt][0] + bb0; sg = 1.0f / (1.0f + __expf(-x)); p0 += x * (0.2f + 0.8f * sg) * w0;
                    x = d[mt][nt][1] + bb1; sg = 1.0f / (1.0f + __expf(-x)); p0 += x * (0.2f + 0.8f * sg) * w1;
                    x = d[mt][nt][2] + bb0; sg = 1.0f / (1.0f + __expf(-x)); p1 += x * (0.2f + 0.8f * sg) * w0;
                    x = d[mt][nt][3] + bb1; sg = 1.0f / (1.0f + __expf(-x)); p1 += x * (0.2f + 0.8f * sg) * w1;
                }
                p0 += __shfl_xor_sync(0xffffffffu, p0, 1);
                p0 += __shfl_xor_sync(0xffffffffu, p0, 2);
                p1 += __shfl_xor_sync(0xffffffffu, p1, 1);
                p1 += __shfl_xor_sync(0xffffffffu, p1, 2);
                const float ew0 = __expf(p0), ew1 = __expf(p1);
                const int d0 = sDst[g][r0i], d1 = sDst[g][r0i + 8];
                if (lc == 0) {
                    if (e0i < E)     atomicAdd(&g_nsum[(size_t)d0 * 8 + h], ew0);
                    if (e0i + 8 < E) atomicAdd(&g_nsum[(size_t)d1 * 8 + h], ew1);
                }
#pragma unroll
                for (int q = 0; q < 2; q++) {
                    const int nt = hh * 4 + 2 + q;
                    const int colb = ncol0 + nt * 8 + lc * 2;
                    const int vidx = q * 8 + lc * 2;
                    const float bb0 = sBsep[colb], bb1 = sBsep[colb + 1];
                    if (e0i < E)
                        RED2(g_nacc + (size_t)d0 * 128 + h * 16 + vidx,
                             (d[mt][nt][0] + bb0) * ew0, (d[mt][nt][1] + bb1) * ew0);
                    if (e0i + 8 < E)
                        RED2(g_nacc + (size_t)d1 * 128 + h * 16 + vidx,
                             (d[mt][nt][2] + bb0) * ew1, (d[mt][nt][3] + bb1) * ew1);
                }
            }
        }
    }
}

// ---------------- K5: out GEMM on HMMA ---------------------------------------
__global__ __launch_bounds__(512, 1) void out_mma_kernel(
    const float* __restrict__ bias, float* __restrict__ out, int n)
{
    extern __shared__ char dynsm[];
    __shared__ float sBias[128];
    const int tid = threadIdx.x;
    const int wid = tid >> 5, lane = tid & 31;
    const int mtx = lane >> 3, rin = lane & 7;
    const int lr = lane >> 2, lc = lane & 3;
    const int r0 = blockIdx.x * 128;

    const uint32_t sb = smem_u32(dynsm);
    const uint32_t Ahi = sb, Alo = sb + 32768, Bsm = sb + 65536;

#pragma unroll
    for (int it = 0; it < 4; it++) {
        int i = tid + 512 * it;
        CP16(Bsm + i * 16, g_PImg + i * 16);
    }
    CP_COMMIT();
    if (tid < 128) sBias[tid] = bias[tid];

#pragma unroll
    for (int it = 0; it < 8; it++) {
        int i = tid + 512 * it;
        int m = i >> 5, k4 = (i & 31) << 2;
        int gr = r0 + m;
        float4 v = make_float4(0.f, 0.f, 0.f, 0.f);
        if (gr < n) {
            v = *(const float4*)(g_nacc + (size_t)gr * 128 + k4);
            float inv = 1.0f / (g_nsum[(size_t)gr * 8 + (k4 >> 4)] + 1e-16f);
            v.x *= inv; v.y *= inv; v.z *= inv; v.w *= inv;
        }
        uint32_t hA, hB, lA, lB; split4(v, hA, hB, lA, lB);
        uint32_t addr = (uint32_t)m * 256 + ((uint32_t)((k4 >> 3) ^ (m & 7)) << 4) + (k4 & 7) * 2;
        STS64(Ahi + addr, hA, hB);
        STS64(Alo + addr, lA, lB);
    }
    CP_WAIT(0);
    __syncthreads();

    const int mi = wid & 3, ni = wid >> 2;
    const int mrow0 = mi * 32, ncol0 = ni * 32;

    float d[2][4][4];
#pragma unroll
    for (int a = 0; a < 2; a++)
#pragma unroll
        for (int b = 0; b < 4; b++)
#pragma unroll
            for (int c = 0; c < 4; c++) d[a][b][c] = 0.0f;

#pragma unroll
    for (int ks = 0; ks < 8; ks++) {
        uint32_t ah[2][4], al[2][4];
#pragma unroll
        for (int mt = 0; mt < 2; mt++) {
            int m = mrow0 + mt * 16 + (mtx & 1) * 8 + rin;
            int kchunk = ks * 2 + (mtx >> 1);
            uint32_t ao = (uint32_t)m * 256 + ((uint32_t)(kchunk ^ (m & 7)) << 4);
            LDSM4(ah[mt], Ahi + ao);
            LDSM4(al[mt], Alo + ao);
        }
        uint32_t b[2][4];
#pragma unroll
        for (int ntp = 0; ntp < 2; ntp++) {
            int k = ks * 16 + (mtx & 1) * 8 + rin;
            int nchunk = (ncol0 >> 3) + ntp * 2 + (mtx >> 1);
            LDSM4T(b[ntp], Bsm + (uint32_t)k * 256 + ((uint32_t)(nchunk ^ (k & 7)) << 4));
        }
#pragma unroll
        for (int mt = 0; mt < 2; mt++)
#pragma unroll
            for (int nt = 0; nt < 4; nt++) {
                MMA16816(d[mt][nt], ah[mt], b[nt >> 1][(nt & 1) * 2], b[nt >> 1][(nt & 1) * 2 + 1]);
                MMA16816(d[mt][nt], al[mt], b[nt >> 1][(nt & 1) * 2], b[nt >> 1][(nt & 1) * 2 + 1]);
            }
    }

#pragma unroll
    for (int mt = 0; mt < 2; mt++) {
        int gr0 = r0 + mrow0 + mt * 16 + lr;
        int gr1 = gr0 + 8;
#pragma unroll
        for (int nt = 0; nt < 4; nt++) {
            int c = ncol0 + nt * 8 + lc * 2;
            float bb0 = sBias[c], bb1 = sBias[c + 1];
            if (gr0 < n)
                *(float2*)(out + (size_t)gr0 * 128 + c) =
                    make_float2(d[mt][nt][0] + bb0, d[mt][nt][1] + bb1);
            if (gr1 < n)
                *(float2*)(out + (size_t)gr1 * 128 + c) =
                    make_float2(d[mt][nt][2] + bb0, d[mt][nt][3] + bb1);
        }
    }
}

// ---------------- launch ----------------
extern "C" void kernel_launch(void* const* d_in, const int* in_sizes, int n_in,
                              void* d_out, int out_size)
{
    const float* node_input = (const float*)d_in[0];
    const float* edge_attr  = (const float*)d_in[2];
    const float* edge_scal  = (const float*)d_in[3];
    const int*   edge_src   = (const int*)d_in[4];
    const int*   edge_dst   = (const int*)d_in[5];
    const float* w_src      = (const float*)d_in[7];
    const float* b_src      = (const float*)d_in[8];
    const float* w_dst      = (const float*)d_in[9];
    const float* fc_w1      = (const float*)d_in[10];
    const float* fc_b1      = (const float*)d_in[11];
    const float* fc_w2      = (const float*)d_in[12];
    const float* fc_b2      = (const float*)d_in[13];
    const float* fc_w3      = (const float*)d_in[14];
    const float* fc_b3      = (const float*)d_in[15];
    const float* w_sep      = (const float*)d_in[16];
    const float* b_sep      = (const float*)d_in[17];
    const float* alpha_dot  = (const float*)d_in[18];
    const float* w_proj     = (const float*)d_in[19];
    const float* b_proj     = (const float*)d_in[20];
    float* out = (float*)d_out;

    int N = in_sizes[0] / 128;
    int E = in_sizes[4];

    cudaFuncSetAttribute(fused_edge_kernel, cudaFuncAttributeMaxDynamicSharedMemorySize, 221184);
    cudaFuncSetAttribute(node_mma_kernel,   cudaFuncAttributeMaxDynamicSharedMemorySize, 131072);
    cudaFuncSetAttribute(out_mma_kernel,    cudaFuncAttributeMaxDynamicSharedMemorySize, 98304);

    static int sms = 0;
    if (sms == 0) {
        cudaDeviceGetAttribute(&sms, cudaDevAttrMultiProcessorCount, 0);
        if (sms <= 0) sms = 148;
    }

    init_kernel<<<(N * 128 + 255) / 256, 256>>>(N);
    prep_kernel<<<94, 256>>>(fc_w1, fc_w2, fc_w3, w_sep, w_src, w_dst, w_proj);

    int nt = (N + 127) / 128;
    node_mma_kernel<<<nt, 512, 131072>>>(node_input, b_src, N);

    int numTiles = (E + 63) / 64;               // 64-edge tiles
    int nblk = (numTiles + 1) / 2;
    if (nblk > sms) nblk = sms;
    fused_edge_kernel<<<nblk, 512, 221184>>>(edge_scal, edge_attr, edge_src, edge_dst,
                                             fc_b1, fc_b2, fc_b3,
                                             b_sep, alpha_dot, E, numTiles);

    out_mma_kernel<<<nt, 512, 98304>>>(b_proj, out, N);
}

// round 16
// speedup vs baseline: 1.6953x; 1.0197x over previous
#include <cuda_runtime.h>
#include <cuda_fp16.h>
#include <cstdint>
#include <math.h>

// ---------------- fixed problem geometry ----------------
#define MAXN 50000
#define MAXE 800000
// C=128, A_ALL=256, RAD_IN=32, FC1=FC2=64, H=8, AH=VH=16

// ---------------- scratch ----------------
__device__ __align__(16) __half g_msgh_src[(size_t)MAXN * 128];   // LINEAR rows
__device__ __align__(16) __half g_msgh_dst[(size_t)MAXN * 128];   // LINEAR rows
__device__ __align__(16) float g_nsum[(size_t)MAXN * 8];
__device__ __align__(16) float g_nacc[(size_t)MAXN * 128];
// prepacked fp16 weight images (exact SMEM layouts, swizzled)
__device__ __align__(16) unsigned char g_Bimg[65536];    // w_sep [k][n] 256n
__device__ __align__(16) unsigned char g_W1img[4096];    // hi only
__device__ __align__(16) unsigned char g_W2img[8192];    // hi only
__device__ __align__(16) unsigned char g_W3img[16384];   // hi only
__device__ __align__(16) unsigned char g_BnodeImg[65536];// [w_src|w_dst] [k][256n]
__device__ __align__(16) unsigned char g_PImg[32768];    // w_proj [k][128n]

// ---------------- helpers ----------------
__device__ __forceinline__ uint32_t smem_u32(const void* p) {
    uint32_t a;
    asm("{ .reg .u64 t; cvta.to.shared.u64 t, %1; cvt.u32.u64 %0, t; }"
        : "=r"(a) : "l"(p));
    return a;
}

#define LDSM4(r, addr) \
    asm volatile("ldmatrix.sync.aligned.m8n8.x4.shared.b16 {%0,%1,%2,%3}, [%4];" \
        : "=r"((r)[0]), "=r"((r)[1]), "=r"((r)[2]), "=r"((r)[3]) : "r"(addr))

#define LDSM4T(r, addr) \
    asm volatile("ldmatrix.sync.aligned.m8n8.x4.trans.shared.b16 {%0,%1,%2,%3}, [%4];" \
        : "=r"((r)[0]), "=r"((r)[1]), "=r"((r)[2]), "=r"((r)[3]) : "r"(addr))

#define MMA16816(d, a, b0v, b1v) \
    asm volatile("mma.sync.aligned.m16n8k16.row.col.f32.f16.f16.f32 " \
        "{%0,%1,%2,%3}, {%4,%5,%6,%7}, {%8,%9}, {%0,%1,%2,%3};" \
        : "+f"((d)[0]), "+f"((d)[1]), "+f"((d)[2]), "+f"((d)[3]) \
        : "r"((a)[0]), "r"((a)[1]), "r"((a)[2]), "r"((a)[3]), "r"(b0v), "r"(b1v))

#define STS32(addr, v) \
    asm volatile("st.shared.b32 [%0], %1;" :: "r"(addr), "r"(v))
#define STS64(addr, v0, v1) \
    asm volatile("st.shared.v2.b32 [%0], {%1,%2};" :: "r"(addr), "r"(v0), "r"(v1))
#define LDS32(v, addr) \
    asm volatile("ld.shared.b32 %0, [%1];" : "=r"(v) : "r"(addr))

// async 16B global->shared copy (sm_80+)
#define CP16(dst, src) \
    asm volatile("{ .reg .u64 g; cvta.to.global.u64 g, %1; " \
                 "cp.async.cg.shared.global [%0], [g], 16; }" \
                 :: "r"(dst), "l"(src) : "memory")
#define CP_COMMIT() asm volatile("cp.async.commit_group;" ::: "memory")
#define CP_WAIT(n)  asm volatile("cp.async.wait_group %0;" :: "n"(n) : "memory")

// vector fire-and-forget global reduction (sm_90+)
#define RED2(ptr, x, y) \
    asm volatile("red.global.add.v2.f32 [%0], {%1,%2};" :: "l"(ptr), "f"(x), "f"(y) : "memory")

// named barrier
#define NBAR(id, cnt) \
    asm volatile("bar.sync %0, %1;" :: "r"(id), "r"(cnt) : "memory")

__device__ __forceinline__ uint32_t packh2(float x, float y) {
    __half2 t = __floats2half2_rn(x, y);
    return *(uint32_t*)&t;
}
__device__ __forceinline__ void split2(float x, float y, uint32_t& hi, uint32_t& lo) {
    __half h0 = __float2half_rn(x), h1 = __float2half_rn(y);
    __half2 hh = __halves2half2(h0, h1);
    hi = *(uint32_t*)&hh;
    lo = packh2(x - __half2float(h0), y - __half2float(h1));
}
__device__ __forceinline__ void split4(float4 v, uint32_t& hA, uint32_t& hB,
                                       uint32_t& lA, uint32_t& lB) {
    split2(v.x, v.y, hA, lA);
    split2(v.z, v.w, hB, lB);
}
__device__ __forceinline__ float silu(float x) {
    return x / (1.0f + __expf(-x));
}

// ---------------- K0: init segment buffers ----------------
__global__ void init_kernel(int n) {
    int i = blockIdx.x * blockDim.x + threadIdx.x;
    if (i < n * 128) g_nacc[i] = 0.0f;
    if (i < n * 8) g_nsum[i] = 0.0f;
}

// ---------------- K0b: prepack weight images (fp16, swizzled SMEM layout) --
__global__ void prep_kernel(const float* __restrict__ w1, const float* __restrict__ w2,
                            const float* __restrict__ w3, const float* __restrict__ w_sep,
                            const float* __restrict__ w_src, const float* __restrict__ w_dst,
                            const float* __restrict__ w_proj)
{
    int idx = blockIdx.x * blockDim.x + threadIdx.x;  // float4 units
    if (idx < 8192) {                       // w_sep: 128 x 256, rows 512B
        int k = idx >> 6, n4 = (idx & 63) << 2;
        float4 v = *(const float4*)(w_sep + (size_t)k * 256 + n4);
        uint32_t hA = packh2(v.x, v.y), hB = packh2(v.z, v.w);
        uint32_t addr = (uint32_t)k * 512 + ((uint32_t)((n4 >> 3) ^ (k & 7)) << 4) + (n4 & 7) * 2;
        *(uint2*)(g_Bimg + addr) = make_uint2(hA, hB);
    } else if (idx < 8704) {                // w1: 32 x 64, rows 128B (hi only)
        int i = idx - 8192;
        int k = i >> 4, n4 = (i & 15) << 2;
        float4 v = *(const float4*)(w1 + (size_t)k * 64 + n4);
        uint32_t hA = packh2(v.x, v.y), hB = packh2(v.z, v.w);
        uint32_t addr = (uint32_t)k * 128 + ((uint32_t)((n4 >> 3) ^ (k & 7)) << 4) + (n4 & 7) * 2;
        *(uint2*)(g_W1img + addr) = make_uint2(hA, hB);
    } else if (idx < 9728) {                // w2: 64 x 64, rows 128B (hi only)
        int i = idx - 8704;
        int k = i >> 4, n4 = (i & 15) << 2;
        float4 v = *(const float4*)(w2 + (size_t)k * 64 + n4);
        uint32_t hA = packh2(v.x, v.y), hB = packh2(v.z, v.w);
        uint32_t addr = (uint32_t)k * 128 + ((uint32_t)((n4 >> 3) ^ (k & 7)) << 4) + (n4 & 7) * 2;
        *(uint2*)(g_W2img + addr) = make_uint2(hA, hB);
    } else if (idx < 11776) {               // w3: 64 x 128, rows 256B (hi only)
        int i = idx - 9728;
        int k = i >> 5, n4 = (i & 31) << 2;
        float4 v = *(const float4*)(w3 + (size_t)k * 128 + n4);
        uint32_t hA = packh2(v.x, v.y), hB = packh2(v.z, v.w);
        uint32_t addr = (uint32_t)k * 256 + ((uint32_t)((n4 >> 3) ^ (k & 7)) << 4) + (n4 & 7) * 2;
        *(uint2*)(g_W3img + addr) = make_uint2(hA, hB);
    } else if (idx < 19968) {               // Bnode = [w_src|w_dst]: 128 x 256, rows 512B
        int i = idx - 11776;
        int k = i >> 6, n4 = (i & 63) << 2;
        float4 v = (n4 < 128)
            ? *(const float4*)(w_src + (size_t)k * 128 + n4)
            : *(const float4*)(w_dst + (size_t)k * 128 + (n4 - 128));
        uint32_t hA = packh2(v.x, v.y), hB = packh2(v.z, v.w);
        uint32_t addr = (uint32_t)k * 512 + ((uint32_t)((n4 >> 3) ^ (k & 7)) << 4) + (n4 & 7) * 2;
        *(uint2*)(g_BnodeImg + addr) = make_uint2(hA, hB);
    } else if (idx < 24064) {               // w_proj: 128 x 128, rows 256B
        int i = idx - 19968;
        int k = i >> 5, n4 = (i & 31) << 2;
        float4 v = *(const float4*)(w_proj + (size_t)k * 128 + n4);
        uint32_t hA = packh2(v.x, v.y), hB = packh2(v.z, v.w);
        uint32_t addr = (uint32_t)k * 256 + ((uint32_t)((n4 >> 3) ^ (k & 7)) << 4) + (n4 & 7) * 2;
        *(uint2*)(g_PImg + addr) = make_uint2(hA, hB);
    }
}

// ---------------- K1: node GEMM on HMMA -> fp16 msg arrays (LINEAR rows) ----
__global__ __launch_bounds__(512, 1) void node_mma_kernel(
    const float* __restrict__ X, const float* __restrict__ bias_src, int n)
{
    extern __shared__ char dynsm[];
    __shared__ float sBias[128];
    const int tid = threadIdx.x;
    const int wid = tid >> 5, lane = tid & 31;
    const int mtx = lane >> 3, rin = lane & 7;
    const int lr = lane >> 2, lc = lane & 3;
    const int r0 = blockIdx.x * 128;

    const uint32_t sb = smem_u32(dynsm);
    const uint32_t Ahi = sb, Alo = sb + 32768, Bsm = sb + 65536;

#pragma unroll
    for (int it = 0; it < 8; it++) {
        int i = tid + 512 * it;
        CP16(Bsm + i * 16, g_BnodeImg + i * 16);
    }
    CP_COMMIT();
    if (tid < 128) sBias[tid] = bias_src[tid];

#pragma unroll
    for (int it = 0; it < 8; it++) {
        int i = tid + 512 * it;
        int m = i >> 5, k4 = (i & 31) << 2;
        int gr = r0 + m;
        float4 v = make_float4(0.f, 0.f, 0.f, 0.f);
        if (gr < n) v = *(const float4*)(X + (size_t)gr * 128 + k4);
        uint32_t hA, hB, lA, lB; split4(v, hA, hB, lA, lB);
        uint32_t addr = (uint32_t)m * 256 + ((uint32_t)((k4 >> 3) ^ (m & 7)) << 4) + (k4 & 7) * 2;
        STS64(Ahi + addr, hA, hB);
        STS64(Alo + addr, lA, lB);
    }
    CP_WAIT(0);
    __syncthreads();

    const int mi = wid & 3, ni = wid >> 2;
    const int mrow0 = mi * 32, ncol0 = ni * 64;

    float d[2][8][4];
#pragma unroll
    for (int a = 0; a < 2; a++)
#pragma unroll
        for (int b = 0; b < 8; b++)
#pragma unroll
            for (int c = 0; c < 4; c++) d[a][b][c] = 0.0f;

#pragma unroll
    for (int ks = 0; ks < 8; ks++) {
        uint32_t ah[2][4], al[2][4];
#pragma unroll
        for (int mt = 0; mt < 2; mt++) {
            int m = mrow0 + mt * 16 + (mtx & 1) * 8 + rin;
            int kchunk = ks * 2 + (mtx >> 1);
            uint32_t ao = (uint32_t)m * 256 + ((uint32_t)(kchunk ^ (m & 7)) << 4);
            LDSM4(ah[mt], Ahi + ao);
            LDSM4(al[mt], Alo + ao);
        }
        uint32_t b[4][4];
#pragma unroll
        for (int ntp = 0; ntp < 4; ntp++) {
            int k = ks * 16 + (mtx & 1) * 8 + rin;
            int nchunk = (ncol0 >> 3) + ntp * 2 + (mtx >> 1);
            LDSM4T(b[ntp], Bsm + (uint32_t)k * 512 + ((uint32_t)(nchunk ^ (k & 7)) << 4));
        }
#pragma unroll
        for (int mt = 0; mt < 2; mt++)
#pragma unroll
            for (int nt = 0; nt < 8; nt++) {
                MMA16816(d[mt][nt], ah[mt], b[nt >> 1][(nt & 1) * 2], b[nt >> 1][(nt & 1) * 2 + 1]);
                MMA16816(d[mt][nt], al[mt], b[nt >> 1][(nt & 1) * 2], b[nt >> 1][(nt & 1) * 2 + 1]);
            }
    }

#pragma unroll
    for (int mt = 0; mt < 2; mt++) {
        int gr0 = r0 + mrow0 + mt * 16 + lr;
        int gr1 = gr0 + 8;
#pragma unroll
        for (int nt = 0; nt < 8; nt++) {
            int cg = ncol0 + nt * 8 + lc * 2;
            float bb0 = 0.0f, bb1 = 0.0f;
            unsigned char* buf;
            int c;
            if (cg < 128) { buf = (unsigned char*)g_msgh_src; c = cg; bb0 = sBias[c]; bb1 = sBias[c + 1]; }
            else          { buf = (unsigned char*)g_msgh_dst; c = cg - 128; }
            if (gr0 < n)
                *(uint32_t*)(buf + (size_t)gr0 * 256 + c * 2) =
                    packh2(d[mt][nt][0] + bb0, d[mt][nt][1] + bb1);
            if (gr1 < n)
                *(uint32_t*)(buf + (size_t)gr1 * 256 + c * 2) =
                    packh2(d[mt][nt][2] + bb0, d[mt][nt][3] + bb1);
        }
    }
}

// ============================================================================
// K23: PERSISTENT fused kernel, TWO warp groups of 8, 64-edge tiles,
// software-pipelined front-end: next tile's indices (LDG during phase2) and
// raw X (cp.async during MLP) prefetched one tile ahead.
//
// Dynamic SMEM (221184 B):
//  [0,8K) W1 | [8K,24K) W2 | [24K,56K) W3 | [56K,120K) B
//  group g at 120K + g*48K: Xraw(8K) H(8K, doubles as X image) Msrc(16K,=A) Mdst(16K)
// ============================================================================
__global__ __launch_bounds__(512, 1) void fused_edge_kernel(
    const float* __restrict__ edge_scalars, const float* __restrict__ edge_attr,
    const int* __restrict__ edge_src, const int* __restrict__ edge_dst,
    const float* __restrict__ b1, const float* __restrict__ b2,
    const float* __restrict__ b3, const float* __restrict__ b_sep,
    const float* __restrict__ alpha_dot, int E, int numTiles)
{
    extern __shared__ char dynsm[];
    __shared__ float sB1[64], sB2[64], sB3[128];
    __shared__ float sBsep[256], sAD[128];
    __shared__ int   sSrc[2][2][64], sDst[2][2][64];
    __shared__ float sAttr[2][2][64];

    const int tid = threadIdx.x;
    const int lane = tid & 31;
    const int g = tid >> 8;            // warp group 0/1
    const int tg = tid & 255;          // tid within group
    const int wg = (tid >> 5) & 7;     // warp within group
    const int mtx = lane >> 3, rin = lane & 7;
    const int lr = lane >> 2, lc = lane & 3;

    const uint32_t sb = smem_u32(dynsm);
    const uint32_t W1hi = sb;
    const uint32_t W2hi = sb + 8192;
    const uint32_t W3hi = sb + 24576;
    const uint32_t Bsm  = sb + 57344;
    const uint32_t goff = 122880 + (uint32_t)g * 49152;
    char* const XrawP   = dynsm + goff;              // 8KB raw fp32 (64 x 128B)
    const uint32_t Hsm  = sb + goff + 8192;          // X image + H (in place)
    const uint32_t Msrc = sb + goff + 16384;
    const uint32_t Mdst = sb + goff + 32768;
    const uint32_t Asm  = Msrc;

    // ---------------- one-time weight staging (hi-only) ----------------
    if (tid < 256) CP16(W1hi + tid * 16, g_W1img + tid * 16);        // 4KB
    if (tid < 512) CP16(W2hi + tid * 16, g_W2img + tid * 16);        // 8KB
#pragma unroll
    for (int it = 0; it < 2; it++) {                                 // 16KB
        int i = tid + 512 * it;
        if (i < 1024) CP16(W3hi + i * 16, g_W3img + i * 16);
    }
#pragma unroll
    for (int it = 0; it < 8; it++) {                                 // 64KB
        int i = tid + 512 * it;
        CP16(Bsm + i * 16, g_Bimg + i * 16);
    }
    CP_COMMIT();
    if (tid < 64)  { sB1[tid] = b1[tid]; sB2[tid] = b2[tid]; }
    if (tid < 128) { sB3[tid] = b3[tid]; sAD[tid] = alpha_dot[tid]; }
    if (tid < 256) sBsep[tid] = b_sep[tid];
    CP_WAIT(0);
    __syncthreads();

    // MLP warp tiling within group: 4 M-tiles x 2 N-tiles (M=64)
    const int mi1 = wg & 3, ni1 = wg >> 2;
    const int mr = mi1 * 16;
    // phase2 warp tiling within group: 2 M-tiles x 4 N-tiles
    const int mi = wg & 1, ni = wg >> 1;
    const int mrow0 = mi * 32, ncol0 = ni * 64;

    const int GB = 1 + g;              // group barrier id
    const int PB = 4 + g * 4 + mi1;    // layer1/2 pair barrier id
    const int stride = gridDim.x * 2;

    // ---------------- prefill: tile0 indices (LDG) + Xraw (cp.async) --------
    int tile = blockIdx.x * 2 + g;
    int pb = 0;
    if (tile < numTiles) {
        int e0p = tile * 64;
        if (tg < 64) {
            int e = min(e0p + tg, E - 1);
            sSrc[g][0][tg] = edge_src[e];
            sDst[g][0][tg] = edge_dst[e];
            sAttr[g][0][tg] = (e0p + tg < E) ? edge_attr[e] : 0.0f;
        }
#pragma unroll
        for (int it = 0; it < 2; it++) {
            int i = tg + 256 * it;            // 0..511
            int m = i >> 3, c = i & 7;
            int e = min(e0p + m, E - 1);
            CP16((uint32_t)(sb + goff) + (uint32_t)m * 128 + c * 16,
                 (const unsigned char*)edge_scalars + (size_t)e * 128 + c * 16);
        }
    }
    CP_COMMIT();     // group: pre(tile0)

    // =================== persistent tile loop (64-edge tiles) ===============
    while (tile < numTiles) {
        const int e0 = tile * 64;
        const int tn = tile + stride;

        NBAR(GB, 256);   // prev tile fully done with group buffers; idx[pb] ready
        CP_WAIT(0);      // Xraw(tile) arrived

        // ---- msg prefetch for THIS tile (indices already resident) ----
#pragma unroll
        for (int it = 0; it < 8; it++) {
            int i = tg + 256 * it;            // 0..2047
            int r = (i >> 4) & 63, seg = i & 15, buf = i >> 10;
            int node = buf ? sDst[g][pb][r] : sSrc[g][pb][r];
            const unsigned char* srcp =
                (const unsigned char*)(buf ? g_msgh_dst : g_msgh_src) +
                (size_t)node * 256 + seg * 16;
            uint32_t dst = (buf ? Mdst : Msrc) + (uint32_t)r * 256 +
                           ((uint32_t)(seg ^ (r & 7)) << 4);
            CP16(dst, srcp);
        }
        CP_COMMIT();     // group: msg(tile)

        // ---- convert Xraw (fp32) -> X image (fp16, swizzled) in H region ---
#pragma unroll
        for (int it = 0; it < 2; it++) {
            int i = tg + 256 * it;            // 0..511
            int m = i >> 3, k4 = (i & 7) << 2;
            float4 v = *(const float4*)(XrawP + (uint32_t)m * 128 + k4 * 4);
            uint32_t hA = packh2(v.x, v.y), hB = packh2(v.z, v.w);
            uint32_t addr = (uint32_t)m * 128 + ((uint32_t)(((k4 >> 3) ^ (m & 7))) << 4) + (k4 & 7) * 2;
            STS64(Hsm + addr, hA, hB);
        }
        NBAR(GB, 256);   // X image ready; Xraw free for next prefetch

        // ---- prefetch next tile's Xraw (hidden under entire MLP) ----
        if (tn < numTiles) {
            int e0n = tn * 64;
#pragma unroll
            for (int it = 0; it < 2; it++) {
                int i = tg + 256 * it;
                int m = i >> 3, c = i & 7;
                int e = min(e0n + m, E - 1);
                CP16((uint32_t)(sb + goff) + (uint32_t)m * 128 + c * 16,
                     (const unsigned char*)edge_scalars + (size_t)e * 128 + c * 16);
            }
        }
        CP_COMMIT();     // group: pre(tn)   (possibly empty)

        // ---- layer1: H <- silu(X @ W1 + b1) [64x64, K=32] (in place) ----
        {
            const int nc = ni1 * 32;
            float acc[4][4];
#pragma unroll
            for (int i = 0; i < 4; i++)
#pragma unroll
                for (int j = 0; j < 4; j++) acc[i][j] = 0.0f;
#pragma unroll
            for (int ks = 0; ks < 2; ks++) {
                int m = mr + (mtx & 1) * 8 + rin;
                int kc = ks * 2 + (mtx >> 1);
                uint32_t aH[4];
                LDSM4(aH, Hsm + (uint32_t)m * 128 + ((uint32_t)(kc ^ (m & 7)) << 4));
                uint32_t bH[2][4];
#pragma unroll
                for (int ntp = 0; ntp < 2; ntp++) {
                    int k = ks * 16 + (mtx & 1) * 8 + rin;
                    int nch = (nc >> 3) + ntp * 2 + (mtx >> 1);
                    uint32_t boff = (uint32_t)k * 128 + ((uint32_t)(nch ^ (k & 7)) << 4);
                    LDSM4T(bH[ntp], W1hi + boff);
                }
#pragma unroll
                for (int nt = 0; nt < 4; nt++)
                    MMA16816(acc[nt], aH, bH[nt >> 1][(nt & 1) * 2], bH[nt >> 1][(nt & 1) * 2 + 1]);
            }
            // pair barrier: both N-warps done reading X rows before overwrite
            NBAR(PB, 64);
#pragma unroll
            for (int nt = 0; nt < 4; nt++) {
                int col = nc + nt * 8 + lc * 2;
                float s0 = silu(acc[nt][0] + sB1[col]);
                float s1 = silu(acc[nt][1] + sB1[col + 1]);
                float s2 = silu(acc[nt][2] + sB1[col]);
                float s3 = silu(acc[nt][3] + sB1[col + 1]);
                int r0 = mr + lr, r1 = r0 + 8;
                uint32_t ad0 = (uint32_t)r0 * 128 + ((uint32_t)((col >> 3) ^ (r0 & 7)) << 4) + (col & 7) * 2;
                STS32(Hsm + ad0, packh2(s0, s1));
                uint32_t ad1 = (uint32_t)r1 * 128 + ((uint32_t)((col >> 3) ^ (r1 & 7)) << 4) + (col & 7) * 2;
                STS32(Hsm + ad1, packh2(s2, s3));
            }
        }
        NBAR(GB, 256);

        // ---- layer2: H <- silu(H @ W2 + b2) [64x64, K=64] (in place) ----
        {
            const int nc = ni1 * 32;
            float acc[4][4];
#pragma unroll
            for (int i = 0; i < 4; i++)
#pragma unroll
                for (int j = 0; j < 4; j++) acc[i][j] = 0.0f;
#pragma unroll
            for (int ks = 0; ks < 4; ks++) {
                int m = mr + (mtx & 1) * 8 + rin;
                int kc = ks * 2 + (mtx >> 1);
                uint32_t aH[4];
                LDSM4(aH, Hsm + (uint32_t)m * 128 + ((uint32_t)(kc ^ (m & 7)) << 4));
                uint32_t bH[2][4];
#pragma unroll
                for (int ntp = 0; ntp < 2; ntp++) {
                    int k = ks * 16 + (mtx & 1) * 8 + rin;
                    int nch = (nc >> 3) + ntp * 2 + (mtx >> 1);
                    uint32_t boff = (uint32_t)k * 128 + ((uint32_t)(nch ^ (k & 7)) << 4);
                    LDSM4T(bH[ntp], W2hi + boff);
                }
#pragma unroll
                for (int nt = 0; nt < 4; nt++)
                    MMA16816(acc[nt], aH, bH[nt >> 1][(nt & 1) * 2], bH[nt >> 1][(nt & 1) * 2 + 1]);
            }
            NBAR(PB, 64);
#pragma unroll
            for (int nt = 0; nt < 4; nt++) {
                int col = nc + nt * 8 + lc * 2;
                float s0 = silu(acc[nt][0] + sB2[col]);
                float s1 = silu(acc[nt][1] + sB2[col + 1]);
                float s2 = silu(acc[nt][2] + sB2[col]);
                float s3 = silu(acc[nt][3] + sB2[col + 1]);
                int r0 = mr + lr, r1 = r0 + 8;
                uint32_t ad0 = (uint32_t)r0 * 128 + ((uint32_t)((col >> 3) ^ (r0 & 7)) << 4) + (col & 7) * 2;
                STS32(Hsm + ad0, packh2(s0, s1));
                uint32_t ad1 = (uint32_t)r1 * 128 + ((uint32_t)((col >> 3) ^ (r1 & 7)) << 4) + (col & 7) * 2;
                STS32(Hsm + ad1, packh2(s2, s3));
            }
        }
        NBAR(GB, 256);

        // ---- layer3: rad = H @ W3 + b3 [64x128, K=64] (regs) ----
        float acc3[8][4];
#pragma unroll
        for (int i = 0; i < 8; i++)
#pragma unroll
            for (int j = 0; j < 4; j++) acc3[i][j] = 0.0f;
        {
            const int nc = ni1 * 64;
#pragma unroll
            for (int ks = 0; ks < 4; ks++) {
                int m = mr + (mtx & 1) * 8 + rin;
                int kc = ks * 2 + (mtx >> 1);
                uint32_t aH[4];
                LDSM4(aH, Hsm + (uint32_t)m * 128 + ((uint32_t)(kc ^ (m & 7)) << 4));
                uint32_t bH[4][4];
#pragma unroll
                for (int ntp = 0; ntp < 4; ntp++) {
                    int k = ks * 16 + (mtx & 1) * 8 + rin;
                    int nch = (nc >> 3) + ntp * 2 + (mtx >> 1);
                    uint32_t boff = (uint32_t)k * 256 + ((uint32_t)(nch ^ (k & 7)) << 4);
                    LDSM4T(bH[ntp], W3hi + boff);
                }
#pragma unroll
                for (int nt = 0; nt < 8; nt++)
                    MMA16816(acc3[nt], aH, bH[nt >> 1][(nt & 1) * 2], bH[nt >> 1][(nt & 1) * 2 + 1]);
            }
        }
        CP_WAIT(1);       // msg(tile) done; pre(tn) may still be in flight
        NBAR(GB, 256);    // whole group's msg copies visible

        // ---- index prefetch for next tile (latency hidden by phase2) ----
        int rsN = 0, rdN = 0; float raN = 0.0f;
        if (tg < 64 && tn < numTiles) {
            int en = min(tn * 64 + tg, E - 1);
            rsN = edge_src[en];
            rdN = edge_dst[en];
            raN = (tn * 64 + tg < E) ? edge_attr[en] : 0.0f;
        }

        // ---- gather from SMEM + form A = (src+dst)*attr*rad (in place) ----
        {
            const int nc = ni1 * 64;
#pragma unroll
            for (int rh = 0; rh < 2; rh++) {
                int r = mr + rh * 8 + lr;
                float at = sAttr[g][pb][r];
#pragma unroll
                for (int nt = 0; nt < 8; nt++) {
                    int col = nc + nt * 8 + lc * 2;
                    uint32_t ad = (uint32_t)r * 256 + ((uint32_t)((col >> 3) ^ (r & 7)) << 4) + (col & 7) * 2;
                    uint32_t us, ud;
                    LDS32(us, Msrc + ad);
                    LDS32(ud, Mdst + ad);
                    float2 ms = __half22float2(*(__half2*)&us);
                    float2 md = __half22float2(*(__half2*)&ud);
                    float rad0 = acc3[nt][rh * 2 + 0] + sB3[col];
                    float rad1 = acc3[nt][rh * 2 + 1] + sB3[col + 1];
                    float m0 = (ms.x + md.x) * at * rad0;
                    float m1 = (ms.y + md.y) * at * rad1;
                    STS32(Asm + ad, packh2(m0, m1));
                }
            }
        }
        NBAR(GB, 256);

        // ---- phase2: D[64,256] = A @ B + epilogue ----
        float d[2][8][4];
#pragma unroll
        for (int a = 0; a < 2; a++)
#pragma unroll
            for (int b = 0; b < 8; b++)
#pragma unroll
                for (int c = 0; c < 4; c++) d[a][b][c] = 0.0f;

#pragma unroll
        for (int ks = 0; ks < 8; ks++) {
            uint32_t ah[2][4];
#pragma unroll
            for (int mt = 0; mt < 2; mt++) {
                int m = mrow0 + mt * 16 + (mtx & 1) * 8 + rin;
                int kchunk = ks * 2 + (mtx >> 1);
                LDSM4(ah[mt], Asm + (uint32_t)m * 256 + ((uint32_t)(kchunk ^ (m & 7)) << 4));
            }
            uint32_t b[4][4];
#pragma unroll
            for (int ntp = 0; ntp < 4; ntp++) {
                int k = ks * 16 + (mtx & 1) * 8 + rin;
                int nchunk = (ncol0 >> 3) + ntp * 2 + (mtx >> 1);
                LDSM4T(b[ntp], Bsm + (uint32_t)k * 512 + ((uint32_t)(nchunk ^ (k & 7)) << 4));
            }
#pragma unroll
            for (int mt = 0; mt < 2; mt++)
#pragma unroll
                for (int nt = 0; nt < 8; nt++)
                    MMA16816(d[mt][nt], ah[mt], b[nt >> 1][(nt & 1) * 2], b[nt >> 1][(nt & 1) * 2 + 1]);
        }

        // ---- epilogue: w = exp(score); direct segment reduction ----
#pragma unroll
        for (int hh = 0; hh < 2; hh++) {
            const int h = ni * 2 + hh;
#pragma unroll
            for (int mt = 0; mt < 2; mt++) {
                const int r0i = mrow0 + mt * 16 + lr;
                const int e0i = e0 + r0i;
                float p0 = 0.0f, p1 = 0.0f;
#pragma unroll
                for (int q = 0; q < 2; q++) {
                    const int nt = hh * 4 + q;
                    const int colb = ncol0 + nt * 8 + lc * 2;
                    const int jb = q * 8 + lc * 2;
                    const float bb0 = sBsep[colb], bb1 = sBsep[colb + 1];
                    const float w0 = sAD[h * 16 + jb], w1 = sAD[h * 16 + jb + 1];
                    float x, sg;
                    x = d[mt][nt][0] + bb0; sg = 1.0f / (1.0f + __expf(-x)); p0 += x * (0.2f + 0.8f * sg) * w0;
                    x = d[mt][nt][1] + bb1; sg = 1.0f / (1.0f + __expf(-x)); p0 += x * (0.2f + 0.8f * sg) * w1;
                    x = d[mt][nt][2] + bb0; sg = 1.0f / (1.0f + __expf(-x)); p1 += x * (0.2f + 0.8f * sg) * w0;
                    x = d[mt][nt][3] + bb1; sg = 1.0f / (1.0f + __expf(-x)); p1 += x * (0.2f + 0.8f * sg) * w1;
                }
                p0 += __shfl_xor_sync(0xffffffffu, p0, 1);
                p0 += __shfl_xor_sync(0xffffffffu, p0, 2);
                p1 += __shfl_xor_sync(0xffffffffu, p1, 1);
                p1 += __shfl_xor_sync(0xffffffffu, p1, 2);
                const float ew0 = __expf(p0), ew1 = __expf(p1);
                const int d0 = sDst[g][pb][r0i], d1 = sDst[g][pb][r0i + 8];
                if (lc == 0) {
                    if (e0i < E)     atomicAdd(&g_nsum[(size_t)d0 * 8 + h], ew0);
                    if (e0i + 8 < E) atomicAdd(&g_nsum[(size_t)d1 * 8 + h], ew1);
                }
#pragma unroll
                for (int q = 0; q < 2; q++) {
                    const int nt = hh * 4 + 2 + q;
                    const int colb = ncol0 + nt * 8 + lc * 2;
                    const int vidx = q * 8 + lc * 2;
                    const float bb0 = sBsep[colb], bb1 = sBsep[colb + 1];
                    if (e0i < E)
                        RED2(g_nacc + (size_t)d0 * 128 + h * 16 + vidx,
                             (d[mt][nt][0] + bb0) * ew0, (d[mt][nt][1] + bb1) * ew0);
                    if (e0i + 8 < E)
                        RED2(g_nacc + (size_t)d1 * 128 + h * 16 + vidx,
                             (d[mt][nt][2] + bb0) * ew1, (d[mt][nt][3] + bb1) * ew1);
                }
            }
        }

        // ---- publish prefetched indices for next tile ----
        if (tg < 64 && tn < numTiles) {
            sSrc[g][pb ^ 1][tg] = rsN;
            sDst[g][pb ^ 1][tg] = rdN;
            sAttr[g][pb ^ 1][tg] = raN;
        }
        pb ^= 1;
        tile = tn;
    }
}

// ---------------- K5: out GEMM on HMMA ---------------------------------------
__global__ __launch_bounds__(512, 1) void out_mma_kernel(
    const float* __restrict__ bias, float* __restrict__ out, int n)
{
    extern __shared__ char dynsm[];
    __shared__ float sBias[128];
    const int tid = threadIdx.x;
    const int wid = tid >> 5, lane = tid & 31;
    const int mtx = lane >> 3, rin = lane & 7;
    const int lr = lane >> 2, lc = lane & 3;
    const int r0 = blockIdx.x * 128;

    const uint32_t sb = smem_u32(dynsm);
    const uint32_t Ahi = sb, Alo = sb + 32768, Bsm = sb + 65536;

#pragma unroll
    for (int it = 0; it < 4; it++) {
        int i = tid + 512 * it;
        CP16(Bsm + i * 16, g_PImg + i * 16);
    }
    CP_COMMIT();
    if (tid < 128) sBias[tid] = bias[tid];

#pragma unroll
    for (int it = 0; it < 8; it++) {
        int i = tid + 512 * it;
        int m = i >> 5, k4 = (i & 31) << 2;
        int gr = r0 + m;
        float4 v = make_float4(0.f, 0.f, 0.f, 0.f);
        if (gr < n) {
            v = *(const float4*)(g_nacc + (size_t)gr * 128 + k4);
            float inv = 1.0f / (g_nsum[(size_t)gr * 8 + (k4 >> 4)] + 1e-16f);
            v.x *= inv; v.y *= inv; v.z *= inv; v.w *= inv;
        }
        uint32_t hA, hB, lA, lB; split4(v, hA, hB, lA, lB);
        uint32_t addr = (uint32_t)m * 256 + ((uint32_t)((k4 >> 3) ^ (m & 7)) << 4) + (k4 & 7) * 2;
        STS64(Ahi + addr, hA, hB);
        STS64(Alo + addr, lA, lB);
    }
    CP_WAIT(0);
    __syncthreads();

    const int mi = wid & 3, ni = wid >> 2;
    const int mrow0 = mi * 32, ncol0 = ni * 32;

    float d[2][4][4];
#pragma unroll
    for (int a = 0; a < 2; a++)
#pragma unroll
        for (int b = 0; b < 4; b++)
#pragma unroll
            for (int c = 0; c < 4; c++) d[a][b][c] = 0.0f;

#pragma unroll
    for (int ks = 0; ks < 8; ks++) {
        uint32_t ah[2][4], al[2][4];
#pragma unroll
        for (int mt = 0; mt < 2; mt++) {
            int m = mrow0 + mt * 16 + (mtx & 1) * 8 + rin;
            int kchunk = ks * 2 + (mtx >> 1);
            uint32_t ao = (uint32_t)m * 256 + ((uint32_t)(kchunk ^ (m & 7)) << 4);
            LDSM4(ah[mt], Ahi + ao);
            LDSM4(al[mt], Alo + ao);
        }
        uint32_t b[2][4];
#pragma unroll
        for (int ntp = 0; ntp < 2; ntp++) {
            int k = ks * 16 + (mtx & 1) * 8 + rin;
            int nchunk = (ncol0 >> 3) + ntp * 2 + (mtx >> 1);
            LDSM4T(b[ntp], Bsm + (uint32_t)k * 256 + ((uint32_t)(nchunk ^ (k & 7)) << 4));
        }
#pragma unroll
        for (int mt = 0; mt < 2; mt++)
#pragma unroll
            for (int nt = 0; nt < 4; nt++) {
                MMA16816(d[mt][nt], ah[mt], b[nt >> 1][(nt & 1) * 2], b[nt >> 1][(nt & 1) * 2 + 1]);
                MMA16816(d[mt][nt], al[mt], b[nt >> 1][(nt & 1) * 2], b[nt >> 1][(nt & 1) * 2 + 1]);
            }
    }

#pragma unroll
    for (int mt = 0; mt < 2; mt++) {
        int gr0 = r0 + mrow0 + mt * 16 + lr;
        int gr1 = gr0 + 8;
#pragma unroll
        for (int nt = 0; nt < 4; nt++) {
            int c = ncol0 + nt * 8 + lc * 2;
            float bb0 = sBias[c], bb1 = sBias[c + 1];
            if (gr0 < n)
                *(float2*)(out + (size_t)gr0 * 128 + c) =
                    make_float2(d[mt][nt][0] + bb0, d[mt][nt][1] + bb1);
            if (gr1 < n)
                *(float2*)(out + (size_t)gr1 * 128 + c) =
                    make_float2(d[mt][nt][2] + bb0, d[mt][nt][3] + bb1);
        }
    }
}

// ---------------- launch ----------------
extern "C" void kernel_launch(void* const* d_in, const int* in_sizes, int n_in,
                              void* d_out, int out_size)
{
    const float* node_input = (const float*)d_in[0];
    const float* edge_attr  = (const float*)d_in[2];
    const float* edge_scal  = (const float*)d_in[3];
    const int*   edge_src   = (const int*)d_in[4];
    const int*   edge_dst   = (const int*)d_in[5];
    const float* w_src      = (const float*)d_in[7];
    const float* b_src      = (const float*)d_in[8];
    const float* w_dst      = (const float*)d_in[9];
    const float* fc_w1      = (const float*)d_in[10];
    const float* fc_b1      = (const float*)d_in[11];
    const float* fc_w2      = (const float*)d_in[12];
    const float* fc_b2      = (const float*)d_in[13];
    const float* fc_w3      = (const float*)d_in[14];
    const float* fc_b3      = (const float*)d_in[15];
    const float* w_sep      = (const float*)d_in[16];
    const float* b_sep      = (const float*)d_in[17];
    const float* alpha_dot  = (const float*)d_in[18];
    const float* w_proj     = (const float*)d_in[19];
    const float* b_proj     = (const float*)d_in[20];
    float* out = (float*)d_out;

    int N = in_sizes[0] / 128;
    int E = in_sizes[4];

    cudaFuncSetAttribute(fused_edge_kernel, cudaFuncAttributeMaxDynamicSharedMemorySize, 221184);
    cudaFuncSetAttribute(node_mma_kernel,   cudaFuncAttributeMaxDynamicSharedMemorySize, 131072);
    cudaFuncSetAttribute(out_mma_kernel,    cudaFuncAttributeMaxDynamicSharedMemorySize, 98304);

    static int sms = 0;
    if (sms == 0) {
        cudaDeviceGetAttribute(&sms, cudaDevAttrMultiProcessorCount, 0);
        if (sms <= 0) sms = 148;
    }

    init_kernel<<<(N * 128 + 255) / 256, 256>>>(N);
    prep_kernel<<<94, 256>>>(fc_w1, fc_w2, fc_w3, w_sep, w_src, w_dst, w_proj);

    int nt = (N + 127) / 128;
    node_mma_kernel<<<nt, 512, 131072>>>(node_input, b_src, N);

    int numTiles = (E + 63) / 64;               // 64-edge tiles
    int nblk = (numTiles + 1) / 2;
    if (nblk > sms) nblk = sms;
    fused_edge_kernel<<<nblk, 512, 221184>>>(edge_scal, edge_attr, edge_src, edge_dst,
                                             fc_b1, fc_b2, fc_b3,
                                             b_sep, alpha_dot, E, numTiles);

    out_mma_kernel<<<nt, 512, 98304>>>(b_proj, out, N);
}

// round 17
// speedup vs baseline: 1.7256x; 1.0179x over previous
#include <cuda_runtime.h>
#include <cuda_fp16.h>
#include <cstdint>
#include <math.h>

// ---------------- fixed problem geometry ----------------
#define MAXN 50000
#define MAXE 800000
// C=128, A_ALL=256, RAD_IN=32, FC1=FC2=64, H=8, AH=VH=16

// ---------------- scratch ----------------
__device__ __align__(16) __half g_msgh_src[(size_t)MAXN * 128];   // LINEAR rows
__device__ __align__(16) __half g_msgh_dst[(size_t)MAXN * 128];   // LINEAR rows
__device__ __align__(16) float g_nsum[(size_t)MAXN * 8];
__device__ __align__(16) float g_nacc[(size_t)MAXN * 128];
// prepacked fp16 weight images (exact SMEM layouts, swizzled)
__device__ __align__(16) unsigned char g_Bimg[65536];    // w_sep [k][n] 256n
__device__ __align__(16) unsigned char g_W1img[4096];    // hi only
__device__ __align__(16) unsigned char g_W2img[8192];    // hi only
__device__ __align__(16) unsigned char g_W3img[16384];   // hi only
__device__ __align__(16) unsigned char g_BnodeImg[65536];// [w_src|w_dst] [k][256n]
__device__ __align__(16) unsigned char g_PImg[32768];    // w_proj [k][128n]

// ---------------- helpers ----------------
__device__ __forceinline__ uint32_t smem_u32(const void* p) {
    uint32_t a;
    asm("{ .reg .u64 t; cvta.to.shared.u64 t, %1; cvt.u32.u64 %0, t; }"
        : "=r"(a) : "l"(p));
    return a;
}

#define LDSM4(r, addr) \
    asm volatile("ldmatrix.sync.aligned.m8n8.x4.shared.b16 {%0,%1,%2,%3}, [%4];" \
        : "=r"((r)[0]), "=r"((r)[1]), "=r"((r)[2]), "=r"((r)[3]) : "r"(addr))

#define LDSM4T(r, addr) \
    asm volatile("ldmatrix.sync.aligned.m8n8.x4.trans.shared.b16 {%0,%1,%2,%3}, [%4];" \
        : "=r"((r)[0]), "=r"((r)[1]), "=r"((r)[2]), "=r"((r)[3]) : "r"(addr))

#define MMA16816(d, a, b0v, b1v) \
    asm volatile("mma.sync.aligned.m16n8k16.row.col.f32.f16.f16.f32 " \
        "{%0,%1,%2,%3}, {%4,%5,%6,%7}, {%8,%9}, {%0,%1,%2,%3};" \
        : "+f"((d)[0]), "+f"((d)[1]), "+f"((d)[2]), "+f"((d)[3]) \
        : "r"((a)[0]), "r"((a)[1]), "r"((a)[2]), "r"((a)[3]), "r"(b0v), "r"(b1v))

#define STS32(addr, v) \
    asm volatile("st.shared.b32 [%0], %1;" :: "r"(addr), "r"(v))
#define STS64(addr, v0, v1) \
    asm volatile("st.shared.v2.b32 [%0], {%1,%2};" :: "r"(addr), "r"(v0), "r"(v1))
#define LDS32(v, addr) \
    asm volatile("ld.shared.b32 %0, [%1];" : "=r"(v) : "r"(addr))

// async 16B global->shared copy (sm_80+)
#define CP16(dst, src) \
    asm volatile("{ .reg .u64 g; cvta.to.global.u64 g, %1; " \
                 "cp.async.cg.shared.global [%0], [g], 16; }" \
                 :: "r"(dst), "l"(src) : "memory")
#define CP_COMMIT() asm volatile("cp.async.commit_group;" ::: "memory")
#define CP_WAIT(n)  asm volatile("cp.async.wait_group %0;" :: "n"(n) : "memory")

// vector fire-and-forget global reduction (sm_90+)
#define RED2(ptr, x, y) \
    asm volatile("red.global.add.v2.f32 [%0], {%1,%2};" :: "l"(ptr), "f"(x), "f"(y) : "memory")

// named barrier
#define NBAR(id, cnt) \
    asm volatile("bar.sync %0, %1;" :: "r"(id), "r"(cnt) : "memory")

__device__ __forceinline__ uint32_t packh2(float x, float y) {
    __half2 t = __floats2half2_rn(x, y);
    return *(uint32_t*)&t;
}
__device__ __forceinline__ void split2(float x, float y, uint32_t& hi, uint32_t& lo) {
    __half h0 = __float2half_rn(x), h1 = __float2half_rn(y);
    __half2 hh = __halves2half2(h0, h1);
    hi = *(uint32_t*)&hh;
    lo = packh2(x - __half2float(h0), y - __half2float(h1));
}
__device__ __forceinline__ void split4(float4 v, uint32_t& hA, uint32_t& hB,
                                       uint32_t& lA, uint32_t& lB) {
    split2(v.x, v.y, hA, lA);
    split2(v.z, v.w, hB, lB);
}
__device__ __forceinline__ float silu(float x) {
    return x / (1.0f + __expf(-x));
}

// ---------------- K0: init segment buffers ----------------
__global__ void init_kernel(int n) {
    int i = blockIdx.x * blockDim.x + threadIdx.x;
    if (i < n * 128) g_nacc[i] = 0.0f;
    if (i < n * 8) g_nsum[i] = 0.0f;
}

// ---------------- K0b: prepack weight images (fp16, swizzled SMEM layout) --
__global__ void prep_kernel(const float* __restrict__ w1, const float* __restrict__ w2,
                            const float* __restrict__ w3, const float* __restrict__ w_sep,
                            const float* __restrict__ w_src, const float* __restrict__ w_dst,
                            const float* __restrict__ w_proj)
{
    int idx = blockIdx.x * blockDim.x + threadIdx.x;  // float4 units
    if (idx < 8192) {                       // w_sep: 128 x 256, rows 512B
        int k = idx >> 6, n4 = (idx & 63) << 2;
        float4 v = *(const float4*)(w_sep + (size_t)k * 256 + n4);
        uint32_t hA = packh2(v.x, v.y), hB = packh2(v.z, v.w);
        uint32_t addr = (uint32_t)k * 512 + ((uint32_t)((n4 >> 3) ^ (k & 7)) << 4) + (n4 & 7) * 2;
        *(uint2*)(g_Bimg + addr) = make_uint2(hA, hB);
    } else if (idx < 8704) {                // w1: 32 x 64, rows 128B (hi only)
        int i = idx - 8192;
        int k = i >> 4, n4 = (i & 15) << 2;
        float4 v = *(const float4*)(w1 + (size_t)k * 64 + n4);
        uint32_t hA = packh2(v.x, v.y), hB = packh2(v.z, v.w);
        uint32_t addr = (uint32_t)k * 128 + ((uint32_t)((n4 >> 3) ^ (k & 7)) << 4) + (n4 & 7) * 2;
        *(uint2*)(g_W1img + addr) = make_uint2(hA, hB);
    } else if (idx < 9728) {                // w2: 64 x 64, rows 128B (hi only)
        int i = idx - 8704;
        int k = i >> 4, n4 = (i & 15) << 2;
        float4 v = *(const float4*)(w2 + (size_t)k * 64 + n4);
        uint32_t hA = packh2(v.x, v.y), hB = packh2(v.z, v.w);
        uint32_t addr = (uint32_t)k * 128 + ((uint32_t)((n4 >> 3) ^ (k & 7)) << 4) + (n4 & 7) * 2;
        *(uint2*)(g_W2img + addr) = make_uint2(hA, hB);
    } else if (idx < 11776) {               // w3: 64 x 128, rows 256B (hi only)
        int i = idx - 9728;
        int k = i >> 5, n4 = (i & 31) << 2;
        float4 v = *(const float4*)(w3 + (size_t)k * 128 + n4);
        uint32_t hA = packh2(v.x, v.y), hB = packh2(v.z, v.w);
        uint32_t addr = (uint32_t)k * 256 + ((uint32_t)((n4 >> 3) ^ (k & 7)) << 4) + (n4 & 7) * 2;
        *(uint2*)(g_W3img + addr) = make_uint2(hA, hB);
    } else if (idx < 19968) {               // Bnode = [w_src|w_dst]: 128 x 256, rows 512B
        int i = idx - 11776;
        int k = i >> 6, n4 = (i & 63) << 2;
        float4 v = (n4 < 128)
            ? *(const float4*)(w_src + (size_t)k * 128 + n4)
            : *(const float4*)(w_dst + (size_t)k * 128 + (n4 - 128));
        uint32_t hA = packh2(v.x, v.y), hB = packh2(v.z, v.w);
        uint32_t addr = (uint32_t)k * 512 + ((uint32_t)((n4 >> 3) ^ (k & 7)) << 4) + (n4 & 7) * 2;
        *(uint2*)(g_BnodeImg + addr) = make_uint2(hA, hB);
    } else if (idx < 24064) {               // w_proj: 128 x 128, rows 256B
        int i = idx - 19968;
        int k = i >> 5, n4 = (i & 31) << 2;
        float4 v = *(const float4*)(w_proj + (size_t)k * 128 + n4);
        uint32_t hA = packh2(v.x, v.y), hB = packh2(v.z, v.w);
        uint32_t addr = (uint32_t)k * 256 + ((uint32_t)((n4 >> 3) ^ (k & 7)) << 4) + (n4 & 7) * 2;
        *(uint2*)(g_PImg + addr) = make_uint2(hA, hB);
    }
}

// ---------------- K1: node GEMM on HMMA -> fp16 msg arrays (LINEAR rows) ----
__global__ __launch_bounds__(512, 1) void node_mma_kernel(
    const float* __restrict__ X, const float* __restrict__ bias_src, int n)
{
    extern __shared__ char dynsm[];
    __shared__ float sBias[128];
    const int tid = threadIdx.x;
    const int wid = tid >> 5, lane = tid & 31;
    const int mtx = lane >> 3, rin = lane & 7;
    const int lr = lane >> 2, lc = lane & 3;
    const int r0 = blockIdx.x * 128;

    const uint32_t sb = smem_u32(dynsm);
    const uint32_t Ahi = sb, Alo = sb + 32768, Bsm = sb + 65536;

#pragma unroll
    for (int it = 0; it < 8; it++) {
        int i = tid + 512 * it;
        CP16(Bsm + i * 16, g_BnodeImg + i * 16);
    }
    CP_COMMIT();
    if (tid < 128) sBias[tid] = bias_src[tid];

#pragma unroll
    for (int it = 0; it < 8; it++) {
        int i = tid + 512 * it;
        int m = i >> 5, k4 = (i & 31) << 2;
        int gr = r0 + m;
        float4 v = make_float4(0.f, 0.f, 0.f, 0.f);
        if (gr < n) v = *(const float4*)(X + (size_t)gr * 128 + k4);
        uint32_t hA, hB, lA, lB; split4(v, hA, hB, lA, lB);
        uint32_t addr = (uint32_t)m * 256 + ((uint32_t)((k4 >> 3) ^ (m & 7)) << 4) + (k4 & 7) * 2;
        STS64(Ahi + addr, hA, hB);
        STS64(Alo + addr, lA, lB);
    }
    CP_WAIT(0);
    __syncthreads();

    const int mi = wid & 3, ni = wid >> 2;
    const int mrow0 = mi * 32, ncol0 = ni * 64;

    float d[2][8][4];
#pragma unroll
    for (int a = 0; a < 2; a++)
#pragma unroll
        for (int b = 0; b < 8; b++)
#pragma unroll
            for (int c = 0; c < 4; c++) d[a][b][c] = 0.0f;

#pragma unroll
    for (int ks = 0; ks < 8; ks++) {
        uint32_t ah[2][4], al[2][4];
#pragma unroll
        for (int mt = 0; mt < 2; mt++) {
            int m = mrow0 + mt * 16 + (mtx & 1) * 8 + rin;
            int kchunk = ks * 2 + (mtx >> 1);
            uint32_t ao = (uint32_t)m * 256 + ((uint32_t)(kchunk ^ (m & 7)) << 4);
            LDSM4(ah[mt], Ahi + ao);
            LDSM4(al[mt], Alo + ao);
        }
        uint32_t b[4][4];
#pragma unroll
        for (int ntp = 0; ntp < 4; ntp++) {
            int k = ks * 16 + (mtx & 1) * 8 + rin;
            int nchunk = (ncol0 >> 3) + ntp * 2 + (mtx >> 1);
            LDSM4T(b[ntp], Bsm + (uint32_t)k * 512 + ((uint32_t)(nchunk ^ (k & 7)) << 4));
        }
#pragma unroll
        for (int mt = 0; mt < 2; mt++)
#pragma unroll
            for (int nt = 0; nt < 8; nt++) {
                MMA16816(d[mt][nt], ah[mt], b[nt >> 1][(nt & 1) * 2], b[nt >> 1][(nt & 1) * 2 + 1]);
                MMA16816(d[mt][nt], al[mt], b[nt >> 1][(nt & 1) * 2], b[nt >> 1][(nt & 1) * 2 + 1]);
            }
    }

#pragma unroll
    for (int mt = 0; mt < 2; mt++) {
        int gr0 = r0 + mrow0 + mt * 16 + lr;
        int gr1 = gr0 + 8;
#pragma unroll
        for (int nt = 0; nt < 8; nt++) {
            int cg = ncol0 + nt * 8 + lc * 2;
            float bb0 = 0.0f, bb1 = 0.0f;
            unsigned char* buf;
            int c;
            if (cg < 128) { buf = (unsigned char*)g_msgh_src; c = cg; bb0 = sBias[c]; bb1 = sBias[c + 1]; }
            else          { buf = (unsigned char*)g_msgh_dst; c = cg - 128; }
            if (gr0 < n)
                *(uint32_t*)(buf + (size_t)gr0 * 256 + c * 2) =
                    packh2(d[mt][nt][0] + bb0, d[mt][nt][1] + bb1);
            if (gr1 < n)
                *(uint32_t*)(buf + (size_t)gr1 * 256 + c * 2) =
                    packh2(d[mt][nt][2] + bb0, d[mt][nt][3] + bb1);
        }
    }
}

// ============================================================================
// K23: PERSISTENT fused kernel, TWO warp groups of 8, 64-edge tiles.
// Pair-scoped MLP: H rows are private to warp pair {mi1, mi1+4}; all MLP
// barriers are 64-thread. Xraw prefetch/convert is thread-private.
//
// Dynamic SMEM (221184 B):
//  [0,8K) W1 | [8K,24K) W2 | [24K,56K) W3 | [56K,120K) B
//  group g at 120K + g*48K: Xraw(8K) H(8K, doubles as X image) Msrc(16K,=A) Mdst(16K)
// ============================================================================
__global__ __launch_bounds__(512, 1) void fused_edge_kernel(
    const float* __restrict__ edge_scalars, const float* __restrict__ edge_attr,
    const int* __restrict__ edge_src, const int* __restrict__ edge_dst,
    const float* __restrict__ b1, const float* __restrict__ b2,
    const float* __restrict__ b3, const float* __restrict__ b_sep,
    const float* __restrict__ alpha_dot, int E, int numTiles)
{
    extern __shared__ char dynsm[];
    __shared__ float sB1[64], sB2[64], sB3[128];
    __shared__ float sBsep[256], sAD[128];
    __shared__ int   sSrc[2][2][64], sDst[2][2][64];
    __shared__ float sAttr[2][2][64];

    const int tid = threadIdx.x;
    const int lane = tid & 31;
    const int g = tid >> 8;            // warp group 0/1
    const int tg = tid & 255;          // tid within group
    const int wg = (tid >> 5) & 7;     // warp within group
    const int mtx = lane >> 3, rin = lane & 7;
    const int lr = lane >> 2, lc = lane & 3;

    const uint32_t sb = smem_u32(dynsm);
    const uint32_t W1hi = sb;
    const uint32_t W2hi = sb + 8192;
    const uint32_t W3hi = sb + 24576;
    const uint32_t Bsm  = sb + 57344;
    const uint32_t goff = 122880 + (uint32_t)g * 49152;
    char* const XrawP   = dynsm + goff;              // 8KB raw fp32 (64 x 128B)
    const uint32_t Xraw = sb + goff;
    const uint32_t Hsm  = sb + goff + 8192;          // X image + H (in place)
    const uint32_t Msrc = sb + goff + 16384;
    const uint32_t Mdst = sb + goff + 32768;
    const uint32_t Asm  = Msrc;

    // ---------------- one-time weight staging (hi-only) ----------------
    if (tid < 256) CP16(W1hi + tid * 16, g_W1img + tid * 16);        // 4KB
    if (tid < 512) CP16(W2hi + tid * 16, g_W2img + tid * 16);        // 8KB
#pragma unroll
    for (int it = 0; it < 2; it++) {                                 // 16KB
        int i = tid + 512 * it;
        if (i < 1024) CP16(W3hi + i * 16, g_W3img + i * 16);
    }
#pragma unroll
    for (int it = 0; it < 8; it++) {                                 // 64KB
        int i = tid + 512 * it;
        CP16(Bsm + i * 16, g_Bimg + i * 16);
    }
    CP_COMMIT();
    if (tid < 64)  { sB1[tid] = b1[tid]; sB2[tid] = b2[tid]; }
    if (tid < 128) { sB3[tid] = b3[tid]; sAD[tid] = alpha_dot[tid]; }
    if (tid < 256) sBsep[tid] = b_sep[tid];
    CP_WAIT(0);
    __syncthreads();

    // MLP warp tiling within group: 4 M-tiles x 2 N-tiles (M=64)
    const int mi1 = wg & 3, ni1 = wg >> 2;
    const int mr = mi1 * 16;
    // pair-lane id (0..63) across pair {mi1, mi1+4}
    const int pl = ni1 * 32 + lane;
    // phase2 warp tiling within group: 2 M-tiles x 4 N-tiles
    const int mi = wg & 1, ni = wg >> 1;
    const int mrow0 = mi * 32, ncol0 = ni * 64;

    const int GB = 1 + g;              // group barrier id
    const int PB = 4 + g * 4 + mi1;    // pair barrier id
    const int stride = gridDim.x * 2;

    // ---------------- prefill: tile0 indices (LDG) + Xraw (pair rows) -------
    int tile = blockIdx.x * 2 + g;
    int pb = 0;
    if (tile < numTiles) {
        int e0p = tile * 64;
        if (tg < 64) {
            int e = min(e0p + tg, E - 1);
            sSrc[g][0][tg] = edge_src[e];
            sDst[g][0][tg] = edge_dst[e];
            sAttr[g][0][tg] = (e0p + tg < E) ? edge_attr[e] : 0.0f;
        }
#pragma unroll
        for (int it = 0; it < 2; it++) {
            int i = pl + 64 * it;             // 0..127 within pair
            int m = mr + (i >> 3), c = i & 7;
            int e = min(e0p + m, E - 1);
            CP16(Xraw + (uint32_t)m * 128 + c * 16,
                 (const unsigned char*)edge_scalars + (size_t)e * 128 + c * 16);
        }
    }
    CP_COMMIT();     // Xraw(tile0)

    // =================== persistent tile loop (64-edge tiles) ===============
    while (tile < numTiles) {
        const int e0 = tile * 64;
        const int tn = tile + stride;

        NBAR(GB, 256);   // prev tile fully done with group buffers; idx[pb] ready
        CP_WAIT(0);      // Xraw(tile) arrived (thread-private chunks)

        // ---- msg prefetch for THIS tile (indices already resident) ----
#pragma unroll
        for (int it = 0; it < 8; it++) {
            int i = tg + 256 * it;            // 0..2047
            int r = (i >> 4) & 63, seg = i & 15, buf = i >> 10;
            int node = buf ? sDst[g][pb][r] : sSrc[g][pb][r];
            const unsigned char* srcp =
                (const unsigned char*)(buf ? g_msgh_dst : g_msgh_src) +
                (size_t)node * 256 + seg * 16;
            uint32_t dst = (buf ? Mdst : Msrc) + (uint32_t)r * 256 +
                           ((uint32_t)(seg ^ (r & 7)) << 4);
            CP16(dst, srcp);
        }
        CP_COMMIT();     // msg(tile)

        // ---- convert own Xraw chunks (fp32) -> X image (fp16) in H region --
#pragma unroll
        for (int it = 0; it < 2; it++) {
            int i = pl + 64 * it;             // same mapping as the cp.async
            int m = mr + (i >> 3), k4 = (i & 7) << 2;
            float4 v = *(const float4*)(XrawP + (uint32_t)m * 128 + k4 * 4);
            uint32_t hA = packh2(v.x, v.y), hB = packh2(v.z, v.w);
            uint32_t addr = (uint32_t)m * 128 + ((uint32_t)(((k4 >> 3) ^ (m & 7))) << 4) + (k4 & 7) * 2;
            STS64(Hsm + addr, hA, hB);
        }
        // ---- prefetch next tile's Xraw (pair rows; reads done above) ----
        if (tn < numTiles) {
            int e0n = tn * 64;
#pragma unroll
            for (int it = 0; it < 2; it++) {
                int i = pl + 64 * it;
                int m = mr + (i >> 3), c = i & 7;
                int e = min(e0n + m, E - 1);
                CP16(Xraw + (uint32_t)m * 128 + c * 16,
                     (const unsigned char*)edge_scalars + (size_t)e * 128 + c * 16);
            }
        }
        CP_COMMIT();     // Xraw(tn)   (possibly empty)

        NBAR(PB, 64);    // X image visible to pair

        // ---- layer1: H <- silu(X @ W1 + b1) [64x64, K=32] (in place) ----
        {
            const int nc = ni1 * 32;
            float acc[4][4];
#pragma unroll
            for (int i = 0; i < 4; i++)
#pragma unroll
                for (int j = 0; j < 4; j++) acc[i][j] = 0.0f;
#pragma unroll
            for (int ks = 0; ks < 2; ks++) {
                int m = mr + (mtx & 1) * 8 + rin;
                int kc = ks * 2 + (mtx >> 1);
                uint32_t aH[4];
                LDSM4(aH, Hsm + (uint32_t)m * 128 + ((uint32_t)(kc ^ (m & 7)) << 4));
                uint32_t bH[2][4];
#pragma unroll
                for (int ntp = 0; ntp < 2; ntp++) {
                    int k = ks * 16 + (mtx & 1) * 8 + rin;
                    int nch = (nc >> 3) + ntp * 2 + (mtx >> 1);
                    uint32_t boff = (uint32_t)k * 128 + ((uint32_t)(nch ^ (k & 7)) << 4);
                    LDSM4T(bH[ntp], W1hi + boff);
                }
#pragma unroll
                for (int nt = 0; nt < 4; nt++)
                    MMA16816(acc[nt], aH, bH[nt >> 1][(nt & 1) * 2], bH[nt >> 1][(nt & 1) * 2 + 1]);
            }
            NBAR(PB, 64);    // pair done reading X rows before overwrite
#pragma unroll
            for (int nt = 0; nt < 4; nt++) {
                int col = nc + nt * 8 + lc * 2;
                float s0 = silu(acc[nt][0] + sB1[col]);
                float s1 = silu(acc[nt][1] + sB1[col + 1]);
                float s2 = silu(acc[nt][2] + sB1[col]);
                float s3 = silu(acc[nt][3] + sB1[col + 1]);
                int r0 = mr + lr, r1 = r0 + 8;
                uint32_t ad0 = (uint32_t)r0 * 128 + ((uint32_t)((col >> 3) ^ (r0 & 7)) << 4) + (col & 7) * 2;
                STS32(Hsm + ad0, packh2(s0, s1));
                uint32_t ad1 = (uint32_t)r1 * 128 + ((uint32_t)((col >> 3) ^ (r1 & 7)) << 4) + (col & 7) * 2;
                STS32(Hsm + ad1, packh2(s2, s3));
            }
        }
        NBAR(PB, 64);        // H1 visible to pair

        // ---- layer2: H <- silu(H @ W2 + b2) [64x64, K=64] (in place) ----
        {
            const int nc = ni1 * 32;
            float acc[4][4];
#pragma unroll
            for (int i = 0; i < 4; i++)
#pragma unroll
                for (int j = 0; j < 4; j++) acc[i][j] = 0.0f;
#pragma unroll
            for (int ks = 0; ks < 4; ks++) {
                int m = mr + (mtx & 1) * 8 + rin;
                int kc = ks * 2 + (mtx >> 1);
                uint32_t aH[4];
                LDSM4(aH, Hsm + (uint32_t)m * 128 + ((uint32_t)(kc ^ (m & 7)) << 4));
                uint32_t bH[2][4];
#pragma unroll
                for (int ntp = 0; ntp < 2; ntp++) {
                    int k = ks * 16 + (mtx & 1) * 8 + rin;
                    int nch = (nc >> 3) + ntp * 2 + (mtx >> 1);
                    uint32_t boff = (uint32_t)k * 128 + ((uint32_t)(nch ^ (k & 7)) << 4);
                    LDSM4T(bH[ntp], W2hi + boff);
                }
#pragma unroll
                for (int nt = 0; nt < 4; nt++)
                    MMA16816(acc[nt], aH, bH[nt >> 1][(nt & 1) * 2], bH[nt >> 1][(nt & 1) * 2 + 1]);
            }
            NBAR(PB, 64);
#pragma unroll
            for (int nt = 0; nt < 4; nt++) {
                int col = nc + nt * 8 + lc * 2;
                float s0 = silu(acc[nt][0] + sB2[col]);
                float s1 = silu(acc[nt][1] + sB2[col + 1]);
                float s2 = silu(acc[nt][2] + sB2[col]);
                float s3 = silu(acc[nt][3] + sB2[col + 1]);
                int r0 = mr + lr, r1 = r0 + 8;
                uint32_t ad0 = (uint32_t)r0 * 128 + ((uint32_t)((col >> 3) ^ (r0 & 7)) << 4) + (col & 7) * 2;
                STS32(Hsm + ad0, packh2(s0, s1));
                uint32_t ad1 = (uint32_t)r1 * 128 + ((uint32_t)((col >> 3) ^ (r1 & 7)) << 4) + (col & 7) * 2;
                STS32(Hsm + ad1, packh2(s2, s3));
            }
        }
        NBAR(PB, 64);        // H2 visible to pair

        // ---- layer3: rad = H @ W3 + b3 [64x128, K=64] (regs) ----
        float acc3[8][4];
#pragma unroll
        for (int i = 0; i < 8; i++)
#pragma unroll
            for (int j = 0; j < 4; j++) acc3[i][j] = 0.0f;
        {
            const int nc = ni1 * 64;
#pragma unroll
            for (int ks = 0; ks < 4; ks++) {
                int m = mr + (mtx & 1) * 8 + rin;
                int kc = ks * 2 + (mtx >> 1);
                uint32_t aH[4];
                LDSM4(aH, Hsm + (uint32_t)m * 128 + ((uint32_t)(kc ^ (m & 7)) << 4));
                uint32_t bH[4][4];
#pragma unroll
                for (int ntp = 0; ntp < 4; ntp++) {
                    int k = ks * 16 + (mtx & 1) * 8 + rin;
                    int nch = (nc >> 3) + ntp * 2 + (mtx >> 1);
                    uint32_t boff = (uint32_t)k * 256 + ((uint32_t)(nch ^ (k & 7)) << 4);
                    LDSM4T(bH[ntp], W3hi + boff);
                }
#pragma unroll
                for (int nt = 0; nt < 8; nt++)
                    MMA16816(acc3[nt], aH, bH[nt >> 1][(nt & 1) * 2], bH[nt >> 1][(nt & 1) * 2 + 1]);
            }
        }
        CP_WAIT(1);       // msg(tile) done (this thread's copies)
        NBAR(GB, 256);    // whole group's msg copies visible

        // ---- index prefetch for next tile (latency hidden by phase2) ----
        int rsN = 0, rdN = 0; float raN = 0.0f;
        if (tg < 64 && tn < numTiles) {
            int en = min(tn * 64 + tg, E - 1);
            rsN = edge_src[en];
            rdN = edge_dst[en];
            raN = (tn * 64 + tg < E) ? edge_attr[en] : 0.0f;
        }

        // ---- gather from SMEM + form A = (src+dst)*attr*rad (in place) ----
        {
            const int nc = ni1 * 64;
#pragma unroll
            for (int rh = 0; rh < 2; rh++) {
                int r = mr + rh * 8 + lr;
                float at = sAttr[g][pb][r];
#pragma unroll
                for (int nt = 0; nt < 8; nt++) {
                    int col = nc + nt * 8 + lc * 2;
                    uint32_t ad = (uint32_t)r * 256 + ((uint32_t)((col >> 3) ^ (r & 7)) << 4) + (col & 7) * 2;
                    uint32_t us, ud;
                    LDS32(us, Msrc + ad);
                    LDS32(ud, Mdst + ad);
                    float2 ms = __half22float2(*(__half2*)&us);
                    float2 md = __half22float2(*(__half2*)&ud);
                    float rad0 = acc3[nt][rh * 2 + 0] + sB3[col];
                    float rad1 = acc3[nt][rh * 2 + 1] + sB3[col + 1];
                    float m0 = (ms.x + md.x) * at * rad0;
                    float m1 = (ms.y + md.y) * at * rad1;
                    STS32(Asm + ad, packh2(m0, m1));
                }
            }
        }
        NBAR(GB, 256);

        // ---- phase2: D[64,256] = A @ B + epilogue ----
        float d[2][8][4];
#pragma unroll
        for (int a = 0; a < 2; a++)
#pragma unroll
            for (int b = 0; b < 8; b++)
#pragma unroll
                for (int c = 0; c < 4; c++) d[a][b][c] = 0.0f;

#pragma unroll
        for (int ks = 0; ks < 8; ks++) {
            uint32_t ah[2][4];
#pragma unroll
            for (int mt = 0; mt < 2; mt++) {
                int m = mrow0 + mt * 16 + (mtx & 1) * 8 + rin;
                int kchunk = ks * 2 + (mtx >> 1);
                LDSM4(ah[mt], Asm + (uint32_t)m * 256 + ((uint32_t)(kchunk ^ (m & 7)) << 4));
            }
            uint32_t b[4][4];
#pragma unroll
            for (int ntp = 0; ntp < 4; ntp++) {
                int k = ks * 16 + (mtx & 1) * 8 + rin;
                int nchunk = (ncol0 >> 3) + ntp * 2 + (mtx >> 1);
                LDSM4T(b[ntp], Bsm + (uint32_t)k * 512 + ((uint32_t)(nchunk ^ (k & 7)) << 4));
            }
#pragma unroll
            for (int mt = 0; mt < 2; mt++)
#pragma unroll
                for (int nt = 0; nt < 8; nt++)
                    MMA16816(d[mt][nt], ah[mt], b[nt >> 1][(nt & 1) * 2], b[nt >> 1][(nt & 1) * 2 + 1]);
        }

        // ---- epilogue: w = exp(score); direct segment reduction ----
#pragma unroll
        for (int hh = 0; hh < 2; hh++) {
            const int h = ni * 2 + hh;
#pragma unroll
            for (int mt = 0; mt < 2; mt++) {
                const int r0i = mrow0 + mt * 16 + lr;
                const int e0i = e0 + r0i;
                float p0 = 0.0f, p1 = 0.0f;
#pragma unroll
                for (int q = 0; q < 2; q++) {
                    const int nt = hh * 4 + q;
                    const int colb = ncol0 + nt * 8 + lc * 2;
                    const int jb = q * 8 + lc * 2;
                    const float bb0 = sBsep[colb], bb1 = sBsep[colb + 1];
                    const float w0 = sAD[h * 16 + jb], w1 = sAD[h * 16 + jb + 1];
                    float x, sg;
                    x = d[mt][nt][0] + bb0; sg = 1.0f / (1.0f + __expf(-x)); p0 += x * (0.2f + 0.8f * sg) * w0;
                    x = d[mt][nt][1] + bb1; sg = 1.0f / (1.0f + __expf(-x)); p0 += x * (0.2f + 0.8f * sg) * w1;
                    x = d[mt][nt][2] + bb0; sg = 1.0f / (1.0f + __expf(-x)); p1 += x * (0.2f + 0.8f * sg) * w0;
                    x = d[mt][nt][3] + bb1; sg = 1.0f / (1.0f + __expf(-x)); p1 += x * (0.2f + 0.8f * sg) * w1;
                }
                p0 += __shfl_xor_sync(0xffffffffu, p0, 1);
                p0 += __shfl_xor_sync(0xffffffffu, p0, 2);
                p1 += __shfl_xor_sync(0xffffffffu, p1, 1);
                p1 += __shfl_xor_sync(0xffffffffu, p1, 2);
                const float ew0 = __expf(p0), ew1 = __expf(p1);
                const int d0 = sDst[g][pb][r0i], d1 = sDst[g][pb][r0i + 8];
                if (lc == 0) {
                    if (e0i < E)     atomicAdd(&g_nsum[(size_t)d0 * 8 + h], ew0);
                    if (e0i + 8 < E) atomicAdd(&g_nsum[(size_t)d1 * 8 + h], ew1);
                }
#pragma unroll
                for (int q = 0; q < 2; q++) {
                    const int nt = hh * 4 + 2 + q;
                    const int colb = ncol0 + nt * 8 + lc * 2;
                    const int vidx = q * 8 + lc * 2;
                    const float bb0 = sBsep[colb], bb1 = sBsep[colb + 1];
                    if (e0i < E)
                        RED2(g_nacc + (size_t)d0 * 128 + h * 16 + vidx,
                             (d[mt][nt][0] + bb0) * ew0, (d[mt][nt][1] + bb1) * ew0);
                    if (e0i + 8 < E)
                        RED2(g_nacc + (size_t)d1 * 128 + h * 16 + vidx,
                             (d[mt][nt][2] + bb0) * ew1, (d[mt][nt][3] + bb1) * ew1);
                }
            }
        }

        // ---- publish prefetched indices for next tile ----
        if (tg < 64 && tn < numTiles) {
            sSrc[g][pb ^ 1][tg] = rsN;
            sDst[g][pb ^ 1][tg] = rdN;
            sAttr[g][pb ^ 1][tg] = raN;
        }
        pb ^= 1;
        tile = tn;
    }
}

// ---------------- K5: out GEMM on HMMA ---------------------------------------
__global__ __launch_bounds__(512, 1) void out_mma_kernel(
    const float* __restrict__ bias, float* __restrict__ out, int n)
{
    extern __shared__ char dynsm[];
    __shared__ float sBias[128];
    const int tid = threadIdx.x;
    const int wid = tid >> 5, lane = tid & 31;
    const int mtx = lane >> 3, rin = lane & 7;
    const int lr = lane >> 2, lc = lane & 3;
    const int r0 = blockIdx.x * 128;

    const uint32_t sb = smem_u32(dynsm);
    const uint32_t Ahi = sb, Alo = sb + 32768, Bsm = sb + 65536;

#pragma unroll
    for (int it = 0; it < 4; it++) {
        int i = tid + 512 * it;
        CP16(Bsm + i * 16, g_PImg + i * 16);
    }
    CP_COMMIT();
    if (tid < 128) sBias[tid] = bias[tid];

#pragma unroll
    for (int it = 0; it < 8; it++) {
        int i = tid + 512 * it;
        int m = i >> 5, k4 = (i & 31) << 2;
        int gr = r0 + m;
        float4 v = make_float4(0.f, 0.f, 0.f, 0.f);
        if (gr < n) {
            v = *(const float4*)(g_nacc + (size_t)gr * 128 + k4);
            float inv = 1.0f / (g_nsum[(size_t)gr * 8 + (k4 >> 4)] + 1e-16f);
            v.x *= inv; v.y *= inv; v.z *= inv; v.w *= inv;
        }
        uint32_t hA, hB, lA, lB; split4(v, hA, hB, lA, lB);
        uint32_t addr = (uint32_t)m * 256 + ((uint32_t)((k4 >> 3) ^ (m & 7)) << 4) + (k4 & 7) * 2;
        STS64(Ahi + addr, hA, hB);
        STS64(Alo + addr, lA, lB);
    }
    CP_WAIT(0);
    __syncthreads();

    const int mi = wid & 3, ni = wid >> 2;
    const int mrow0 = mi * 32, ncol0 = ni * 32;

    float d[2][4][4];
#pragma unroll
    for (int a = 0; a < 2; a++)
#pragma unroll
        for (int b = 0; b < 4; b++)
#pragma unroll
            for (int c = 0; c < 4; c++) d[a][b][c] = 0.0f;

#pragma unroll
    for (int ks = 0; ks < 8; ks++) {
        uint32_t ah[2][4], al[2][4];
#pragma unroll
        for (int mt = 0; mt < 2; mt++) {
            int m = mrow0 + mt * 16 + (mtx & 1) * 8 + rin;
            int kchunk = ks * 2 + (mtx >> 1);
            uint32_t ao = (uint32_t)m * 256 + ((uint32_t)(kchunk ^ (m & 7)) << 4);
            LDSM4(ah[mt], Ahi + ao);
            LDSM4(al[mt], Alo + ao);
        }
        uint32_t b[2][4];
#pragma unroll
        for (int ntp = 0; ntp < 2; ntp++) {
            int k = ks * 16 + (mtx & 1) * 8 + rin;
            int nchunk = (ncol0 >> 3) + ntp * 2 + (mtx >> 1);
            LDSM4T(b[ntp], Bsm + (uint32_t)k * 256 + ((uint32_t)(nchunk ^ (k & 7)) << 4));
        }
#pragma unroll
        for (int mt = 0; mt < 2; mt++)
#pragma unroll
            for (int nt = 0; nt < 4; nt++) {
                MMA16816(d[mt][nt], ah[mt], b[nt >> 1][(nt & 1) * 2], b[nt >> 1][(nt & 1) * 2 + 1]);
                MMA16816(d[mt][nt], al[mt], b[nt >> 1][(nt & 1) * 2], b[nt >> 1][(nt & 1) * 2 + 1]);
            }
    }

#pragma unroll
    for (int mt = 0; mt < 2; mt++) {
        int gr0 = r0 + mrow0 + mt * 16 + lr;
        int gr1 = gr0 + 8;
#pragma unroll
        for (int nt = 0; nt < 4; nt++) {
            int c = ncol0 + nt * 8 + lc * 2;
            float bb0 = sBias[c], bb1 = sBias[c + 1];
            if (gr0 < n)
                *(float2*)(out + (size_t)gr0 * 128 + c) =
                    make_float2(d[mt][nt][0] + bb0, d[mt][nt][1] + bb1);
            if (gr1 < n)
                *(float2*)(out + (size_t)gr1 * 128 + c) =
                    make_float2(d[mt][nt][2] + bb0, d[mt][nt][3] + bb1);
        }
    }
}

// ---------------- launch ----------------
extern "C" void kernel_launch(void* const* d_in, const int* in_sizes, int n_in,
                              void* d_out, int out_size)
{
    const float* node_input = (const float*)d_in[0];
    const float* edge_attr  = (const float*)d_in[2];
    const float* edge_scal  = (const float*)d_in[3];
    const int*   edge_src   = (const int*)d_in[4];
    const int*   edge_dst   = (const int*)d_in[5];
    const float* w_src      = (const float*)d_in[7];
    const float* b_src      = (const float*)d_in[8];
    const float* w_dst      = (const float*)d_in[9];
    const float* fc_w1      = (const float*)d_in[10];
    const float* fc_b1      = (const float*)d_in[11];
    const float* fc_w2      = (const float*)d_in[12];
    const float* fc_b2      = (const float*)d_in[13];
    const float* fc_w3      = (const float*)d_in[14];
    const float* fc_b3      = (const float*)d_in[15];
    const float* w_sep      = (const float*)d_in[16];
    const float* b_sep      = (const float*)d_in[17];
    const float* alpha_dot  = (const float*)d_in[18];
    const float* w_proj     = (const float*)d_in[19];
    const float* b_proj     = (const float*)d_in[20];
    float* out = (float*)d_out;

    int N = in_sizes[0] / 128;
    int E = in_sizes[4];

    cudaFuncSetAttribute(fused_edge_kernel, cudaFuncAttributeMaxDynamicSharedMemorySize, 221184);
    cudaFuncSetAttribute(node_mma_kernel,   cudaFuncAttributeMaxDynamicSharedMemorySize, 131072);
    cudaFuncSetAttribute(out_mma_kernel,    cudaFuncAttributeMaxDynamicSharedMemorySize, 98304);

    static int sms = 0;
    if (sms == 0) {
        cudaDeviceGetAttribute(&sms, cudaDevAttrMultiProcessorCount, 0);
        if (sms <= 0) sms = 148;
    }

    init_kernel<<<(N * 128 + 255) / 256, 256>>>(N);
    prep_kernel<<<94, 256>>>(fc_w1, fc_w2, fc_w3, w_sep, w_src, w_dst, w_proj);

    int nt = (N + 127) / 128;
    node_mma_kernel<<<nt, 512, 131072>>>(node_input, b_src, N);

    int numTiles = (E + 63) / 64;               // 64-edge tiles
    int nblk = (numTiles + 1) / 2;
    if (nblk > sms) nblk = sms;
    fused_edge_kernel<<<nblk, 512, 221184>>>(edge_scal, edge_attr, edge_src, edge_dst,
                                             fc_b1, fc_b2, fc_b3,
                                             b_sep, alpha_dot, E, numTiles);

    out_mma_kernel<<<nt, 512, 98304>>>(b_proj, out, N);
}